// round 4
// baseline (speedup 1.0000x reference)
#include <cuda_runtime.h>
#include <cuda_bf16.h>
#include <math.h>
#include <stdint.h>

#define CC 2.3026f
#define BATCH 65536

// tcgen05 only exists on arch-specific targets (sm_100a/sm_103a/f-family).
#if (defined(__CUDA_ARCH_FEAT_SM103_ALL) || defined(__CUDA_ARCH_FEAT_SM100_ALL) || \
     defined(__CUDA_ARCH_FEAT_SM101_ALL) || \
     (defined(__CUDA_ARCH_SPECIFIC__) && (__CUDA_ARCH_SPECIFIC__ >= 1000)) || \
     (defined(__CUDA_ARCH_FAMILY_SPECIFIC__) && (__CUDA_ARCH_FAMILY_SPECIFIC__ >= 1000)))
#define TC_OK 1
#else
#define TC_OK 0
#endif

// ---------------- static device scratch ----------------
__device__ __align__(256) __nv_bfloat16 g_xhi[(size_t)BATCH * 768];
__device__ __align__(256) __nv_bfloat16 g_xlo[(size_t)BATCH * 768];
__device__ __align__(256) __nv_bfloat16 g_hhi[(size_t)BATCH * 512];
__device__ __align__(256) __nv_bfloat16 g_hlo[(size_t)BATCH * 512];
__device__ __align__(256) __nv_bfloat16 g_h2hi[(size_t)BATCH * 256];
__device__ __align__(256) __nv_bfloat16 g_h2lo[(size_t)BATCH * 256];
__device__ __align__(256) __nv_bfloat16 g_h3hi[(size_t)BATCH * 128];
__device__ __align__(256) __nv_bfloat16 g_h3lo[(size_t)BATCH * 128];
__device__ float g_m[(size_t)BATCH * 512];
__device__ float g_lam[BATCH];
__device__ float g_zn[897], g_chv[897], g_shv[897];
// transposed split weights [N, K] row-major
__device__ __align__(256) __nv_bfloat16 g_zt1h[512 * 768], g_zt1l[512 * 768];
__device__ __align__(256) __nv_bfloat16 g_zt2h[256 * 512], g_zt2l[256 * 512];
__device__ __align__(256) __nv_bfloat16 g_zt3h[128 * 256], g_zt3l[128 * 256];

// ---------------- PTX helpers ----------------
__device__ __forceinline__ uint32_t smem_u32(const void* p) {
    uint32_t a;
    asm("{ .reg .u64 t; cvta.to.shared.u64 t, %1; cvt.u32.u64 %0, t; }" : "=r"(a) : "l"(p));
    return a;
}

#if TC_OK
#define TC_ALLOC(sa, n)  asm volatile("tcgen05.alloc.cta_group::1.sync.aligned.shared::cta.b32 [%0], %1;" :: "r"(sa), "r"(n) : "memory")
#define TC_DEALLOC(t, n) asm volatile("tcgen05.dealloc.cta_group::1.sync.aligned.b32 %0, %1;" :: "r"(t), "r"(n))
#define TC_COMMIT(mb)    asm volatile("tcgen05.commit.cta_group::1.mbarrier::arrive::one.shared::cluster.b64 [%0];" :: "r"(mb) : "memory")
#define TC_FENCE_AFTER() asm volatile("tcgen05.fence::after_thread_sync;" ::: "memory")
#define TC_WAIT_LD()     asm volatile("tcgen05.wait::ld.sync.aligned;" ::: "memory")
#define MB_INIT(mb, c)   asm volatile("mbarrier.init.shared.b64 [%0], %1;" :: "r"(mb), "r"(c) : "memory")
#define FENCE_ASYNC()    asm volatile("fence.proxy.async.shared::cta;" ::: "memory")

#define MB_WAIT(mb, ph) do { \
    uint32_t _m = (mb), _p = (ph), _d; \
    asm volatile("{ .reg .pred p; mbarrier.try_wait.parity.acquire.cta.shared::cta.b64 p, [%1], %2; selp.b32 %0,1,0,p; }" \
        : "=r"(_d) : "r"(_m), "r"(_p) : "memory"); \
    if (!_d) { \
        asm volatile("{ .reg .pred P1; WL_%=: mbarrier.try_wait.parity.acquire.cta.shared::cta.b64 P1, [%0], %1, 0x989680; @P1 bra.uni WD_%=; bra.uni WL_%=; WD_%=: }" \
            :: "r"(_m), "r"(_p) : "memory"); \
    } \
} while (0)

#define TC_LD_X32(r, ta) \
    asm volatile("tcgen05.ld.sync.aligned.32x32b.x32.b32 " \
        "{%0,%1,%2,%3,%4,%5,%6,%7,%8,%9,%10,%11,%12,%13,%14,%15," \
        "%16,%17,%18,%19,%20,%21,%22,%23,%24,%25,%26,%27,%28,%29,%30,%31}, [%32];" \
        : "=r"((r)[0]),"=r"((r)[1]),"=r"((r)[2]),"=r"((r)[3]),"=r"((r)[4]),"=r"((r)[5]),"=r"((r)[6]),"=r"((r)[7]), \
          "=r"((r)[8]),"=r"((r)[9]),"=r"((r)[10]),"=r"((r)[11]),"=r"((r)[12]),"=r"((r)[13]),"=r"((r)[14]),"=r"((r)[15]), \
          "=r"((r)[16]),"=r"((r)[17]),"=r"((r)[18]),"=r"((r)[19]),"=r"((r)[20]),"=r"((r)[21]),"=r"((r)[22]),"=r"((r)[23]), \
          "=r"((r)[24]),"=r"((r)[25]),"=r"((r)[26]),"=r"((r)[27]),"=r"((r)[28]),"=r"((r)[29]),"=r"((r)[30]),"=r"((r)[31]) \
        : "r"(ta))

static __device__ __forceinline__ uint64_t desc_sw128(uint32_t addr) {
    const uint64_t base = (uint64_t(2) << 61) | (uint64_t(1) << 46)
                        | (uint64_t(64) << 32) | (uint64_t(1) << 16);
    return base | ((uint64_t)(addr >> 4) & 0x3FFF);
}
__device__ __forceinline__ void mma_f16(uint32_t d, uint64_t ad, uint64_t bd,
                                        uint32_t idesc, uint32_t en) {
    asm volatile(
        "{ .reg .pred p; setp.ne.u32 p, %4, 0;\n\t"
        "tcgen05.mma.cta_group::1.kind::f16 [%0], %1, %2, %3, {%5,%5,%5,%5}, p; }"
        :: "r"(d), "l"(ad), "l"(bd), "r"(idesc), "r"(en), "r"(0u) : "memory");
}
#endif  // TC_OK

// ---------------- prep kernels ----------------
__global__ void prep_kernel(const float* __restrict__ z, const float* __restrict__ r,
                            int fi, int fo, int off)
{
    int k = blockIdx.x * blockDim.x + threadIdx.x;
    if (k >= fo) return;
    float s = 0.f;
    for (int i = 0; i < fi; i++) { float v = z[(long long)i * fo + k]; s = fmaf(v, v, s); }
    float zn = fmaxf(sqrtf(s), 1e-15f);
    float t = 2.f * sqrtf(CC) * r[k];
    g_zn[off + k] = zn; g_chv[off + k] = coshf(t); g_shv[off + k] = sinhf(t);
}

__global__ void tsplit_kernel(const float* __restrict__ z,
                              __nv_bfloat16* __restrict__ th, __nv_bfloat16* __restrict__ tl,
                              int fi, int fo)
{
    int idx = blockIdx.x * blockDim.x + threadIdx.x;
    if (idx >= fi * fo) return;
    int n = idx / fi, k = idx - n * fi;
    float v = z[(long long)k * fo + n];
    __nv_bfloat16 h = __float2bfloat16(v);
    th[idx] = h;
    tl[idx] = __float2bfloat16(v - __bfloat162float(h));
}

// lam0 + split x into bf16 hi/lo. warp per row, fi=768.
__global__ void lam0_kernel(const float* __restrict__ x)
{
    int gid = blockIdx.x * blockDim.x + threadIdx.x;
    int row = gid >> 5, lane = gid & 31;
    const float4* xr = (const float4*)(x + (long long)row * 768);
    float s = 0.f;
#pragma unroll
    for (int p = 0; p < 6; p++) {
        int e4 = lane + 32 * p;
        float4 v = xr[e4];
        s += v.x * v.x + v.y * v.y + v.z * v.z + v.w * v.w;
        long long b = (long long)row * 768 + e4 * 4;
        float vv[4] = {v.x, v.y, v.z, v.w};
#pragma unroll
        for (int q = 0; q < 4; q++) {
            __nv_bfloat16 h = __float2bfloat16(vv[q]);
            g_xhi[b + q] = h;
            g_xlo[b + q] = __float2bfloat16(vv[q] - __bfloat162float(h));
        }
    }
#pragma unroll
    for (int o = 16; o; o >>= 1) s += __shfl_xor_sync(0xffffffffu, s, o);
    if (lane == 0) g_lam[row] = 2.f / (1.f - CC * s);
}

// ---------------- SW128 tile loader: nrows x 64 bf16 (128B rows) ----------------
__device__ __forceinline__ void load_tile(const __nv_bfloat16* __restrict__ g,
                                          long long rowbase, int K, int k0,
                                          char* sb, int nrows, int tid)
{
    int nvec = nrows * 8;
    for (int v = tid; v < nvec; v += 256) {
        int r = v >> 3, c = v & 7;
        uint4 d = *(const uint4*)(g + (rowbase + r) * K + k0 + c * 8);
        uint32_t o = (uint32_t)(r * 128 + c * 16);
        o ^= (o >> 3) & 0x70;
        *(uint4*)(sb + o) = d;
    }
}

// ---------------- GEMM: C[128x128] = (Ahi+Alo)[128xK] @ (Bth+Btl)[128xK]^T ----------------
// tcgen05 split-bf16 path on arch-specific targets; fp32 SIMT fallback otherwise.
template <int KDIM>
__global__ __launch_bounds__(256)
void gemm_tc(const __nv_bfloat16* __restrict__ Ahi, const __nv_bfloat16* __restrict__ Alo,
             const __nv_bfloat16* __restrict__ Bth, const __nv_bfloat16* __restrict__ Btl,
             float* __restrict__ Mout, int Nfull)
{
    extern __shared__ char smem_raw[];
    int tid = threadIdx.x;
    long long bm = (long long)blockIdx.y * 128;
    int bn = blockIdx.x * 128;

#if TC_OK
    constexpr int NB = KDIM / 64;
    constexpr int BUFSZ = 65536;  // Ahi 16K | Alo 16K | Bhi 16K | Blo 16K
    constexpr uint32_t IDESC = (1u << 4) | (1u << 7) | (1u << 10) | (16u << 17) | (8u << 24);
    int wid = tid >> 5, lane = tid & 31;

    uint32_t sraw = smem_u32(smem_raw);
    uint32_t abase = (sraw + 1023u) & ~1023u;
    char* smem = smem_raw + (abase - sraw);

    if (wid == 0) TC_ALLOC(abase, 128);
    if (tid == 0) { MB_INIT(abase + 16, 1); MB_INIT(abase + 24, 1); }

    {
        char* b0 = smem + 1024;
        load_tile(Ahi, bm, KDIM, 0, b0, 128, tid);
        load_tile(Alo, bm, KDIM, 0, b0 + 16384, 128, tid);
        load_tile(Bth, bn, KDIM, 0, b0 + 32768, 128, tid);
        load_tile(Btl, bn, KDIM, 0, b0 + 49152, 128, tid);
    }
    FENCE_ASYNC();
    __syncthreads();
    uint32_t tmem;
    asm volatile("ld.shared.b32 %0, [%1];" : "=r"(tmem) : "r"(abase));

    for (int i = 0; i < NB; i++) {
        int cur = i & 1;
        if (tid == 0) {
            uint32_t a0 = abase + 1024 + cur * BUFSZ;
            uint64_t adh = desc_sw128(a0);
            uint64_t adl = desc_sw128(a0 + 16384);
            uint64_t bdh = desc_sw128(a0 + 32768);
            uint64_t bdl = desc_sw128(a0 + 49152);
#pragma unroll
            for (int ks = 0; ks < 4; ks++) {
                mma_f16(tmem, adh + ks * 2, bdh + ks * 2, IDESC, (i > 0 || ks > 0) ? 1u : 0u);
                mma_f16(tmem, adh + ks * 2, bdl + ks * 2, IDESC, 1u);
                mma_f16(tmem, adl + ks * 2, bdh + ks * 2, IDESC, 1u);
            }
            TC_COMMIT(abase + 16 + cur * 8);
        }
        if (i + 1 < NB) {
            if (i >= 1) MB_WAIT(abase + 16 + ((i - 1) & 1) * 8, ((i - 1) >> 1) & 1);
            int k0 = (i + 1) * 64;
            char* nb = smem + 1024 + ((i + 1) & 1) * BUFSZ;
            load_tile(Ahi, bm, KDIM, k0, nb, 128, tid);
            load_tile(Alo, bm, KDIM, k0, nb + 16384, 128, tid);
            load_tile(Bth, bn, KDIM, k0, nb + 32768, 128, tid);
            load_tile(Btl, bn, KDIM, k0, nb + 49152, 128, tid);
            FENCE_ASYNC();
        }
        __syncthreads();
    }
    MB_WAIT(abase + 16 + ((NB - 1) & 1) * 8, ((NB - 1) >> 1) & 1);
    TC_FENCE_AFTER();

    // TMEM -> SMEM stage -> coalesced global
    constexpr int PITCH = 132;
    float* stage = (float*)(smem + 1024);
    int cb = (wid >> 2) * 64;
    int row = (wid & 3) * 32 + lane;
#pragma unroll
    for (int c0 = 0; c0 < 64; c0 += 32) {
        uint32_t r32[32];
        TC_LD_X32(r32, tmem + cb + c0);
        TC_WAIT_LD();
#pragma unroll
        for (int j = 0; j < 32; j++) stage[row * PITCH + cb + c0 + j] = __uint_as_float(r32[j]);
    }
    __syncthreads();
    if (wid == 0) TC_DEALLOC(tmem, 128);
    for (int idx = tid; idx < 128 * 32; idx += 256) {
        int r = idx >> 5, c = (idx & 31) * 4;
        float4 v;
        v.x = stage[r * PITCH + c];     v.y = stage[r * PITCH + c + 1];
        v.z = stage[r * PITCH + c + 2]; v.w = stage[r * PITCH + c + 3];
        *(float4*)(Mout + (bm + r) * Nfull + bn + c) = v;
    }
#else
    // ---------- correct fp32 SIMT fallback (non-'a' compilation pass) ----------
    __shared__ float As[16][132];
    __shared__ float Bs[16][132];
    int tx = tid & 15, ty = tid >> 4;
    float acc[8][8];
#pragma unroll
    for (int i = 0; i < 8; i++)
#pragma unroll
        for (int j = 0; j < 8; j++) acc[i][j] = 0.f;

    for (int k0 = 0; k0 < KDIM; k0 += 16) {
#pragma unroll
        for (int l = 0; l < 8; l++) {
            int idx = tid + 256 * l;          // 2048 = 128 rows x 16 k
            int r = idx >> 4, kk = idx & 15;
            long long ai = (bm + r) * (long long)KDIM + k0 + kk;
            As[kk][r] = __bfloat162float(Ahi[ai]) + __bfloat162float(Alo[ai]);
            long long bi = (long long)(bn + r) * KDIM + k0 + kk;
            Bs[kk][r] = __bfloat162float(Bth[bi]) + __bfloat162float(Btl[bi]);
        }
        __syncthreads();
#pragma unroll
        for (int k = 0; k < 16; k++) {
            float a[8], b[8];
#pragma unroll
            for (int i = 0; i < 8; i++) a[i] = As[k][ty * 8 + i];
#pragma unroll
            for (int j = 0; j < 8; j++) b[j] = Bs[k][tx * 8 + j];
#pragma unroll
            for (int i = 0; i < 8; i++)
#pragma unroll
                for (int j = 0; j < 8; j++) acc[i][j] = fmaf(a[i], b[j], acc[i][j]);
        }
        __syncthreads();
    }
#pragma unroll
    for (int i = 0; i < 8; i++)
#pragma unroll
        for (int j = 0; j < 8; j++)
            Mout[(bm + ty * 8 + i) * Nfull + bn + tx * 8 + j] = acc[i][j];
#endif
}

// ---------------- fused hlinear-epilogue + hrelu, warp per row; bf16 hi/lo out ----------------
template <int P>
__global__ void epi_kernel(const float* __restrict__ m,
                           __nv_bfloat16* __restrict__ hh, __nv_bfloat16* __restrict__ hl, int off)
{
    constexpr int FO = P * 32;
    int gid = blockIdx.x * blockDim.x + threadIdx.x;
    int row = gid >> 5, lane = gid & 31;
    const float cs = sqrtf(CC);

    float lam = g_lam[row];
    float w[P];
    float s = 0.f;
#pragma unroll
    for (int p = 0; p < P; p++) {
        int k = lane + 32 * p;
        float mm = m[(long long)row * FO + k];
        float zn = g_zn[off + k];
        float u  = cs * lam * mm / zn * g_chv[off + k] - (lam - 1.f) * g_shv[off + k];
        float ww = sinhf(2.f * zn * asinhf(u)) * (1.f / cs);
        w[p] = ww;
        s = fmaf(ww, ww, s);
    }
#pragma unroll
    for (int o = 16; o; o >>= 1) s += __shfl_xor_sync(0xffffffffu, s, o);
    float inv = 1.f / (1.f + sqrtf(1.f + CC * s));
    float sp = 0.f;
#pragma unroll
    for (int p = 0; p < P; p++) {
        float y = w[p] * inv;
        w[p] = y;
        float yp = fmaxf(y, 0.f);
        sp = fmaf(yp, yp, sp);
    }
#pragma unroll
    for (int o = 16; o; o >>= 1) sp += __shfl_xor_sync(0xffffffffu, sp, o);
    float n  = fmaxf(sqrtf(s) * inv, 1e-15f);
    float a  = atanhf(fminf(cs * n, 1.f - 1e-7f)) / (cs * n);
    float vn = fmaxf(a * sqrtf(sp), 1e-15f);
    float fac = tanhf(cs * vn) / (cs * vn) * a;
#pragma unroll
    for (int p = 0; p < P; p++) {
        int k = lane + 32 * p;
        float h = fac * fmaxf(w[p], 0.f);
        __nv_bfloat16 hb = __float2bfloat16(h);
        hh[(long long)row * FO + k] = hb;
        hl[(long long)row * FO + k] = __float2bfloat16(h - __bfloat162float(hb));
    }
    if (lane == 0) {
        float chv = coshf(cs * vn);
        g_lam[row] = 2.f * chv * chv;
    }
}

// ---------------- final layer fo=1 ----------------
__global__ void final_kernel(const __nv_bfloat16* __restrict__ hh, const __nv_bfloat16* __restrict__ hl,
                             const float* __restrict__ z4, float* __restrict__ out)
{
    int gid = blockIdx.x * blockDim.x + threadIdx.x;
    int row = gid >> 5, lane = gid & 31;
    float s = 0.f;
#pragma unroll
    for (int p = 0; p < 4; p++) {
        int k = lane + 32 * p;
        long long idx = (long long)row * 128 + k;
        float h = __bfloat162float(hh[idx]) + __bfloat162float(hl[idx]);
        s = fmaf(h, z4[k], s);
    }
#pragma unroll
    for (int o = 16; o; o >>= 1) s += __shfl_xor_sync(0xffffffffu, s, o);
    if (lane == 0) {
        const float cs = sqrtf(CC);
        float lam = g_lam[row];
        float zn = g_zn[896];
        float u = cs * lam * s / zn * g_chv[896] - (lam - 1.f) * g_shv[896];
        float w = sinhf(2.f * zn * asinhf(u)) * (1.f / cs);
        out[row] = w / (1.f + sqrtf(1.f + CC * w * w));
    }
}

// ---------------- launch ----------------
extern "C" void kernel_launch(void* const* d_in, const int* in_sizes, int n_in,
                              void* d_out, int out_size)
{
    const float* x  = (const float*)d_in[0];
    const float* z1 = (const float*)d_in[1];
    const float* b1 = (const float*)d_in[2];
    const float* z2 = (const float*)d_in[3];
    const float* b2 = (const float*)d_in[4];
    const float* z3 = (const float*)d_in[5];
    const float* b3 = (const float*)d_in[6];
    const float* z4 = (const float*)d_in[7];
    const float* b4 = (const float*)d_in[8];
    float* out = (float*)d_out;

    float* pm;            cudaGetSymbolAddress((void**)&pm, g_m);
    __nv_bfloat16 *xh, *xl, *h1h, *h1l, *h2h, *h2l, *h3h, *h3l;
    __nv_bfloat16 *t1h, *t1l, *t2h, *t2l, *t3h, *t3l;
    cudaGetSymbolAddress((void**)&xh, g_xhi);   cudaGetSymbolAddress((void**)&xl, g_xlo);
    cudaGetSymbolAddress((void**)&h1h, g_hhi);  cudaGetSymbolAddress((void**)&h1l, g_hlo);
    cudaGetSymbolAddress((void**)&h2h, g_h2hi); cudaGetSymbolAddress((void**)&h2l, g_h2lo);
    cudaGetSymbolAddress((void**)&h3h, g_h3hi); cudaGetSymbolAddress((void**)&h3l, g_h3lo);
    cudaGetSymbolAddress((void**)&t1h, g_zt1h); cudaGetSymbolAddress((void**)&t1l, g_zt1l);
    cudaGetSymbolAddress((void**)&t2h, g_zt2h); cudaGetSymbolAddress((void**)&t2l, g_zt2l);
    cudaGetSymbolAddress((void**)&t3h, g_zt3h); cudaGetSymbolAddress((void**)&t3l, g_zt3l);

    const int SMEM_SZ = 1024 + 1024 + 2 * 65536;
    static int configured = 0;
    if (!configured) {
        cudaFuncSetAttribute(gemm_tc<768>, cudaFuncAttributeMaxDynamicSharedMemorySize, SMEM_SZ);
        cudaFuncSetAttribute(gemm_tc<512>, cudaFuncAttributeMaxDynamicSharedMemorySize, SMEM_SZ);
        cudaFuncSetAttribute(gemm_tc<256>, cudaFuncAttributeMaxDynamicSharedMemorySize, SMEM_SZ);
        configured = 1;
    }

    const int warpBlocks = BATCH * 32 / 256;

    lam0_kernel<<<warpBlocks, 256>>>(x);
    prep_kernel<<<2, 256>>>(z1, b1, 768, 512, 0);
    prep_kernel<<<1, 256>>>(z2, b2, 512, 256, 512);
    prep_kernel<<<1, 256>>>(z3, b3, 256, 128, 768);
    prep_kernel<<<1, 256>>>(z4, b4, 128, 1, 896);
    tsplit_kernel<<<(512 * 768 + 255) / 256, 256>>>(z1, t1h, t1l, 768, 512);
    tsplit_kernel<<<(256 * 512 + 255) / 256, 256>>>(z2, t2h, t2l, 512, 256);
    tsplit_kernel<<<(128 * 256 + 255) / 256, 256>>>(z3, t3h, t3l, 256, 128);

    // layer 1: (B,768) @ (768,512)
    gemm_tc<768><<<dim3(4, BATCH / 128), 256, SMEM_SZ>>>(xh, xl, t1h, t1l, pm, 512);
    epi_kernel<16><<<warpBlocks, 256>>>(pm, h1h, h1l, 0);
    // layer 2: (B,512) @ (512,256)
    gemm_tc<512><<<dim3(2, BATCH / 128), 256, SMEM_SZ>>>(h1h, h1l, t2h, t2l, pm, 256);
    epi_kernel<8><<<warpBlocks, 256>>>(pm, h2h, h2l, 512);
    // layer 3: (B,256) @ (256,128)
    gemm_tc<256><<<dim3(1, BATCH / 128), 256, SMEM_SZ>>>(h2h, h2l, t3h, t3l, pm, 128);
    epi_kernel<4><<<warpBlocks, 256>>>(pm, h3h, h3l, 768);
    // layer 4
    final_kernel<<<warpBlocks, 256>>>(h3h, h3l, z4, out);
}

// round 5
// speedup vs baseline: 1.8198x; 1.8198x over previous
#include <cuda_runtime.h>
#include <cuda_bf16.h>
#include <math.h>
#include <stdint.h>

#define CC 2.3026f
#define BATCH 65536

// ---------------- static device scratch ----------------
__device__ __align__(256) __nv_bfloat16 g_xhi[(size_t)BATCH * 768];
__device__ __align__(256) __nv_bfloat16 g_xlo[(size_t)BATCH * 768];
__device__ __align__(256) __nv_bfloat16 g_hhi[(size_t)BATCH * 512];
__device__ __align__(256) __nv_bfloat16 g_hlo[(size_t)BATCH * 512];
__device__ __align__(256) __nv_bfloat16 g_h2hi[(size_t)BATCH * 256];
__device__ __align__(256) __nv_bfloat16 g_h2lo[(size_t)BATCH * 256];
__device__ __align__(256) __nv_bfloat16 g_h3hi[(size_t)BATCH * 128];
__device__ __align__(256) __nv_bfloat16 g_h3lo[(size_t)BATCH * 128];
__device__ float g_m[(size_t)BATCH * 512];
__device__ float g_lam[BATCH];
__device__ float g_zn[897], g_chv[897], g_shv[897];
// transposed split weights [N, K] row-major
__device__ __align__(256) __nv_bfloat16 g_zt1h[512 * 768], g_zt1l[512 * 768];
__device__ __align__(256) __nv_bfloat16 g_zt2h[256 * 512], g_zt2l[256 * 512];
__device__ __align__(256) __nv_bfloat16 g_zt3h[128 * 256], g_zt3l[128 * 256];

// ---------------- mma.sync helper (baseline-portable, no 'a' features) ----------------
__device__ __forceinline__ void mma16816(float* d, const uint32_t* a, const uint32_t* b) {
    asm volatile(
        "mma.sync.aligned.m16n8k16.row.col.f32.bf16.bf16.f32 "
        "{%0,%1,%2,%3}, {%4,%5,%6,%7}, {%8,%9}, {%0,%1,%2,%3};"
        : "+f"(d[0]), "+f"(d[1]), "+f"(d[2]), "+f"(d[3])
        : "r"(a[0]), "r"(a[1]), "r"(a[2]), "r"(a[3]), "r"(b[0]), "r"(b[1]));
}

// ---------------- prep kernels ----------------
__global__ void prep_kernel(const float* __restrict__ z, const float* __restrict__ r,
                            int fi, int fo, int off)
{
    int k = blockIdx.x * blockDim.x + threadIdx.x;
    if (k >= fo) return;
    float s = 0.f;
    for (int i = 0; i < fi; i++) { float v = z[(long long)i * fo + k]; s = fmaf(v, v, s); }
    float zn = fmaxf(sqrtf(s), 1e-15f);
    float t = 2.f * sqrtf(CC) * r[k];
    g_zn[off + k] = zn; g_chv[off + k] = coshf(t); g_shv[off + k] = sinhf(t);
}

__global__ void tsplit_kernel(const float* __restrict__ z,
                              __nv_bfloat16* __restrict__ th, __nv_bfloat16* __restrict__ tl,
                              int fi, int fo)
{
    int idx = blockIdx.x * blockDim.x + threadIdx.x;
    if (idx >= fi * fo) return;
    int n = idx / fi, k = idx - n * fi;
    float v = z[(long long)k * fo + n];
    __nv_bfloat16 h = __float2bfloat16(v);
    th[idx] = h;
    tl[idx] = __float2bfloat16(v - __bfloat162float(h));
}

// lam0 + split x into bf16 hi/lo. warp per row, fi=768.
__global__ void lam0_kernel(const float* __restrict__ x)
{
    int gid = blockIdx.x * blockDim.x + threadIdx.x;
    int row = gid >> 5, lane = gid & 31;
    const float4* xr = (const float4*)(x + (long long)row * 768);
    float s = 0.f;
#pragma unroll
    for (int p = 0; p < 6; p++) {
        int e4 = lane + 32 * p;
        float4 v = xr[e4];
        s += v.x * v.x + v.y * v.y + v.z * v.z + v.w * v.w;
        long long b = (long long)row * 768 + e4 * 4;
        float vv[4] = {v.x, v.y, v.z, v.w};
#pragma unroll
        for (int q = 0; q < 4; q++) {
            __nv_bfloat16 h = __float2bfloat16(vv[q]);
            g_xhi[b + q] = h;
            g_xlo[b + q] = __float2bfloat16(vv[q] - __bfloat162float(h));
        }
    }
#pragma unroll
    for (int o = 16; o; o >>= 1) s += __shfl_xor_sync(0xffffffffu, s, o);
    if (lane == 0) g_lam[row] = 2.f / (1.f - CC * s);
}

// ---------------- split-bf16 tensor-core GEMM via mma.sync ----------------
// C[128x128] = (Ahi+Alo)[128xK] @ (Bth+Btl)[128xK]^T  (Bt is [N,K] row-major)
// 8 warps: 4 (m) x 2 (n); warp tile 32x64; K-chunk 32; SMEM pitch 40 bf16.
#define SPITCH 40
template <int KDIM>
__global__ __launch_bounds__(256, 2)
void gemm_mma(const __nv_bfloat16* __restrict__ Ahi, const __nv_bfloat16* __restrict__ Alo,
              const __nv_bfloat16* __restrict__ Bth, const __nv_bfloat16* __restrict__ Btl,
              float* __restrict__ Mout, int Nfull)
{
    __shared__ __align__(16) __nv_bfloat16 Ash[128 * SPITCH];
    __shared__ __align__(16) __nv_bfloat16 Asl[128 * SPITCH];
    __shared__ __align__(16) __nv_bfloat16 Bsh[128 * SPITCH];
    __shared__ __align__(16) __nv_bfloat16 Bsl[128 * SPITCH];

    int tid = threadIdx.x, wid = tid >> 5, lane = tid & 31;
    int warp_m = wid >> 1, warp_n = wid & 1;
    int gID = lane >> 2, tig = lane & 3;
    long long bm = (long long)blockIdx.y * 128;
    int bn = blockIdx.x * 128;

    float acc[2][8][4];
#pragma unroll
    for (int m = 0; m < 2; m++)
#pragma unroll
        for (int n = 0; n < 8; n++)
#pragma unroll
            for (int q = 0; q < 4; q++) acc[m][n][q] = 0.f;

    for (int k0 = 0; k0 < KDIM; k0 += 32) {
        __syncthreads();
#pragma unroll
        for (int l = 0; l < 2; l++) {
            int idx = tid + l * 256;      // 0..511
            int row = idx >> 2, seg = idx & 3;
            long long ga = (bm + row) * KDIM + k0 + seg * 8;
            long long gb = (long long)(bn + row) * KDIM + k0 + seg * 8;
            *(uint4*)&Ash[row * SPITCH + seg * 8] = *(const uint4*)(Ahi + ga);
            *(uint4*)&Asl[row * SPITCH + seg * 8] = *(const uint4*)(Alo + ga);
            *(uint4*)&Bsh[row * SPITCH + seg * 8] = *(const uint4*)(Bth + gb);
            *(uint4*)&Bsl[row * SPITCH + seg * 8] = *(const uint4*)(Btl + gb);
        }
        __syncthreads();

#pragma unroll
        for (int ks = 0; ks < 32; ks += 16) {
            uint32_t ah[2][4], al[2][4];
            int kk = ks + tig * 2;
#pragma unroll
            for (int m = 0; m < 2; m++) {
                int r0 = warp_m * 32 + m * 16 + gID;
                ah[m][0] = *(const uint32_t*)&Ash[r0 * SPITCH + kk];
                ah[m][1] = *(const uint32_t*)&Ash[(r0 + 8) * SPITCH + kk];
                ah[m][2] = *(const uint32_t*)&Ash[r0 * SPITCH + kk + 8];
                ah[m][3] = *(const uint32_t*)&Ash[(r0 + 8) * SPITCH + kk + 8];
                al[m][0] = *(const uint32_t*)&Asl[r0 * SPITCH + kk];
                al[m][1] = *(const uint32_t*)&Asl[(r0 + 8) * SPITCH + kk];
                al[m][2] = *(const uint32_t*)&Asl[r0 * SPITCH + kk + 8];
                al[m][3] = *(const uint32_t*)&Asl[(r0 + 8) * SPITCH + kk + 8];
            }
#pragma unroll
            for (int n = 0; n < 8; n++) {
                int c0 = warp_n * 64 + n * 8 + gID;
                uint32_t bh[2], bl[2];
                bh[0] = *(const uint32_t*)&Bsh[c0 * SPITCH + kk];
                bh[1] = *(const uint32_t*)&Bsh[c0 * SPITCH + kk + 8];
                bl[0] = *(const uint32_t*)&Bsl[c0 * SPITCH + kk];
                bl[1] = *(const uint32_t*)&Bsl[c0 * SPITCH + kk + 8];
#pragma unroll
                for (int m = 0; m < 2; m++) {
                    mma16816(acc[m][n], ah[m], bh);
                    mma16816(acc[m][n], ah[m], bl);
                    mma16816(acc[m][n], al[m], bh);
                }
            }
        }
    }

    // write accumulators
#pragma unroll
    for (int m = 0; m < 2; m++) {
#pragma unroll
        for (int n = 0; n < 8; n++) {
            long long r = bm + warp_m * 32 + m * 16 + gID;
            int c = bn + warp_n * 64 + n * 8 + tig * 2;
            float2 v0 = make_float2(acc[m][n][0], acc[m][n][1]);
            float2 v1 = make_float2(acc[m][n][2], acc[m][n][3]);
            *(float2*)(Mout + r * Nfull + c) = v0;
            *(float2*)(Mout + (r + 8) * Nfull + c) = v1;
        }
    }
}

// ---------------- fused hlinear-epilogue + hrelu, warp per row; bf16 hi/lo out ----------------
template <int P>
__global__ void epi_kernel(const float* __restrict__ m,
                           __nv_bfloat16* __restrict__ hh, __nv_bfloat16* __restrict__ hl, int off)
{
    constexpr int FO = P * 32;
    int gid = blockIdx.x * blockDim.x + threadIdx.x;
    int row = gid >> 5, lane = gid & 31;
    const float cs = sqrtf(CC);

    float lam = g_lam[row];
    float w[P];
    float s = 0.f;
#pragma unroll
    for (int p = 0; p < P; p++) {
        int k = lane + 32 * p;
        float mm = m[(long long)row * FO + k];
        float zn = g_zn[off + k];
        float u  = cs * lam * mm / zn * g_chv[off + k] - (lam - 1.f) * g_shv[off + k];
        float ww = sinhf(2.f * zn * asinhf(u)) * (1.f / cs);
        w[p] = ww;
        s = fmaf(ww, ww, s);
    }
#pragma unroll
    for (int o = 16; o; o >>= 1) s += __shfl_xor_sync(0xffffffffu, s, o);
    float inv = 1.f / (1.f + sqrtf(1.f + CC * s));
    float sp = 0.f;
#pragma unroll
    for (int p = 0; p < P; p++) {
        float y = w[p] * inv;
        w[p] = y;
        float yp = fmaxf(y, 0.f);
        sp = fmaf(yp, yp, sp);
    }
#pragma unroll
    for (int o = 16; o; o >>= 1) sp += __shfl_xor_sync(0xffffffffu, sp, o);
    float n  = fmaxf(sqrtf(s) * inv, 1e-15f);
    float a  = atanhf(fminf(cs * n, 1.f - 1e-7f)) / (cs * n);
    float vn = fmaxf(a * sqrtf(sp), 1e-15f);
    float fac = tanhf(cs * vn) / (cs * vn) * a;
#pragma unroll
    for (int p = 0; p < P; p++) {
        int k = lane + 32 * p;
        float h = fac * fmaxf(w[p], 0.f);
        __nv_bfloat16 hb = __float2bfloat16(h);
        hh[(long long)row * FO + k] = hb;
        hl[(long long)row * FO + k] = __float2bfloat16(h - __bfloat162float(hb));
    }
    if (lane == 0) {
        float chv = coshf(cs * vn);
        g_lam[row] = 2.f * chv * chv;
    }
}

// ---------------- final layer fo=1 ----------------
__global__ void final_kernel(const __nv_bfloat16* __restrict__ hh, const __nv_bfloat16* __restrict__ hl,
                             const float* __restrict__ z4, float* __restrict__ out)
{
    int gid = blockIdx.x * blockDim.x + threadIdx.x;
    int row = gid >> 5, lane = gid & 31;
    float s = 0.f;
#pragma unroll
    for (int p = 0; p < 4; p++) {
        int k = lane + 32 * p;
        long long idx = (long long)row * 128 + k;
        float h = __bfloat162float(hh[idx]) + __bfloat162float(hl[idx]);
        s = fmaf(h, z4[k], s);
    }
#pragma unroll
    for (int o = 16; o; o >>= 1) s += __shfl_xor_sync(0xffffffffu, s, o);
    if (lane == 0) {
        const float cs = sqrtf(CC);
        float lam = g_lam[row];
        float zn = g_zn[896];
        float u = cs * lam * s / zn * g_chv[896] - (lam - 1.f) * g_shv[896];
        float w = sinhf(2.f * zn * asinhf(u)) * (1.f / cs);
        out[row] = w / (1.f + sqrtf(1.f + CC * w * w));
    }
}

// ---------------- launch ----------------
extern "C" void kernel_launch(void* const* d_in, const int* in_sizes, int n_in,
                              void* d_out, int out_size)
{
    const float* x  = (const float*)d_in[0];
    const float* z1 = (const float*)d_in[1];
    const float* b1 = (const float*)d_in[2];
    const float* z2 = (const float*)d_in[3];
    const float* b2 = (const float*)d_in[4];
    const float* z3 = (const float*)d_in[5];
    const float* b3 = (const float*)d_in[6];
    const float* z4 = (const float*)d_in[7];
    const float* b4 = (const float*)d_in[8];
    float* out = (float*)d_out;

    float* pm;            cudaGetSymbolAddress((void**)&pm, g_m);
    __nv_bfloat16 *xh, *xl, *h1h, *h1l, *h2h, *h2l, *h3h, *h3l;
    __nv_bfloat16 *t1h, *t1l, *t2h, *t2l, *t3h, *t3l;
    cudaGetSymbolAddress((void**)&xh, g_xhi);   cudaGetSymbolAddress((void**)&xl, g_xlo);
    cudaGetSymbolAddress((void**)&h1h, g_hhi);  cudaGetSymbolAddress((void**)&h1l, g_hlo);
    cudaGetSymbolAddress((void**)&h2h, g_h2hi); cudaGetSymbolAddress((void**)&h2l, g_h2lo);
    cudaGetSymbolAddress((void**)&h3h, g_h3hi); cudaGetSymbolAddress((void**)&h3l, g_h3lo);
    cudaGetSymbolAddress((void**)&t1h, g_zt1h); cudaGetSymbolAddress((void**)&t1l, g_zt1l);
    cudaGetSymbolAddress((void**)&t2h, g_zt2h); cudaGetSymbolAddress((void**)&t2l, g_zt2l);
    cudaGetSymbolAddress((void**)&t3h, g_zt3h); cudaGetSymbolAddress((void**)&t3l, g_zt3l);

    const int warpBlocks = BATCH * 32 / 256;

    lam0_kernel<<<warpBlocks, 256>>>(x);
    prep_kernel<<<2, 256>>>(z1, b1, 768, 512, 0);
    prep_kernel<<<1, 256>>>(z2, b2, 512, 256, 512);
    prep_kernel<<<1, 256>>>(z3, b3, 256, 128, 768);
    prep_kernel<<<1, 256>>>(z4, b4, 128, 1, 896);
    tsplit_kernel<<<(512 * 768 + 255) / 256, 256>>>(z1, t1h, t1l, 768, 512);
    tsplit_kernel<<<(256 * 512 + 255) / 256, 256>>>(z2, t2h, t2l, 512, 256);
    tsplit_kernel<<<(128 * 256 + 255) / 256, 256>>>(z3, t3h, t3l, 256, 128);

    // layer 1: (B,768) @ (768,512)
    gemm_mma<768><<<dim3(4, BATCH / 128), 256>>>(xh, xl, t1h, t1l, pm, 512);
    epi_kernel<16><<<warpBlocks, 256>>>(pm, h1h, h1l, 0);
    // layer 2: (B,512) @ (512,256)
    gemm_mma<512><<<dim3(2, BATCH / 128), 256>>>(h1h, h1l, t2h, t2l, pm, 256);
    epi_kernel<8><<<warpBlocks, 256>>>(pm, h2h, h2l, 512);
    // layer 3: (B,256) @ (256,128)
    gemm_mma<256><<<dim3(1, BATCH / 128), 256>>>(h2h, h2l, t3h, t3l, pm, 128);
    epi_kernel<4><<<warpBlocks, 256>>>(pm, h3h, h3l, 768);
    // layer 4
    final_kernel<<<warpBlocks, 256>>>(h3h, h3l, z4, out);
}

// round 6
// speedup vs baseline: 2.0186x; 1.1093x over previous
#include <cuda_runtime.h>
#include <cuda_bf16.h>
#include <math.h>
#include <stdint.h>

#define CC 2.3026f
#define BATCH 65536

// ---------------- static device scratch ----------------
__device__ __align__(256) __nv_bfloat16 g_xhi[(size_t)BATCH * 768];
__device__ __align__(256) __nv_bfloat16 g_xlo[(size_t)BATCH * 768];
__device__ __align__(256) __nv_bfloat16 g_hhi[(size_t)BATCH * 512];
__device__ __align__(256) __nv_bfloat16 g_hlo[(size_t)BATCH * 512];
__device__ __align__(256) __nv_bfloat16 g_h2hi[(size_t)BATCH * 256];
__device__ __align__(256) __nv_bfloat16 g_h2lo[(size_t)BATCH * 256];
__device__ __align__(256) __nv_bfloat16 g_h3hi[(size_t)BATCH * 128];
__device__ __align__(256) __nv_bfloat16 g_h3lo[(size_t)BATCH * 128];
__device__ float g_m[(size_t)BATCH * 512];
__device__ float g_lam[BATCH];
__device__ float g_zn[897], g_chv[897], g_shv[897];
// transposed split weights [N, K] row-major
__device__ __align__(256) __nv_bfloat16 g_zt1h[512 * 768], g_zt1l[512 * 768];
__device__ __align__(256) __nv_bfloat16 g_zt2h[256 * 512], g_zt2l[256 * 512];
__device__ __align__(256) __nv_bfloat16 g_zt3h[128 * 256], g_zt3l[128 * 256];

// ---------------- PTX helpers (baseline sm_80+ features only) ----------------
__device__ __forceinline__ uint32_t smem_u32(const void* p) {
    uint32_t a;
    asm("{ .reg .u64 t; cvta.to.shared.u64 t, %1; cvt.u32.u64 %0, t; }" : "=r"(a) : "l"(p));
    return a;
}
__device__ __forceinline__ void mma16816(float* d, const uint32_t* a, const uint32_t* b) {
    asm volatile(
        "mma.sync.aligned.m16n8k16.row.col.f32.bf16.bf16.f32 "
        "{%0,%1,%2,%3}, {%4,%5,%6,%7}, {%8,%9}, {%0,%1,%2,%3};"
        : "+f"(d[0]), "+f"(d[1]), "+f"(d[2]), "+f"(d[3])
        : "r"(a[0]), "r"(a[1]), "r"(a[2]), "r"(a[3]), "r"(b[0]), "r"(b[1]));
}
__device__ __forceinline__ void ldm_x4(uint32_t* r, uint32_t saddr) {
    asm volatile("ldmatrix.sync.aligned.m8n8.x4.shared.b16 {%0,%1,%2,%3}, [%4];"
        : "=r"(r[0]), "=r"(r[1]), "=r"(r[2]), "=r"(r[3]) : "r"(saddr));
}
#define CP16(sa, gp) asm volatile("cp.async.cg.shared.global [%0], [%1], 16;" :: "r"(sa), "l"(gp))
#define CP_COMMIT()  asm volatile("cp.async.commit_group;" ::: "memory")

// ---------------- prep kernels ----------------
__global__ void prep_kernel(const float* __restrict__ z, const float* __restrict__ r,
                            int fi, int fo, int off)
{
    int k = blockIdx.x * blockDim.x + threadIdx.x;
    if (k >= fo) return;
    float s = 0.f;
    for (int i = 0; i < fi; i++) { float v = z[(long long)i * fo + k]; s = fmaf(v, v, s); }
    float zn = fmaxf(sqrtf(s), 1e-15f);
    float t = 2.f * sqrtf(CC) * r[k];
    g_zn[off + k] = zn; g_chv[off + k] = coshf(t); g_shv[off + k] = sinhf(t);
}

__global__ void tsplit_kernel(const float* __restrict__ z,
                              __nv_bfloat16* __restrict__ th, __nv_bfloat16* __restrict__ tl,
                              int fi, int fo)
{
    int idx = blockIdx.x * blockDim.x + threadIdx.x;
    if (idx >= fi * fo) return;
    int n = idx / fi, k = idx - n * fi;
    float v = z[(long long)k * fo + n];
    __nv_bfloat16 h = __float2bfloat16(v);
    th[idx] = h;
    tl[idx] = __float2bfloat16(v - __bfloat162float(h));
}

// lam0 + split x into bf16 hi/lo. warp per row, fi=768.
__global__ void lam0_kernel(const float* __restrict__ x)
{
    int gid = blockIdx.x * blockDim.x + threadIdx.x;
    int row = gid >> 5, lane = gid & 31;
    const float4* xr = (const float4*)(x + (long long)row * 768);
    float s = 0.f;
#pragma unroll
    for (int p = 0; p < 6; p++) {
        int e4 = lane + 32 * p;
        float4 v = xr[e4];
        s += v.x * v.x + v.y * v.y + v.z * v.z + v.w * v.w;
        long long b = (long long)row * 768 + e4 * 4;
        float vv[4] = {v.x, v.y, v.z, v.w};
#pragma unroll
        for (int q = 0; q < 4; q++) {
            __nv_bfloat16 h = __float2bfloat16(vv[q]);
            g_xhi[b + q] = h;
            g_xlo[b + q] = __float2bfloat16(vv[q] - __bfloat162float(h));
        }
    }
#pragma unroll
    for (int o = 16; o; o >>= 1) s += __shfl_xor_sync(0xffffffffu, s, o);
    if (lane == 0) g_lam[row] = 2.f / (1.f - CC * s);
}

// ---------------- pipelined split-bf16 tensor-core GEMM ----------------
// C[128x128] = (Ahi+Alo)[128xK] @ (Bth+Btl)[128xK]^T   (Bt is [N,K] row-major)
// 8 warps 4(m) x 2(n), warp tile 32x64. K-chunk 32, cp.async double buffer.
// SMEM stage: A | Al | B | Bl, each 128 rows x 80B pitch (40 bf16) = 10240B.
#define STAGE_SZ 40960
template <int KDIM>
__global__ __launch_bounds__(256, 2)
void gemm_mma(const __nv_bfloat16* __restrict__ Ahi, const __nv_bfloat16* __restrict__ Alo,
              const __nv_bfloat16* __restrict__ Bth, const __nv_bfloat16* __restrict__ Btl,
              float* __restrict__ Mout, int Nfull)
{
    extern __shared__ char smem[];
    const uint32_t sbase = smem_u32(smem);
    constexpr int NB = KDIM / 32;

    int tid = threadIdx.x, wid = tid >> 5, lane = tid & 31;
    int warp_m = wid >> 1, warp_n = wid & 1;
    int gID = lane >> 2, tig = lane & 3;
    long long bm = (long long)blockIdx.y * 128;
    int bn = blockIdx.x * 128;

    // per-thread cp.async source/dest offsets (2 chunks of 16B per array)
    int c_row0 = tid >> 2, c_seg0 = tid & 3;
    int c_row1 = (tid + 256) >> 2, c_seg1 = (tid + 256) & 3;
    uint32_t so0 = (uint32_t)(c_row0 * 80 + c_seg0 * 16);
    uint32_t so1 = (uint32_t)(c_row1 * 80 + c_seg1 * 16);

    // ldmatrix lane offsets
    // A frag (x4): lane L -> row r0 + (L&15), col kk + (L>>4)*8
    uint32_t a_off0 = (uint32_t)((warp_m * 32 + (lane & 15)) * 80 + ((lane >> 4) * 8) * 2);
    uint32_t a_off1 = a_off0 + 16 * 80;
    // B frag (x4 = 2 n-groups): j=L>>3, t=L&7 -> row c0 + t + (j&2)*4, col kk + (j&1)*8
    uint32_t b_off = (uint32_t)((warp_n * 64 + (lane & 7) + ((lane >> 3) & 2) * 4) * 80
                                + (((lane >> 3) & 1) * 8) * 2);

    float acc[2][8][4];
#pragma unroll
    for (int m = 0; m < 2; m++)
#pragma unroll
        for (int n = 0; n < 8; n++)
#pragma unroll
            for (int q = 0; q < 4; q++) acc[m][n][q] = 0.f;

    // issue loads for a stage
    auto issue = [&](int stage, int k0) {
        uint32_t st = sbase + stage * STAGE_SZ;
        long long ga0 = (bm + c_row0) * KDIM + k0 + c_seg0 * 8;
        long long gb0 = (long long)(bn + c_row0) * KDIM + k0 + c_seg0 * 8;
        long long ga1 = (bm + c_row1) * KDIM + k0 + c_seg1 * 8;
        long long gb1 = (long long)(bn + c_row1) * KDIM + k0 + c_seg1 * 8;
        CP16(st + so0,          Ahi + ga0);
        CP16(st + 10240 + so0,  Alo + ga0);
        CP16(st + 20480 + so0,  Bth + gb0);
        CP16(st + 30720 + so0,  Btl + gb0);
        CP16(st + so1,          Ahi + ga1);
        CP16(st + 10240 + so1,  Alo + ga1);
        CP16(st + 20480 + so1,  Bth + gb1);
        CP16(st + 30720 + so1,  Btl + gb1);
    };

    issue(0, 0);
    CP_COMMIT();

    for (int i = 0; i < NB; i++) {
        if (i + 1 < NB) {
            issue((i + 1) & 1, (i + 1) * 32);
            CP_COMMIT();
            asm volatile("cp.async.wait_group 1;" ::: "memory");
        } else {
            asm volatile("cp.async.wait_group 0;" ::: "memory");
        }
        __syncthreads();

        uint32_t st = sbase + (i & 1) * STAGE_SZ;
        uint32_t sA = st, sAl = st + 10240, sB = st + 20480, sBl = st + 30720;

#pragma unroll
        for (int ks = 0; ks < 32; ks += 16) {
            uint32_t ah[2][4], al[2][4];
            ldm_x4(ah[0], sA  + a_off0 + ks * 2);
            ldm_x4(ah[1], sA  + a_off1 + ks * 2);
            ldm_x4(al[0], sAl + a_off0 + ks * 2);
            ldm_x4(al[1], sAl + a_off1 + ks * 2);
#pragma unroll
            for (int n2 = 0; n2 < 4; n2++) {
                uint32_t bh[4], bl[4];
                uint32_t boff = b_off + (uint32_t)(n2 * 16 * 80) + ks * 2;
                ldm_x4(bh, sB + boff);
                ldm_x4(bl, sBl + boff);
#pragma unroll
                for (int g = 0; g < 2; g++) {
#pragma unroll
                    for (int m = 0; m < 2; m++) {
                        mma16816(acc[m][n2 * 2 + g], ah[m], &bh[g * 2]);
                        mma16816(acc[m][n2 * 2 + g], ah[m], &bl[g * 2]);
                        mma16816(acc[m][n2 * 2 + g], al[m], &bh[g * 2]);
                    }
                }
            }
        }
        __syncthreads();
    }

    // write accumulators
#pragma unroll
    for (int m = 0; m < 2; m++) {
#pragma unroll
        for (int n = 0; n < 8; n++) {
            long long r = bm + warp_m * 32 + m * 16 + gID;
            int c = bn + warp_n * 64 + n * 8 + tig * 2;
            *(float2*)(Mout + r * Nfull + c)       = make_float2(acc[m][n][0], acc[m][n][1]);
            *(float2*)(Mout + (r + 8) * Nfull + c) = make_float2(acc[m][n][2], acc[m][n][3]);
        }
    }
}

// ---------------- fused hlinear-epilogue + hrelu, warp per row; bf16 hi/lo out ----------------
template <int P>
__global__ void epi_kernel(const float* __restrict__ m,
                           __nv_bfloat16* __restrict__ hh, __nv_bfloat16* __restrict__ hl, int off)
{
    constexpr int FO = P * 32;
    int gid = blockIdx.x * blockDim.x + threadIdx.x;
    int row = gid >> 5, lane = gid & 31;
    const float cs = sqrtf(CC);

    float lam = g_lam[row];
    float w[P];
    float s = 0.f;
#pragma unroll
    for (int p = 0; p < P; p++) {
        int k = lane + 32 * p;
        float mm = m[(long long)row * FO + k];
        float zn = g_zn[off + k];
        float u  = cs * lam * mm / zn * g_chv[off + k] - (lam - 1.f) * g_shv[off + k];
        float ww = sinhf(2.f * zn * asinhf(u)) * (1.f / cs);
        w[p] = ww;
        s = fmaf(ww, ww, s);
    }
#pragma unroll
    for (int o = 16; o; o >>= 1) s += __shfl_xor_sync(0xffffffffu, s, o);
    float inv = 1.f / (1.f + sqrtf(1.f + CC * s));
    float sp = 0.f;
#pragma unroll
    for (int p = 0; p < P; p++) {
        float y = w[p] * inv;
        w[p] = y;
        float yp = fmaxf(y, 0.f);
        sp = fmaf(yp, yp, sp);
    }
#pragma unroll
    for (int o = 16; o; o >>= 1) sp += __shfl_xor_sync(0xffffffffu, sp, o);
    float n  = fmaxf(sqrtf(s) * inv, 1e-15f);
    float a  = atanhf(fminf(cs * n, 1.f - 1e-7f)) / (cs * n);
    float vn = fmaxf(a * sqrtf(sp), 1e-15f);
    float fac = tanhf(cs * vn) / (cs * vn) * a;
#pragma unroll
    for (int p = 0; p < P; p++) {
        int k = lane + 32 * p;
        float h = fac * fmaxf(w[p], 0.f);
        __nv_bfloat16 hb = __float2bfloat16(h);
        hh[(long long)row * FO + k] = hb;
        hl[(long long)row * FO + k] = __float2bfloat16(h - __bfloat162float(hb));
    }
    if (lane == 0) {
        float chv = coshf(cs * vn);
        g_lam[row] = 2.f * chv * chv;
    }
}

// ---------------- final layer fo=1 ----------------
__global__ void final_kernel(const __nv_bfloat16* __restrict__ hh, const __nv_bfloat16* __restrict__ hl,
                             const float* __restrict__ z4, float* __restrict__ out)
{
    int gid = blockIdx.x * blockDim.x + threadIdx.x;
    int row = gid >> 5, lane = gid & 31;
    float s = 0.f;
#pragma unroll
    for (int p = 0; p < 4; p++) {
        int k = lane + 32 * p;
        long long idx = (long long)row * 128 + k;
        float h = __bfloat162float(hh[idx]) + __bfloat162float(hl[idx]);
        s = fmaf(h, z4[k], s);
    }
#pragma unroll
    for (int o = 16; o; o >>= 1) s += __shfl_xor_sync(0xffffffffu, s, o);
    if (lane == 0) {
        const float cs = sqrtf(CC);
        float lam = g_lam[row];
        float zn = g_zn[896];
        float u = cs * lam * s / zn * g_chv[896] - (lam - 1.f) * g_shv[896];
        float w = sinhf(2.f * zn * asinhf(u)) * (1.f / cs);
        out[row] = w / (1.f + sqrtf(1.f + CC * w * w));
    }
}

// ---------------- launch ----------------
extern "C" void kernel_launch(void* const* d_in, const int* in_sizes, int n_in,
                              void* d_out, int out_size)
{
    const float* x  = (const float*)d_in[0];
    const float* z1 = (const float*)d_in[1];
    const float* b1 = (const float*)d_in[2];
    const float* z2 = (const float*)d_in[3];
    const float* b2 = (const float*)d_in[4];
    const float* z3 = (const float*)d_in[5];
    const float* b3 = (const float*)d_in[6];
    const float* z4 = (const float*)d_in[7];
    const float* b4 = (const float*)d_in[8];
    float* out = (float*)d_out;

    float* pm;            cudaGetSymbolAddress((void**)&pm, g_m);
    __nv_bfloat16 *xh, *xl, *h1h, *h1l, *h2h, *h2l, *h3h, *h3l;
    __nv_bfloat16 *t1h, *t1l, *t2h, *t2l, *t3h, *t3l;
    cudaGetSymbolAddress((void**)&xh, g_xhi);   cudaGetSymbolAddress((void**)&xl, g_xlo);
    cudaGetSymbolAddress((void**)&h1h, g_hhi);  cudaGetSymbolAddress((void**)&h1l, g_hlo);
    cudaGetSymbolAddress((void**)&h2h, g_h2hi); cudaGetSymbolAddress((void**)&h2l, g_h2lo);
    cudaGetSymbolAddress((void**)&h3h, g_h3hi); cudaGetSymbolAddress((void**)&h3l, g_h3lo);
    cudaGetSymbolAddress((void**)&t1h, g_zt1h); cudaGetSymbolAddress((void**)&t1l, g_zt1l);
    cudaGetSymbolAddress((void**)&t2h, g_zt2h); cudaGetSymbolAddress((void**)&t2l, g_zt2l);
    cudaGetSymbolAddress((void**)&t3h, g_zt3h); cudaGetSymbolAddress((void**)&t3l, g_zt3l);

    const int SMEM_SZ = 2 * STAGE_SZ;  // 81920
    cudaFuncSetAttribute(gemm_mma<768>, cudaFuncAttributeMaxDynamicSharedMemorySize, SMEM_SZ);
    cudaFuncSetAttribute(gemm_mma<512>, cudaFuncAttributeMaxDynamicSharedMemorySize, SMEM_SZ);
    cudaFuncSetAttribute(gemm_mma<256>, cudaFuncAttributeMaxDynamicSharedMemorySize, SMEM_SZ);

    const int warpBlocks = BATCH * 32 / 256;

    lam0_kernel<<<warpBlocks, 256>>>(x);
    prep_kernel<<<2, 256>>>(z1, b1, 768, 512, 0);
    prep_kernel<<<1, 256>>>(z2, b2, 512, 256, 512);
    prep_kernel<<<1, 256>>>(z3, b3, 256, 128, 768);
    prep_kernel<<<1, 256>>>(z4, b4, 128, 1, 896);
    tsplit_kernel<<<(512 * 768 + 255) / 256, 256>>>(z1, t1h, t1l, 768, 512);
    tsplit_kernel<<<(256 * 512 + 255) / 256, 256>>>(z2, t2h, t2l, 512, 256);
    tsplit_kernel<<<(128 * 256 + 255) / 256, 256>>>(z3, t3h, t3l, 256, 128);

    // layer 1: (B,768) @ (768,512)
    gemm_mma<768><<<dim3(4, BATCH / 128), 256, SMEM_SZ>>>(xh, xl, t1h, t1l, pm, 512);
    epi_kernel<16><<<warpBlocks, 256>>>(pm, h1h, h1l, 0);
    // layer 2: (B,512) @ (512,256)
    gemm_mma<512><<<dim3(2, BATCH / 128), 256, SMEM_SZ>>>(h1h, h1l, t2h, t2l, pm, 256);
    epi_kernel<8><<<warpBlocks, 256>>>(pm, h2h, h2l, 512);
    // layer 3: (B,256) @ (256,128)
    gemm_mma<256><<<dim3(1, BATCH / 128), 256, SMEM_SZ>>>(h2h, h2l, t3h, t3l, pm, 128);
    epi_kernel<4><<<warpBlocks, 256>>>(pm, h3h, h3l, 768);
    // layer 4
    final_kernel<<<warpBlocks, 256>>>(h3h, h3l, z4, out);
}

// round 7
// speedup vs baseline: 2.3225x; 1.1506x over previous
#include <cuda_runtime.h>
#include <cuda_bf16.h>
#include <math.h>
#include <stdint.h>

#define CC 2.3026f
#define BATCH 65536

// ---------------- static device scratch ----------------
__device__ __align__(256) __nv_bfloat16 g_xhi[(size_t)BATCH * 768];
__device__ __align__(256) __nv_bfloat16 g_xlo[(size_t)BATCH * 768];
__device__ __align__(256) __nv_bfloat16 g_hhi[(size_t)BATCH * 512];
__device__ __align__(256) __nv_bfloat16 g_hlo[(size_t)BATCH * 512];
__device__ __align__(256) __nv_bfloat16 g_h2hi[(size_t)BATCH * 256];
__device__ __align__(256) __nv_bfloat16 g_h2lo[(size_t)BATCH * 256];
__device__ __align__(256) __nv_bfloat16 g_h3hi[(size_t)BATCH * 128];
__device__ __align__(256) __nv_bfloat16 g_h3lo[(size_t)BATCH * 128];
__device__ float g_m[(size_t)BATCH * 512];
__device__ float g_lam[BATCH];
// per-column tables: zn2 = 2*||z||, czn = cosh(2 cs r)/||z||, shv = sinh(2 cs r)
__device__ float g_zn2[897], g_czn[897], g_shv[897];
// transposed split weights [N, K] row-major
__device__ __align__(256) __nv_bfloat16 g_zt1h[512 * 768], g_zt1l[512 * 768];
__device__ __align__(256) __nv_bfloat16 g_zt2h[256 * 512], g_zt2l[256 * 512];
__device__ __align__(256) __nv_bfloat16 g_zt3h[128 * 256], g_zt3l[128 * 256];

// ---------------- PTX helpers (baseline sm_80+ features only) ----------------
__device__ __forceinline__ uint32_t smem_u32(const void* p) {
    uint32_t a;
    asm("{ .reg .u64 t; cvta.to.shared.u64 t, %1; cvt.u32.u64 %0, t; }" : "=r"(a) : "l"(p));
    return a;
}
__device__ __forceinline__ void mma16816(float* d, const uint32_t* a, const uint32_t* b) {
    asm volatile(
        "mma.sync.aligned.m16n8k16.row.col.f32.bf16.bf16.f32 "
        "{%0,%1,%2,%3}, {%4,%5,%6,%7}, {%8,%9}, {%0,%1,%2,%3};"
        : "+f"(d[0]), "+f"(d[1]), "+f"(d[2]), "+f"(d[3])
        : "r"(a[0]), "r"(a[1]), "r"(a[2]), "r"(a[3]), "r"(b[0]), "r"(b[1]));
}
__device__ __forceinline__ void ldm_x4(uint32_t* r, uint32_t saddr) {
    asm volatile("ldmatrix.sync.aligned.m8n8.x4.shared.b16 {%0,%1,%2,%3}, [%4];"
        : "=r"(r[0]), "=r"(r[1]), "=r"(r[2]), "=r"(r[3]) : "r"(saddr));
}
#define CP16(sa, gp) asm volatile("cp.async.cg.shared.global [%0], [%1], 16;" :: "r"(sa), "l"(gp))
#define CP_COMMIT()  asm volatile("cp.async.commit_group;" ::: "memory")

// ---------------- fast-math pieces ----------------
// sinh(zn2 * asinh(u)) = 0.5*(p - 1/p),  p = (u + sqrt(u^2+1))^zn2
__device__ __forceinline__ float sinh_zn_asinh(float u, float zn2) {
    float t = __logf(u + sqrtf(fmaf(u, u, 1.f)));
    float p = __expf(zn2 * t);
    return 0.5f * (p - __fdividef(1.f, p));
}

// ---------------- prep: warp per column ----------------
__global__ void prep_kernel(const float* __restrict__ z, const float* __restrict__ r,
                            int fi, int fo, int off)
{
    int gid = blockIdx.x * blockDim.x + threadIdx.x;
    int k = gid >> 5, lane = gid & 31;
    if (k >= fo) return;
    float s = 0.f;
    for (int i = lane; i < fi; i += 32) {
        float v = z[(long long)i * fo + k];
        s = fmaf(v, v, s);
    }
#pragma unroll
    for (int o = 16; o; o >>= 1) s += __shfl_xor_sync(0xffffffffu, s, o);
    if (lane == 0) {
        float zn = fmaxf(sqrtf(s), 1e-15f);
        float t = 2.f * sqrtf(CC) * r[k];
        float e = __expf(t);
        float ei = __fdividef(1.f, e);
        g_zn2[off + k] = 2.f * zn;
        g_czn[off + k] = 0.5f * (e + ei) / zn;
        g_shv[off + k] = 0.5f * (e - ei);
    }
}

__global__ void tsplit_kernel(const float* __restrict__ z,
                              __nv_bfloat16* __restrict__ th, __nv_bfloat16* __restrict__ tl,
                              int fi, int fo)
{
    int idx = blockIdx.x * blockDim.x + threadIdx.x;
    if (idx >= fi * fo) return;
    int n = idx / fi, k = idx - n * fi;
    float v = z[(long long)k * fo + n];
    __nv_bfloat16 h = __float2bfloat16(v);
    th[idx] = h;
    tl[idx] = __float2bfloat16(v - __bfloat162float(h));
}

// lam0 + split x into bf16 hi/lo. warp per row, fi=768.
__global__ void lam0_kernel(const float* __restrict__ x)
{
    int gid = blockIdx.x * blockDim.x + threadIdx.x;
    int row = gid >> 5, lane = gid & 31;
    const float4* xr = (const float4*)(x + (long long)row * 768);
    float s = 0.f;
#pragma unroll
    for (int p = 0; p < 6; p++) {
        int e4 = lane + 32 * p;
        float4 v = xr[e4];
        s += v.x * v.x + v.y * v.y + v.z * v.z + v.w * v.w;
        long long b = (long long)row * 768 + e4 * 4;
        float vv[4] = {v.x, v.y, v.z, v.w};
#pragma unroll
        for (int q = 0; q < 4; q++) {
            __nv_bfloat16 h = __float2bfloat16(vv[q]);
            g_xhi[b + q] = h;
            g_xlo[b + q] = __float2bfloat16(vv[q] - __bfloat162float(h));
        }
    }
#pragma unroll
    for (int o = 16; o; o >>= 1) s += __shfl_xor_sync(0xffffffffu, s, o);
    if (lane == 0) g_lam[row] = __fdividef(2.f, 1.f - CC * s);
}

// ---------------- pipelined split-bf16 tensor-core GEMM ----------------
#define STAGE_SZ 40960
template <int KDIM>
__global__ __launch_bounds__(256, 2)
void gemm_mma(const __nv_bfloat16* __restrict__ Ahi, const __nv_bfloat16* __restrict__ Alo,
              const __nv_bfloat16* __restrict__ Bth, const __nv_bfloat16* __restrict__ Btl,
              float* __restrict__ Mout, int Nfull)
{
    extern __shared__ char smem[];
    const uint32_t sbase = smem_u32(smem);
    constexpr int NB = KDIM / 32;

    int tid = threadIdx.x, wid = tid >> 5, lane = tid & 31;
    int warp_m = wid >> 1, warp_n = wid & 1;
    int gID = lane >> 2, tig = lane & 3;
    long long bm = (long long)blockIdx.y * 128;
    int bn = blockIdx.x * 128;

    int c_row0 = tid >> 2, c_seg0 = tid & 3;
    int c_row1 = (tid + 256) >> 2, c_seg1 = (tid + 256) & 3;
    uint32_t so0 = (uint32_t)(c_row0 * 80 + c_seg0 * 16);
    uint32_t so1 = (uint32_t)(c_row1 * 80 + c_seg1 * 16);

    uint32_t a_off0 = (uint32_t)((warp_m * 32 + (lane & 15)) * 80 + ((lane >> 4) * 8) * 2);
    uint32_t a_off1 = a_off0 + 16 * 80;
    uint32_t b_off = (uint32_t)((warp_n * 64 + (lane & 7) + ((lane >> 3) & 2) * 4) * 80
                                + (((lane >> 3) & 1) * 8) * 2);

    float acc[2][8][4];
#pragma unroll
    for (int m = 0; m < 2; m++)
#pragma unroll
        for (int n = 0; n < 8; n++)
#pragma unroll
            for (int q = 0; q < 4; q++) acc[m][n][q] = 0.f;

    auto issue = [&](int stage, int k0) {
        uint32_t st = sbase + stage * STAGE_SZ;
        long long ga0 = (bm + c_row0) * KDIM + k0 + c_seg0 * 8;
        long long gb0 = (long long)(bn + c_row0) * KDIM + k0 + c_seg0 * 8;
        long long ga1 = (bm + c_row1) * KDIM + k0 + c_seg1 * 8;
        long long gb1 = (long long)(bn + c_row1) * KDIM + k0 + c_seg1 * 8;
        CP16(st + so0,          Ahi + ga0);
        CP16(st + 10240 + so0,  Alo + ga0);
        CP16(st + 20480 + so0,  Bth + gb0);
        CP16(st + 30720 + so0,  Btl + gb0);
        CP16(st + so1,          Ahi + ga1);
        CP16(st + 10240 + so1,  Alo + ga1);
        CP16(st + 20480 + so1,  Bth + gb1);
        CP16(st + 30720 + so1,  Btl + gb1);
    };

    issue(0, 0);
    CP_COMMIT();

    for (int i = 0; i < NB; i++) {
        if (i + 1 < NB) {
            issue((i + 1) & 1, (i + 1) * 32);
            CP_COMMIT();
            asm volatile("cp.async.wait_group 1;" ::: "memory");
        } else {
            asm volatile("cp.async.wait_group 0;" ::: "memory");
        }
        __syncthreads();

        uint32_t st = sbase + (i & 1) * STAGE_SZ;
        uint32_t sA = st, sAl = st + 10240, sB = st + 20480, sBl = st + 30720;

#pragma unroll
        for (int ks = 0; ks < 32; ks += 16) {
            uint32_t ah[2][4], al[2][4];
            ldm_x4(ah[0], sA  + a_off0 + ks * 2);
            ldm_x4(ah[1], sA  + a_off1 + ks * 2);
            ldm_x4(al[0], sAl + a_off0 + ks * 2);
            ldm_x4(al[1], sAl + a_off1 + ks * 2);
#pragma unroll
            for (int n2 = 0; n2 < 4; n2++) {
                uint32_t bh[4], bl[4];
                uint32_t boff = b_off + (uint32_t)(n2 * 16 * 80) + ks * 2;
                ldm_x4(bh, sB + boff);
                ldm_x4(bl, sBl + boff);
#pragma unroll
                for (int g = 0; g < 2; g++) {
#pragma unroll
                    for (int m = 0; m < 2; m++) {
                        mma16816(acc[m][n2 * 2 + g], ah[m], &bh[g * 2]);
                        mma16816(acc[m][n2 * 2 + g], ah[m], &bl[g * 2]);
                        mma16816(acc[m][n2 * 2 + g], al[m], &bh[g * 2]);
                    }
                }
            }
        }
        __syncthreads();
    }

#pragma unroll
    for (int m = 0; m < 2; m++) {
#pragma unroll
        for (int n = 0; n < 8; n++) {
            long long r = bm + warp_m * 32 + m * 16 + gID;
            int c = bn + warp_n * 64 + n * 8 + tig * 2;
            *(float2*)(Mout + r * Nfull + c)       = make_float2(acc[m][n][0], acc[m][n][1]);
            *(float2*)(Mout + (r + 8) * Nfull + c) = make_float2(acc[m][n][2], acc[m][n][3]);
        }
    }
}

// ---------------- fused hlinear-epilogue + hrelu, warp per row; bf16 hi/lo out ----------------
template <int P>
__global__ void epi_kernel(const float* __restrict__ m,
                           __nv_bfloat16* __restrict__ hh, __nv_bfloat16* __restrict__ hl, int off)
{
    constexpr int FO = P * 32;
    int gid = blockIdx.x * blockDim.x + threadIdx.x;
    int row = gid >> 5, lane = gid & 31;
    const float cs = sqrtf(CC);

    float lam = g_lam[row];
    float a1 = cs * lam, a2 = lam - 1.f;
    float w[P];
    float s = 0.f;
#pragma unroll
    for (int p = 0; p < P; p++) {
        int k = lane + 32 * p;
        float mm = m[(long long)row * FO + k];
        float u = fmaf(a1 * mm, g_czn[off + k], -(a2 * g_shv[off + k]));
        float ww = sinh_zn_asinh(u, g_zn2[off + k]) * (1.f / cs);
        w[p] = ww;
        s = fmaf(ww, ww, s);
    }
#pragma unroll
    for (int o = 16; o; o >>= 1) s += __shfl_xor_sync(0xffffffffu, s, o);
    float inv = __fdividef(1.f, 1.f + sqrtf(fmaf(CC, s, 1.f)));
    float sp = 0.f;
#pragma unroll
    for (int p = 0; p < P; p++) {
        float y = w[p] * inv;
        w[p] = y;
        float yp = fmaxf(y, 0.f);
        sp = fmaf(yp, yp, sp);
    }
#pragma unroll
    for (int o = 16; o; o >>= 1) sp += __shfl_xor_sync(0xffffffffu, sp, o);
    float n  = fmaxf(sqrtf(s) * inv, 1e-15f);
    float cn = fminf(cs * n, 1.f - 1e-7f);
    float a  = __fdividef(0.5f * __logf(__fdividef(1.f + cn, 1.f - cn)), cs * n);
    float vn = fmaxf(a * sqrtf(sp), 1e-15f);
    float e  = __expf(2.f * cs * vn);
    float th = __fdividef(e - 1.f, e + 1.f);                    // tanh(cs*vn)
    float fac = __fdividef(th, cs * vn) * a;
#pragma unroll
    for (int p = 0; p < P; p++) {
        int k = lane + 32 * p;
        float h = fac * fmaxf(w[p], 0.f);
        __nv_bfloat16 hb = __float2bfloat16(h);
        hh[(long long)row * FO + k] = hb;
        hl[(long long)row * FO + k] = __float2bfloat16(h - __bfloat162float(hb));
    }
    if (lane == 0) {
        // lam_next = 2*cosh^2(cs*vn) = 0.5*(e + 2 + 1/e)
        g_lam[row] = 0.5f * (e + 2.f + __fdividef(1.f, e));
    }
}

// ---------------- final layer fo=1 ----------------
__global__ void final_kernel(const __nv_bfloat16* __restrict__ hh, const __nv_bfloat16* __restrict__ hl,
                             const float* __restrict__ z4, float* __restrict__ out)
{
    int gid = blockIdx.x * blockDim.x + threadIdx.x;
    int row = gid >> 5, lane = gid & 31;
    float s = 0.f;
#pragma unroll
    for (int p = 0; p < 4; p++) {
        int k = lane + 32 * p;
        long long idx = (long long)row * 128 + k;
        float h = __bfloat162float(hh[idx]) + __bfloat162float(hl[idx]);
        s = fmaf(h, z4[k], s);
    }
#pragma unroll
    for (int o = 16; o; o >>= 1) s += __shfl_xor_sync(0xffffffffu, s, o);
    if (lane == 0) {
        const float cs = sqrtf(CC);
        float lam = g_lam[row];
        float u = fmaf(cs * lam * s, g_czn[896], -((lam - 1.f) * g_shv[896]));
        float w = sinh_zn_asinh(u, g_zn2[896]) * (1.f / cs);
        out[row] = __fdividef(w, 1.f + sqrtf(fmaf(CC, w * w, 1.f)));
    }
}

// ---------------- launch ----------------
extern "C" void kernel_launch(void* const* d_in, const int* in_sizes, int n_in,
                              void* d_out, int out_size)
{
    const float* x  = (const float*)d_in[0];
    const float* z1 = (const float*)d_in[1];
    const float* b1 = (const float*)d_in[2];
    const float* z2 = (const float*)d_in[3];
    const float* b2 = (const float*)d_in[4];
    const float* z3 = (const float*)d_in[5];
    const float* b3 = (const float*)d_in[6];
    const float* z4 = (const float*)d_in[7];
    const float* b4 = (const float*)d_in[8];
    float* out = (float*)d_out;

    float* pm;            cudaGetSymbolAddress((void**)&pm, g_m);
    __nv_bfloat16 *xh, *xl, *h1h, *h1l, *h2h, *h2l, *h3h, *h3l;
    __nv_bfloat16 *t1h, *t1l, *t2h, *t2l, *t3h, *t3l;
    cudaGetSymbolAddress((void**)&xh, g_xhi);   cudaGetSymbolAddress((void**)&xl, g_xlo);
    cudaGetSymbolAddress((void**)&h1h, g_hhi);  cudaGetSymbolAddress((void**)&h1l, g_hlo);
    cudaGetSymbolAddress((void**)&h2h, g_h2hi); cudaGetSymbolAddress((void**)&h2l, g_h2lo);
    cudaGetSymbolAddress((void**)&h3h, g_h3hi); cudaGetSymbolAddress((void**)&h3l, g_h3lo);
    cudaGetSymbolAddress((void**)&t1h, g_zt1h); cudaGetSymbolAddress((void**)&t1l, g_zt1l);
    cudaGetSymbolAddress((void**)&t2h, g_zt2h); cudaGetSymbolAddress((void**)&t2l, g_zt2l);
    cudaGetSymbolAddress((void**)&t3h, g_zt3h); cudaGetSymbolAddress((void**)&t3l, g_zt3l);

    const int SMEM_SZ = 2 * STAGE_SZ;  // 81920
    cudaFuncSetAttribute(gemm_mma<768>, cudaFuncAttributeMaxDynamicSharedMemorySize, SMEM_SZ);
    cudaFuncSetAttribute(gemm_mma<512>, cudaFuncAttributeMaxDynamicSharedMemorySize, SMEM_SZ);
    cudaFuncSetAttribute(gemm_mma<256>, cudaFuncAttributeMaxDynamicSharedMemorySize, SMEM_SZ);

    const int warpBlocks = BATCH * 32 / 256;

    lam0_kernel<<<warpBlocks, 256>>>(x);
    prep_kernel<<<(512 * 32 + 255) / 256, 256>>>(z1, b1, 768, 512, 0);
    prep_kernel<<<(256 * 32 + 255) / 256, 256>>>(z2, b2, 512, 256, 512);
    prep_kernel<<<(128 * 32 + 255) / 256, 256>>>(z3, b3, 256, 128, 768);
    prep_kernel<<<1, 32>>>(z4, b4, 128, 1, 896);
    tsplit_kernel<<<(512 * 768 + 255) / 256, 256>>>(z1, t1h, t1l, 768, 512);
    tsplit_kernel<<<(256 * 512 + 255) / 256, 256>>>(z2, t2h, t2l, 512, 256);
    tsplit_kernel<<<(128 * 256 + 255) / 256, 256>>>(z3, t3h, t3l, 256, 128);

    // layer 1: (B,768) @ (768,512)
    gemm_mma<768><<<dim3(4, BATCH / 128), 256, SMEM_SZ>>>(xh, xl, t1h, t1l, pm, 512);
    epi_kernel<16><<<warpBlocks, 256>>>(pm, h1h, h1l, 0);
    // layer 2: (B,512) @ (512,256)
    gemm_mma<512><<<dim3(2, BATCH / 128), 256, SMEM_SZ>>>(h1h, h1l, t2h, t2l, pm, 256);
    epi_kernel<8><<<warpBlocks, 256>>>(pm, h2h, h2l, 512);
    // layer 3: (B,256) @ (256,128)
    gemm_mma<256><<<dim3(1, BATCH / 128), 256, SMEM_SZ>>>(h2h, h2l, t3h, t3l, pm, 128);
    epi_kernel<4><<<warpBlocks, 256>>>(pm, h3h, h3l, 768);
    // layer 4
    final_kernel<<<warpBlocks, 256>>>(h3h, h3l, z4, out);
}

// round 8
// speedup vs baseline: 2.4681x; 1.0627x over previous
#include <cuda_runtime.h>
#include <cuda_bf16.h>
#include <math.h>
#include <stdint.h>

#define CC 2.3026f
#define BATCH 65536

// ---------------- static device scratch ----------------
__device__ __align__(256) __nv_bfloat16 g_xhi[(size_t)BATCH * 768];
__device__ __align__(256) __nv_bfloat16 g_xlo[(size_t)BATCH * 768];
__device__ __align__(256) __nv_bfloat16 g_hhi[(size_t)BATCH * 512];
__device__ __align__(256) __nv_bfloat16 g_hlo[(size_t)BATCH * 512];
__device__ __align__(256) __nv_bfloat16 g_h2hi[(size_t)BATCH * 256];
__device__ __align__(256) __nv_bfloat16 g_h2lo[(size_t)BATCH * 256];
__device__ __align__(256) __nv_bfloat16 g_h3hi[(size_t)BATCH * 128];
__device__ __align__(256) __nv_bfloat16 g_h3lo[(size_t)BATCH * 128];
__device__ float g_m[(size_t)BATCH * 512];       // w values (fp32)
__device__ float g_lam[BATCH];
__device__ float g_fac[BATCH];
__device__ float2 g_psum[(size_t)BATCH * 4];     // per (row, n-tile) partial sums
__device__ float g_zn2[897], g_czn[897], g_shv[897];
// transposed split weights [N, K] row-major
__device__ __align__(256) __nv_bfloat16 g_zt1h[512 * 768], g_zt1l[512 * 768];
__device__ __align__(256) __nv_bfloat16 g_zt2h[256 * 512], g_zt2l[256 * 512];
__device__ __align__(256) __nv_bfloat16 g_zt3h[128 * 256], g_zt3l[128 * 256];

// ---------------- PTX helpers ----------------
__device__ __forceinline__ uint32_t smem_u32(const void* p) {
    uint32_t a;
    asm("{ .reg .u64 t; cvta.to.shared.u64 t, %1; cvt.u32.u64 %0, t; }" : "=r"(a) : "l"(p));
    return a;
}
__device__ __forceinline__ void mma16816(float* d, const uint32_t* a, const uint32_t* b) {
    asm volatile(
        "mma.sync.aligned.m16n8k16.row.col.f32.bf16.bf16.f32 "
        "{%0,%1,%2,%3}, {%4,%5,%6,%7}, {%8,%9}, {%0,%1,%2,%3};"
        : "+f"(d[0]), "+f"(d[1]), "+f"(d[2]), "+f"(d[3])
        : "r"(a[0]), "r"(a[1]), "r"(a[2]), "r"(a[3]), "r"(b[0]), "r"(b[1]));
}
__device__ __forceinline__ void ldm_x4(uint32_t* r, uint32_t saddr) {
    asm volatile("ldmatrix.sync.aligned.m8n8.x4.shared.b16 {%0,%1,%2,%3}, [%4];"
        : "=r"(r[0]), "=r"(r[1]), "=r"(r[2]), "=r"(r[3]) : "r"(saddr));
}
#define CP16(sa, gp) asm volatile("cp.async.cg.shared.global [%0], [%1], 16;" :: "r"(sa), "l"(gp))
#define CP_COMMIT()  asm volatile("cp.async.commit_group;" ::: "memory")

// w = sinh(zn2 * asinh(u)) / cs,  u = a1*m*czn - a2*shv
__device__ __forceinline__ float wcalc(float mm, float a1, float a2,
                                       float czn, float shv, float zn2, float invcs)
{
    float u = fmaf(a1 * mm, czn, -(a2 * shv));
    float t = __logf(u + sqrtf(fmaf(u, u, 1.f)));
    float p = __expf(zn2 * t);
    return (p - __fdividef(1.f, p)) * (0.5f * invcs);
}

// ---------------- prep: warp per column ----------------
__global__ void prep_kernel(const float* __restrict__ z, const float* __restrict__ r,
                            int fi, int fo, int off)
{
    int gid = blockIdx.x * blockDim.x + threadIdx.x;
    int k = gid >> 5, lane = gid & 31;
    if (k >= fo) return;
    float s = 0.f;
    for (int i = lane; i < fi; i += 32) {
        float v = z[(long long)i * fo + k];
        s = fmaf(v, v, s);
    }
#pragma unroll
    for (int o = 16; o; o >>= 1) s += __shfl_xor_sync(0xffffffffu, s, o);
    if (lane == 0) {
        float zn = fmaxf(sqrtf(s), 1e-15f);
        float t = 2.f * sqrtf(CC) * r[k];
        float e = __expf(t);
        float ei = __fdividef(1.f, e);
        g_zn2[off + k] = 2.f * zn;
        g_czn[off + k] = 0.5f * (e + ei) / zn;
        g_shv[off + k] = 0.5f * (e - ei);
    }
}

__global__ void tsplit_kernel(const float* __restrict__ z,
                              __nv_bfloat16* __restrict__ th, __nv_bfloat16* __restrict__ tl,
                              int fi, int fo)
{
    int idx = blockIdx.x * blockDim.x + threadIdx.x;
    if (idx >= fi * fo) return;
    int n = idx / fi, k = idx - n * fi;
    float v = z[(long long)k * fo + n];
    __nv_bfloat16 h = __float2bfloat16(v);
    th[idx] = h;
    tl[idx] = __float2bfloat16(v - __bfloat162float(h));
}

// lam0 + split x into bf16 hi/lo. warp per row, fi=768.
__global__ void lam0_kernel(const float* __restrict__ x)
{
    int gid = blockIdx.x * blockDim.x + threadIdx.x;
    int row = gid >> 5, lane = gid & 31;
    const float4* xr = (const float4*)(x + (long long)row * 768);
    float s = 0.f;
#pragma unroll
    for (int p = 0; p < 6; p++) {
        int e4 = lane + 32 * p;
        float4 v = xr[e4];
        s += v.x * v.x + v.y * v.y + v.z * v.z + v.w * v.w;
        long long b = (long long)row * 768 + e4 * 4;
        float vv[4] = {v.x, v.y, v.z, v.w};
#pragma unroll
        for (int q = 0; q < 4; q++) {
            __nv_bfloat16 h = __float2bfloat16(vv[q]);
            g_xhi[b + q] = h;
            g_xlo[b + q] = __float2bfloat16(vv[q] - __bfloat162float(h));
        }
    }
#pragma unroll
    for (int o = 16; o; o >>= 1) s += __shfl_xor_sync(0xffffffffu, s, o);
    if (lane == 0) g_lam[row] = __fdividef(2.f, 1.f - CC * s);
}

// ---------------- pipelined split-bf16 GEMM + fused w-transform ----------------
#define STAGE_SZ 40960
template <int KDIM>
__global__ __launch_bounds__(256, 2)
void gemm_mma(const __nv_bfloat16* __restrict__ Ahi, const __nv_bfloat16* __restrict__ Alo,
              const __nv_bfloat16* __restrict__ Bth, const __nv_bfloat16* __restrict__ Btl,
              float* __restrict__ Mout, int Nfull, int offTab, float2* __restrict__ psum)
{
    extern __shared__ char smem[];
    const uint32_t sbase = smem_u32(smem);
    constexpr int NB = KDIM / 32;

    int tid = threadIdx.x, wid = tid >> 5, lane = tid & 31;
    int warp_m = wid >> 1, warp_n = wid & 1;
    int gID = lane >> 2, tig = lane & 3;
    long long bm = (long long)blockIdx.y * 128;
    int bn = blockIdx.x * 128;
    int ntiles = gridDim.x;

    int c_row0 = tid >> 2, c_seg0 = tid & 3;
    int c_row1 = (tid + 256) >> 2, c_seg1 = (tid + 256) & 3;
    uint32_t so0 = (uint32_t)(c_row0 * 80 + c_seg0 * 16);
    uint32_t so1 = (uint32_t)(c_row1 * 80 + c_seg1 * 16);

    uint32_t a_off0 = (uint32_t)((warp_m * 32 + (lane & 15)) * 80 + ((lane >> 4) * 8) * 2);
    uint32_t a_off1 = a_off0 + 16 * 80;
    uint32_t b_off = (uint32_t)((warp_n * 64 + (lane & 7) + ((lane >> 3) & 2) * 4) * 80
                                + (((lane >> 3) & 1) * 8) * 2);

    float acc[2][8][4];
#pragma unroll
    for (int m = 0; m < 2; m++)
#pragma unroll
        for (int n = 0; n < 8; n++)
#pragma unroll
            for (int q = 0; q < 4; q++) acc[m][n][q] = 0.f;

    auto issue = [&](int stage, int k0) {
        uint32_t st = sbase + stage * STAGE_SZ;
        long long ga0 = (bm + c_row0) * KDIM + k0 + c_seg0 * 8;
        long long gb0 = (long long)(bn + c_row0) * KDIM + k0 + c_seg0 * 8;
        long long ga1 = (bm + c_row1) * KDIM + k0 + c_seg1 * 8;
        long long gb1 = (long long)(bn + c_row1) * KDIM + k0 + c_seg1 * 8;
        CP16(st + so0,          Ahi + ga0);
        CP16(st + 10240 + so0,  Alo + ga0);
        CP16(st + 20480 + so0,  Bth + gb0);
        CP16(st + 30720 + so0,  Btl + gb0);
        CP16(st + so1,          Ahi + ga1);
        CP16(st + 10240 + so1,  Alo + ga1);
        CP16(st + 20480 + so1,  Bth + gb1);
        CP16(st + 30720 + so1,  Btl + gb1);
    };

    issue(0, 0);
    CP_COMMIT();

    for (int i = 0; i < NB; i++) {
        if (i + 1 < NB) {
            issue((i + 1) & 1, (i + 1) * 32);
            CP_COMMIT();
            asm volatile("cp.async.wait_group 1;" ::: "memory");
        } else {
            asm volatile("cp.async.wait_group 0;" ::: "memory");
        }
        __syncthreads();

        uint32_t st = sbase + (i & 1) * STAGE_SZ;
        uint32_t sA = st, sAl = st + 10240, sB = st + 20480, sBl = st + 30720;

#pragma unroll
        for (int ks = 0; ks < 32; ks += 16) {
            uint32_t ah[2][4], al[2][4];
            ldm_x4(ah[0], sA  + a_off0 + ks * 2);
            ldm_x4(ah[1], sA  + a_off1 + ks * 2);
            ldm_x4(al[0], sAl + a_off0 + ks * 2);
            ldm_x4(al[1], sAl + a_off1 + ks * 2);
#pragma unroll
            for (int n2 = 0; n2 < 4; n2++) {
                uint32_t bh[4], bl[4];
                uint32_t boff = b_off + (uint32_t)(n2 * 16 * 80) + ks * 2;
                ldm_x4(bh, sB + boff);
                ldm_x4(bl, sBl + boff);
#pragma unroll
                for (int g = 0; g < 2; g++) {
#pragma unroll
                    for (int m = 0; m < 2; m++) {
                        mma16816(acc[m][n2 * 2 + g], ah[m], &bh[g * 2]);
                        mma16816(acc[m][n2 * 2 + g], ah[m], &bl[g * 2]);
                        mma16816(acc[m][n2 * 2 + g], al[m], &bh[g * 2]);
                    }
                }
            }
        }
        __syncthreads();
    }

    // ---- fused epilogue: m -> w, plus per-row partial sums ----
    const float cs = sqrtf(CC);
    const float invcs = 1.f / cs;
    float s4[4] = {0.f, 0.f, 0.f, 0.f}, sp4[4] = {0.f, 0.f, 0.f, 0.f};
#pragma unroll
    for (int m = 0; m < 2; m++) {
        long long rA = bm + warp_m * 32 + m * 16 + gID;
        float lamA = g_lam[rA], lamB = g_lam[rA + 8];
        float a1A = cs * lamA, a2A = lamA - 1.f;
        float a1B = cs * lamB, a2B = lamB - 1.f;
#pragma unroll
        for (int n = 0; n < 8; n++) {
            int k = offTab + bn + warp_n * 64 + n * 8 + tig * 2;
            float czn0 = g_czn[k], czn1 = g_czn[k + 1];
            float shv0 = g_shv[k], shv1 = g_shv[k + 1];
            float zn0  = g_zn2[k], zn1  = g_zn2[k + 1];
            float w0 = wcalc(acc[m][n][0], a1A, a2A, czn0, shv0, zn0, invcs);
            float w1 = wcalc(acc[m][n][1], a1A, a2A, czn1, shv1, zn1, invcs);
            float w2 = wcalc(acc[m][n][2], a1B, a2B, czn0, shv0, zn0, invcs);
            float w3 = wcalc(acc[m][n][3], a1B, a2B, czn1, shv1, zn1, invcs);
            acc[m][n][0] = w0; acc[m][n][1] = w1; acc[m][n][2] = w2; acc[m][n][3] = w3;
            s4[m * 2]     += fmaf(w0, w0, w1 * w1);
            s4[m * 2 + 1] += fmaf(w2, w2, w3 * w3);
            float p0 = fmaxf(w0, 0.f), p1 = fmaxf(w1, 0.f);
            float p2 = fmaxf(w2, 0.f), p3 = fmaxf(w3, 0.f);
            sp4[m * 2]     += fmaf(p0, p0, p1 * p1);
            sp4[m * 2 + 1] += fmaf(p2, p2, p3 * p3);
        }
    }
#pragma unroll
    for (int q = 0; q < 4; q++) {
        s4[q]  += __shfl_xor_sync(0xffffffffu, s4[q], 1);
        s4[q]  += __shfl_xor_sync(0xffffffffu, s4[q], 2);
        sp4[q] += __shfl_xor_sync(0xffffffffu, sp4[q], 1);
        sp4[q] += __shfl_xor_sync(0xffffffffu, sp4[q], 2);
    }
    float2* sred = (float2*)smem;
    if (tig == 0) {
        int rl = warp_m * 32 + gID;
        sred[(rl)      * 2 + warp_n] = make_float2(s4[0], sp4[0]);
        sred[(rl + 8)  * 2 + warp_n] = make_float2(s4[1], sp4[1]);
        sred[(rl + 16) * 2 + warp_n] = make_float2(s4[2], sp4[2]);
        sred[(rl + 24) * 2 + warp_n] = make_float2(s4[3], sp4[3]);
    }
    __syncthreads();
    if (tid < 128) {
        float2 a = sred[tid * 2], b = sred[tid * 2 + 1];
        psum[(bm + tid) * ntiles + blockIdx.x] = make_float2(a.x + b.x, a.y + b.y);
    }

    // store w
#pragma unroll
    for (int m = 0; m < 2; m++) {
#pragma unroll
        for (int n = 0; n < 8; n++) {
            long long r = bm + warp_m * 32 + m * 16 + gID;
            int c = bn + warp_n * 64 + n * 8 + tig * 2;
            *(float2*)(Mout + r * Nfull + c)       = make_float2(acc[m][n][0], acc[m][n][1]);
            *(float2*)(Mout + (r + 8) * Nfull + c) = make_float2(acc[m][n][2], acc[m][n][3]);
        }
    }
}

// ---------------- per-row factor kernel ----------------
template <int NT>
__global__ void rowfac_kernel(const float2* __restrict__ ps,
                              float* __restrict__ fac, float* __restrict__ lam)
{
    int row = blockIdx.x * blockDim.x + threadIdx.x;
    float s = 0.f, sp = 0.f;
#pragma unroll
    for (int t = 0; t < NT; t++) {
        float2 v = ps[(long long)row * NT + t];
        s += v.x; sp += v.y;
    }
    const float cs = sqrtf(CC);
    float inv = __fdividef(1.f, 1.f + sqrtf(fmaf(CC, s, 1.f)));
    float n  = fmaxf(sqrtf(s) * inv, 1e-15f);
    float cn = fminf(cs * n, 1.f - 1e-7f);
    float a  = __fdividef(0.5f * __logf(__fdividef(1.f + cn, 1.f - cn)), cs * n);
    float vn = fmaxf(a * inv * sqrtf(sp), 1e-15f);
    float e  = __expf(2.f * cs * vn);
    float th = __fdividef(e - 1.f, e + 1.f);
    float fc = __fdividef(th, cs * vn) * a;
    fac[row] = fc * inv;
    lam[row] = 0.5f * (e + 2.f + __fdividef(1.f, e));
}

// ---------------- apply: h = fac*max(w,0) -> bf16 hi/lo ----------------
template <int SHIFT>
__global__ void apply_kernel(const float* __restrict__ w, const float* __restrict__ fac,
                             __nv_bfloat16* __restrict__ hh, __nv_bfloat16* __restrict__ hl)
{
    int gid = blockIdx.x * blockDim.x + threadIdx.x;  // one per 4 elements
    int row = gid >> SHIFT;
    float4 wv = ((const float4*)w)[gid];
    float f = fac[row];
    float h0 = f * fmaxf(wv.x, 0.f), h1 = f * fmaxf(wv.y, 0.f);
    float h2 = f * fmaxf(wv.z, 0.f), h3 = f * fmaxf(wv.w, 0.f);
    __nv_bfloat16 b0 = __float2bfloat16(h0), b1 = __float2bfloat16(h1);
    __nv_bfloat16 b2 = __float2bfloat16(h2), b3 = __float2bfloat16(h3);
    __nv_bfloat162 hi0; hi0.x = b0; hi0.y = b1;
    __nv_bfloat162 hi1; hi1.x = b2; hi1.y = b3;
    __nv_bfloat162 lo0, lo1;
    lo0.x = __float2bfloat16(h0 - __bfloat162float(b0));
    lo0.y = __float2bfloat16(h1 - __bfloat162float(b1));
    lo1.x = __float2bfloat16(h2 - __bfloat162float(b2));
    lo1.y = __float2bfloat16(h3 - __bfloat162float(b3));
    ((__nv_bfloat162*)hh)[gid * 2]     = hi0;
    ((__nv_bfloat162*)hh)[gid * 2 + 1] = hi1;
    ((__nv_bfloat162*)hl)[gid * 2]     = lo0;
    ((__nv_bfloat162*)hl)[gid * 2 + 1] = lo1;
}

// ---------------- final layer fo=1 ----------------
__global__ void final_kernel(const __nv_bfloat16* __restrict__ hh, const __nv_bfloat16* __restrict__ hl,
                             const float* __restrict__ z4, float* __restrict__ out)
{
    int gid = blockIdx.x * blockDim.x + threadIdx.x;
    int row = gid >> 5, lane = gid & 31;
    float s = 0.f;
#pragma unroll
    for (int p = 0; p < 4; p++) {
        int k = lane + 32 * p;
        long long idx = (long long)row * 128 + k;
        float h = __bfloat162float(hh[idx]) + __bfloat162float(hl[idx]);
        s = fmaf(h, z4[k], s);
    }
#pragma unroll
    for (int o = 16; o; o >>= 1) s += __shfl_xor_sync(0xffffffffu, s, o);
    if (lane == 0) {
        const float cs = sqrtf(CC);
        float lam = g_lam[row];
        float u = fmaf(cs * lam * s, g_czn[896], -((lam - 1.f) * g_shv[896]));
        float t = __logf(u + sqrtf(fmaf(u, u, 1.f)));
        float p = __expf(g_zn2[896] * t);
        float w = (p - __fdividef(1.f, p)) * (0.5f / cs);
        out[row] = __fdividef(w, 1.f + sqrtf(fmaf(CC, w * w, 1.f)));
    }
}

// ---------------- launch ----------------
extern "C" void kernel_launch(void* const* d_in, const int* in_sizes, int n_in,
                              void* d_out, int out_size)
{
    const float* x  = (const float*)d_in[0];
    const float* z1 = (const float*)d_in[1];
    const float* b1 = (const float*)d_in[2];
    const float* z2 = (const float*)d_in[3];
    const float* b2 = (const float*)d_in[4];
    const float* z3 = (const float*)d_in[5];
    const float* b3 = (const float*)d_in[6];
    const float* z4 = (const float*)d_in[7];
    const float* b4 = (const float*)d_in[8];
    float* out = (float*)d_out;

    float* pm;   cudaGetSymbolAddress((void**)&pm, g_m);
    float* pfac; cudaGetSymbolAddress((void**)&pfac, g_fac);
    float* plam; cudaGetSymbolAddress((void**)&plam, g_lam);
    float2* pps; cudaGetSymbolAddress((void**)&pps, g_psum);
    __nv_bfloat16 *xh, *xl, *h1h, *h1l, *h2h, *h2l, *h3h, *h3l;
    __nv_bfloat16 *t1h, *t1l, *t2h, *t2l, *t3h, *t3l;
    cudaGetSymbolAddress((void**)&xh, g_xhi);   cudaGetSymbolAddress((void**)&xl, g_xlo);
    cudaGetSymbolAddress((void**)&h1h, g_hhi);  cudaGetSymbolAddress((void**)&h1l, g_hlo);
    cudaGetSymbolAddress((void**)&h2h, g_h2hi); cudaGetSymbolAddress((void**)&h2l, g_h2lo);
    cudaGetSymbolAddress((void**)&h3h, g_h3hi); cudaGetSymbolAddress((void**)&h3l, g_h3lo);
    cudaGetSymbolAddress((void**)&t1h, g_zt1h); cudaGetSymbolAddress((void**)&t1l, g_zt1l);
    cudaGetSymbolAddress((void**)&t2h, g_zt2h); cudaGetSymbolAddress((void**)&t2l, g_zt2l);
    cudaGetSymbolAddress((void**)&t3h, g_zt3h); cudaGetSymbolAddress((void**)&t3l, g_zt3l);

    const int SMEM_SZ = 2 * STAGE_SZ;  // 81920
    cudaFuncSetAttribute(gemm_mma<768>, cudaFuncAttributeMaxDynamicSharedMemorySize, SMEM_SZ);
    cudaFuncSetAttribute(gemm_mma<512>, cudaFuncAttributeMaxDynamicSharedMemorySize, SMEM_SZ);
    cudaFuncSetAttribute(gemm_mma<256>, cudaFuncAttributeMaxDynamicSharedMemorySize, SMEM_SZ);

    const int warpBlocks = BATCH * 32 / 256;

    lam0_kernel<<<warpBlocks, 256>>>(x);
    prep_kernel<<<(512 * 32 + 255) / 256, 256>>>(z1, b1, 768, 512, 0);
    prep_kernel<<<(256 * 32 + 255) / 256, 256>>>(z2, b2, 512, 256, 512);
    prep_kernel<<<(128 * 32 + 255) / 256, 256>>>(z3, b3, 256, 128, 768);
    prep_kernel<<<1, 32>>>(z4, b4, 128, 1, 896);
    tsplit_kernel<<<(512 * 768 + 255) / 256, 256>>>(z1, t1h, t1l, 768, 512);
    tsplit_kernel<<<(256 * 512 + 255) / 256, 256>>>(z2, t2h, t2l, 512, 256);
    tsplit_kernel<<<(128 * 256 + 255) / 256, 256>>>(z3, t3h, t3l, 256, 128);

    // layer 1: (B,768) @ (768,512)
    gemm_mma<768><<<dim3(4, BATCH / 128), 256, SMEM_SZ>>>(xh, xl, t1h, t1l, pm, 512, 0, pps);
    rowfac_kernel<4><<<BATCH / 256, 256>>>(pps, pfac, plam);
    apply_kernel<7><<<BATCH * 512 / 4 / 256, 256>>>(pm, pfac, h1h, h1l);
    // layer 2: (B,512) @ (512,256)
    gemm_mma<512><<<dim3(2, BATCH / 128), 256, SMEM_SZ>>>(h1h, h1l, t2h, t2l, pm, 256, 512, pps);
    rowfac_kernel<2><<<BATCH / 256, 256>>>(pps, pfac, plam);
    apply_kernel<6><<<BATCH * 256 / 4 / 256, 256>>>(pm, pfac, h2h, h2l);
    // layer 3: (B,256) @ (256,128)
    gemm_mma<256><<<dim3(1, BATCH / 128), 256, SMEM_SZ>>>(h2h, h2l, t3h, t3l, pm, 128, 768, pps);
    rowfac_kernel<1><<<BATCH / 256, 256>>>(pps, pfac, plam);
    apply_kernel<5><<<BATCH * 128 / 4 / 256, 256>>>(pm, pfac, h3h, h3l);
    // layer 4
    final_kernel<<<warpBlocks, 256>>>(h3h, h3l, z4, out);
}

// round 9
// speedup vs baseline: 2.5347x; 1.0270x over previous
#include <cuda_runtime.h>
#include <cuda_bf16.h>
#include <math.h>
#include <stdint.h>

#define CC 2.3026f
#define BATCH 65536

// ---------------- static device scratch ----------------
__device__ __align__(256) __nv_bfloat16 g_xhi[(size_t)BATCH * 768];
__device__ __align__(256) __nv_bfloat16 g_xlo[(size_t)BATCH * 768];
__device__ __align__(256) __nv_bfloat16 g_hhi[(size_t)BATCH * 512];
__device__ __align__(256) __nv_bfloat16 g_hlo[(size_t)BATCH * 512];
__device__ __align__(256) __nv_bfloat16 g_h2hi[(size_t)BATCH * 256];
__device__ __align__(256) __nv_bfloat16 g_h2lo[(size_t)BATCH * 256];
__device__ __align__(256) __nv_bfloat16 g_h3hi[(size_t)BATCH * 128];
__device__ __align__(256) __nv_bfloat16 g_h3lo[(size_t)BATCH * 128];
__device__ float g_lam[BATCH];
__device__ float g_fac[BATCH];
__device__ float2 g_psum[(size_t)BATCH * 4];     // per (row, n-tile) partial sums
__device__ float g_zn2[897], g_czn[897], g_shv[897];
// transposed split weights [N, K] row-major
__device__ __align__(256) __nv_bfloat16 g_zt1h[512 * 768], g_zt1l[512 * 768];
__device__ __align__(256) __nv_bfloat16 g_zt2h[256 * 512], g_zt2l[256 * 512];
__device__ __align__(256) __nv_bfloat16 g_zt3h[128 * 256], g_zt3l[128 * 256];

// ---------------- PTX helpers ----------------
__device__ __forceinline__ uint32_t smem_u32(const void* p) {
    uint32_t a;
    asm("{ .reg .u64 t; cvta.to.shared.u64 t, %1; cvt.u32.u64 %0, t; }" : "=r"(a) : "l"(p));
    return a;
}
__device__ __forceinline__ void mma16816(float* d, const uint32_t* a, const uint32_t* b) {
    asm volatile(
        "mma.sync.aligned.m16n8k16.row.col.f32.bf16.bf16.f32 "
        "{%0,%1,%2,%3}, {%4,%5,%6,%7}, {%8,%9}, {%0,%1,%2,%3};"
        : "+f"(d[0]), "+f"(d[1]), "+f"(d[2]), "+f"(d[3])
        : "r"(a[0]), "r"(a[1]), "r"(a[2]), "r"(a[3]), "r"(b[0]), "r"(b[1]));
}
__device__ __forceinline__ void ldm_x4(uint32_t* r, uint32_t saddr) {
    asm volatile("ldmatrix.sync.aligned.m8n8.x4.shared.b16 {%0,%1,%2,%3}, [%4];"
        : "=r"(r[0]), "=r"(r[1]), "=r"(r[2]), "=r"(r[3]) : "r"(saddr));
}
#define CP16(sa, gp) asm volatile("cp.async.cg.shared.global [%0], [%1], 16;" :: "r"(sa), "l"(gp))
#define CP_COMMIT()  asm volatile("cp.async.commit_group;" ::: "memory")

// w = sinh(zn2 * asinh(u)) / cs,  u = a1*m*czn - a2*shv   (a1 includes fac_prev)
__device__ __forceinline__ float wcalc(float mm, float a1, float a2,
                                       float czn, float shv, float zn2, float invcs)
{
    float u = fmaf(a1 * mm, czn, -(a2 * shv));
    float t = __logf(u + sqrtf(fmaf(u, u, 1.f)));
    float p = __expf(zn2 * t);
    return (p - __fdividef(1.f, p)) * (0.5f * invcs);
}

// ---------------- prep: warp per column ----------------
__global__ void prep_kernel(const float* __restrict__ z, const float* __restrict__ r,
                            int fi, int fo, int off)
{
    int gid = blockIdx.x * blockDim.x + threadIdx.x;
    int k = gid >> 5, lane = gid & 31;
    if (k >= fo) return;
    float s = 0.f;
    for (int i = lane; i < fi; i += 32) {
        float v = z[(long long)i * fo + k];
        s = fmaf(v, v, s);
    }
#pragma unroll
    for (int o = 16; o; o >>= 1) s += __shfl_xor_sync(0xffffffffu, s, o);
    if (lane == 0) {
        float zn = fmaxf(sqrtf(s), 1e-15f);
        float t = 2.f * sqrtf(CC) * r[k];
        float e = __expf(t);
        float ei = __fdividef(1.f, e);
        g_zn2[off + k] = 2.f * zn;
        g_czn[off + k] = 0.5f * (e + ei) / zn;
        g_shv[off + k] = 0.5f * (e - ei);
    }
}

__global__ void tsplit_kernel(const float* __restrict__ z,
                              __nv_bfloat16* __restrict__ th, __nv_bfloat16* __restrict__ tl,
                              int fi, int fo)
{
    int idx = blockIdx.x * blockDim.x + threadIdx.x;
    if (idx >= fi * fo) return;
    int n = idx / fi, k = idx - n * fi;
    float v = z[(long long)k * fo + n];
    __nv_bfloat16 h = __float2bfloat16(v);
    th[idx] = h;
    tl[idx] = __float2bfloat16(v - __bfloat162float(h));
}

// lam0 + fac=1 + split x into bf16 hi/lo. warp per row, fi=768.
__global__ void lam0_kernel(const float* __restrict__ x)
{
    int gid = blockIdx.x * blockDim.x + threadIdx.x;
    int row = gid >> 5, lane = gid & 31;
    const float4* xr = (const float4*)(x + (long long)row * 768);
    float s = 0.f;
#pragma unroll
    for (int p = 0; p < 6; p++) {
        int e4 = lane + 32 * p;
        float4 v = xr[e4];
        s += v.x * v.x + v.y * v.y + v.z * v.z + v.w * v.w;
        long long b = (long long)row * 768 + e4 * 4;
        float vv[4] = {v.x, v.y, v.z, v.w};
#pragma unroll
        for (int q = 0; q < 4; q++) {
            __nv_bfloat16 h = __float2bfloat16(vv[q]);
            g_xhi[b + q] = h;
            g_xlo[b + q] = __float2bfloat16(vv[q] - __bfloat162float(h));
        }
    }
#pragma unroll
    for (int o = 16; o; o >>= 1) s += __shfl_xor_sync(0xffffffffu, s, o);
    if (lane == 0) {
        g_lam[row] = __fdividef(2.f, 1.f - CC * s);
        g_fac[row] = 1.f;
    }
}

// ---------------- pipelined split-bf16 GEMM + fused w/relu/split epilogue ----------------
// Output: relu(w) split to bf16 hi/lo; per-(row,ntile) partial sums (w^2, relu(w)^2).
#define STAGE_SZ 40960
template <int KDIM>
__global__ __launch_bounds__(256, 2)
void gemm_mma(const __nv_bfloat16* __restrict__ Ahi, const __nv_bfloat16* __restrict__ Alo,
              const __nv_bfloat16* __restrict__ Bth, const __nv_bfloat16* __restrict__ Btl,
              __nv_bfloat16* __restrict__ Whh, __nv_bfloat16* __restrict__ Whl,
              int Nfull, int offTab, float2* __restrict__ psum,
              const float* __restrict__ facPrev)
{
    extern __shared__ char smem[];
    const uint32_t sbase = smem_u32(smem);
    constexpr int NB = KDIM / 32;

    int tid = threadIdx.x, wid = tid >> 5, lane = tid & 31;
    int warp_m = wid >> 1, warp_n = wid & 1;
    int gID = lane >> 2, tig = lane & 3;
    long long bm = (long long)blockIdx.y * 128;
    int bn = blockIdx.x * 128;
    int ntiles = gridDim.x;

    int c_row0 = tid >> 2, c_seg0 = tid & 3;
    int c_row1 = (tid + 256) >> 2, c_seg1 = (tid + 256) & 3;
    uint32_t so0 = (uint32_t)(c_row0 * 80 + c_seg0 * 16);
    uint32_t so1 = (uint32_t)(c_row1 * 80 + c_seg1 * 16);

    uint32_t a_off0 = (uint32_t)((warp_m * 32 + (lane & 15)) * 80 + ((lane >> 4) * 8) * 2);
    uint32_t a_off1 = a_off0 + 16 * 80;
    uint32_t b_off = (uint32_t)((warp_n * 64 + (lane & 7) + ((lane >> 3) & 2) * 4) * 80
                                + (((lane >> 3) & 1) * 8) * 2);

    float acc[2][8][4];
#pragma unroll
    for (int m = 0; m < 2; m++)
#pragma unroll
        for (int n = 0; n < 8; n++)
#pragma unroll
            for (int q = 0; q < 4; q++) acc[m][n][q] = 0.f;

    auto issue = [&](int stage, int k0) {
        uint32_t st = sbase + stage * STAGE_SZ;
        long long ga0 = (bm + c_row0) * KDIM + k0 + c_seg0 * 8;
        long long gb0 = (long long)(bn + c_row0) * KDIM + k0 + c_seg0 * 8;
        long long ga1 = (bm + c_row1) * KDIM + k0 + c_seg1 * 8;
        long long gb1 = (long long)(bn + c_row1) * KDIM + k0 + c_seg1 * 8;
        CP16(st + so0,          Ahi + ga0);
        CP16(st + 10240 + so0,  Alo + ga0);
        CP16(st + 20480 + so0,  Bth + gb0);
        CP16(st + 30720 + so0,  Btl + gb0);
        CP16(st + so1,          Ahi + ga1);
        CP16(st + 10240 + so1,  Alo + ga1);
        CP16(st + 20480 + so1,  Bth + gb1);
        CP16(st + 30720 + so1,  Btl + gb1);
    };

    issue(0, 0);
    CP_COMMIT();

    for (int i = 0; i < NB; i++) {
        if (i + 1 < NB) {
            issue((i + 1) & 1, (i + 1) * 32);
            CP_COMMIT();
            asm volatile("cp.async.wait_group 1;" ::: "memory");
        } else {
            asm volatile("cp.async.wait_group 0;" ::: "memory");
        }
        __syncthreads();

        uint32_t st = sbase + (i & 1) * STAGE_SZ;
        uint32_t sA = st, sAl = st + 10240, sB = st + 20480, sBl = st + 30720;

#pragma unroll
        for (int ks = 0; ks < 32; ks += 16) {
            uint32_t ah[2][4], al[2][4];
            ldm_x4(ah[0], sA  + a_off0 + ks * 2);
            ldm_x4(ah[1], sA  + a_off1 + ks * 2);
            ldm_x4(al[0], sAl + a_off0 + ks * 2);
            ldm_x4(al[1], sAl + a_off1 + ks * 2);
#pragma unroll
            for (int n2 = 0; n2 < 4; n2++) {
                uint32_t bh[4], bl[4];
                uint32_t boff = b_off + (uint32_t)(n2 * 16 * 80) + ks * 2;
                ldm_x4(bh, sB + boff);
                ldm_x4(bl, sBl + boff);
#pragma unroll
                for (int g = 0; g < 2; g++) {
#pragma unroll
                    for (int m = 0; m < 2; m++) {
                        mma16816(acc[m][n2 * 2 + g], ah[m], &bh[g * 2]);
                        mma16816(acc[m][n2 * 2 + g], ah[m], &bl[g * 2]);
                        mma16816(acc[m][n2 * 2 + g], al[m], &bh[g * 2]);
                    }
                }
            }
        }
        __syncthreads();
    }

    // ---- fused epilogue: m -> w -> relu -> bf16 hi/lo, plus per-row partial sums ----
    const float cs = sqrtf(CC);
    const float invcs = 1.f / cs;
    float s4[4] = {0.f, 0.f, 0.f, 0.f}, sp4[4] = {0.f, 0.f, 0.f, 0.f};
#pragma unroll
    for (int m = 0; m < 2; m++) {
        long long rA = bm + warp_m * 32 + m * 16 + gID;
        float lamA = g_lam[rA], lamB = g_lam[rA + 8];
        float fA = facPrev[rA], fB = facPrev[rA + 8];
        float a1A = cs * lamA * fA, a2A = lamA - 1.f;
        float a1B = cs * lamB * fB, a2B = lamB - 1.f;
#pragma unroll
        for (int n = 0; n < 8; n++) {
            int k = offTab + bn + warp_n * 64 + n * 8 + tig * 2;
            float czn0 = g_czn[k], czn1 = g_czn[k + 1];
            float shv0 = g_shv[k], shv1 = g_shv[k + 1];
            float zn0  = g_zn2[k], zn1  = g_zn2[k + 1];
            float w0 = wcalc(acc[m][n][0], a1A, a2A, czn0, shv0, zn0, invcs);
            float w1 = wcalc(acc[m][n][1], a1A, a2A, czn1, shv1, zn1, invcs);
            float w2 = wcalc(acc[m][n][2], a1B, a2B, czn0, shv0, zn0, invcs);
            float w3 = wcalc(acc[m][n][3], a1B, a2B, czn1, shv1, zn1, invcs);
            s4[m * 2]     += fmaf(w0, w0, w1 * w1);
            s4[m * 2 + 1] += fmaf(w2, w2, w3 * w3);
            float p0 = fmaxf(w0, 0.f), p1 = fmaxf(w1, 0.f);
            float p2 = fmaxf(w2, 0.f), p3 = fmaxf(w3, 0.f);
            sp4[m * 2]     += fmaf(p0, p0, p1 * p1);
            sp4[m * 2 + 1] += fmaf(p2, p2, p3 * p3);
            acc[m][n][0] = p0; acc[m][n][1] = p1; acc[m][n][2] = p2; acc[m][n][3] = p3;
        }
    }
#pragma unroll
    for (int q = 0; q < 4; q++) {
        s4[q]  += __shfl_xor_sync(0xffffffffu, s4[q], 1);
        s4[q]  += __shfl_xor_sync(0xffffffffu, s4[q], 2);
        sp4[q] += __shfl_xor_sync(0xffffffffu, sp4[q], 1);
        sp4[q] += __shfl_xor_sync(0xffffffffu, sp4[q], 2);
    }
    float2* sred = (float2*)smem;
    if (tig == 0) {
        int rl = warp_m * 32 + gID;
        sred[(rl)      * 2 + warp_n] = make_float2(s4[0], sp4[0]);
        sred[(rl + 8)  * 2 + warp_n] = make_float2(s4[1], sp4[1]);
        sred[(rl + 16) * 2 + warp_n] = make_float2(s4[2], sp4[2]);
        sred[(rl + 24) * 2 + warp_n] = make_float2(s4[3], sp4[3]);
    }
    __syncthreads();
    if (tid < 128) {
        float2 a = sred[tid * 2], b = sred[tid * 2 + 1];
        psum[(bm + tid) * ntiles + blockIdx.x] = make_float2(a.x + b.x, a.y + b.y);
    }

    // store relu(w) as bf16 hi/lo
#pragma unroll
    for (int m = 0; m < 2; m++) {
#pragma unroll
        for (int n = 0; n < 8; n++) {
            long long r = bm + warp_m * 32 + m * 16 + gID;
            int c = bn + warp_n * 64 + n * 8 + tig * 2;
            float p0 = acc[m][n][0], p1 = acc[m][n][1];
            float p2 = acc[m][n][2], p3 = acc[m][n][3];
            __nv_bfloat16 h0 = __float2bfloat16(p0), h1 = __float2bfloat16(p1);
            __nv_bfloat16 h2 = __float2bfloat16(p2), h3 = __float2bfloat16(p3);
            __nv_bfloat162 hi0; hi0.x = h0; hi0.y = h1;
            __nv_bfloat162 hi1; hi1.x = h2; hi1.y = h3;
            __nv_bfloat162 lo0, lo1;
            lo0.x = __float2bfloat16(p0 - __bfloat162float(h0));
            lo0.y = __float2bfloat16(p1 - __bfloat162float(h1));
            lo1.x = __float2bfloat16(p2 - __bfloat162float(h2));
            lo1.y = __float2bfloat16(p3 - __bfloat162float(h3));
            *(__nv_bfloat162*)(Whh + r * Nfull + c)       = hi0;
            *(__nv_bfloat162*)(Whh + (r + 8) * Nfull + c) = hi1;
            *(__nv_bfloat162*)(Whl + r * Nfull + c)       = lo0;
            *(__nv_bfloat162*)(Whl + (r + 8) * Nfull + c) = lo1;
        }
    }
}

// ---------------- per-row factor kernel ----------------
template <int NT>
__global__ void rowfac_kernel(const float2* __restrict__ ps,
                              float* __restrict__ fac, float* __restrict__ lam)
{
    int row = blockIdx.x * blockDim.x + threadIdx.x;
    float s = 0.f, sp = 0.f;
#pragma unroll
    for (int t = 0; t < NT; t++) {
        float2 v = ps[(long long)row * NT + t];
        s += v.x; sp += v.y;
    }
    const float cs = sqrtf(CC);
    float inv = __fdividef(1.f, 1.f + sqrtf(fmaf(CC, s, 1.f)));
    float n  = fmaxf(sqrtf(s) * inv, 1e-15f);
    float cn = fminf(cs * n, 1.f - 1e-7f);
    float a  = __fdividef(0.5f * __logf(__fdividef(1.f + cn, 1.f - cn)), cs * n);
    float vn = fmaxf(a * inv * sqrtf(sp), 1e-15f);
    float e  = __expf(2.f * cs * vn);
    float th = __fdividef(e - 1.f, e + 1.f);
    float fc = __fdividef(th, cs * vn) * a;
    fac[row] = fc * inv;
    lam[row] = 0.5f * (e + 2.f + __fdividef(1.f, e));
}

// ---------------- final layer fo=1: dot(fac*wp, z4) + ball map ----------------
__global__ void final_kernel(const __nv_bfloat16* __restrict__ hh, const __nv_bfloat16* __restrict__ hl,
                             const float* __restrict__ z4, const float* __restrict__ fac,
                             float* __restrict__ out)
{
    int gid = blockIdx.x * blockDim.x + threadIdx.x;
    int row = gid >> 5, lane = gid & 31;
    float s = 0.f;
#pragma unroll
    for (int p = 0; p < 4; p++) {
        int k = lane + 32 * p;
        long long idx = (long long)row * 128 + k;
        float h = __bfloat162float(hh[idx]) + __bfloat162float(hl[idx]);
        s = fmaf(h, z4[k], s);
    }
#pragma unroll
    for (int o = 16; o; o >>= 1) s += __shfl_xor_sync(0xffffffffu, s, o);
    if (lane == 0) {
        const float cs = sqrtf(CC);
        float lam = g_lam[row];
        float se = s * fac[row];
        float u = fmaf(cs * lam * se, g_czn[896], -((lam - 1.f) * g_shv[896]));
        float t = __logf(u + sqrtf(fmaf(u, u, 1.f)));
        float p = __expf(g_zn2[896] * t);
        float w = (p - __fdividef(1.f, p)) * (0.5f / cs);
        out[row] = __fdividef(w, 1.f + sqrtf(fmaf(CC, w * w, 1.f)));
    }
}

// ---------------- launch ----------------
extern "C" void kernel_launch(void* const* d_in, const int* in_sizes, int n_in,
                              void* d_out, int out_size)
{
    const float* x  = (const float*)d_in[0];
    const float* z1 = (const float*)d_in[1];
    const float* b1 = (const float*)d_in[2];
    const float* z2 = (const float*)d_in[3];
    const float* b2 = (const float*)d_in[4];
    const float* z3 = (const float*)d_in[5];
    const float* b3 = (const float*)d_in[6];
    const float* z4 = (const float*)d_in[7];
    const float* b4 = (const float*)d_in[8];
    float* out = (float*)d_out;

    float* pfac; cudaGetSymbolAddress((void**)&pfac, g_fac);
    float* plam; cudaGetSymbolAddress((void**)&plam, g_lam);
    float2* pps; cudaGetSymbolAddress((void**)&pps, g_psum);
    __nv_bfloat16 *xh, *xl, *h1h, *h1l, *h2h, *h2l, *h3h, *h3l;
    __nv_bfloat16 *t1h, *t1l, *t2h, *t2l, *t3h, *t3l;
    cudaGetSymbolAddress((void**)&xh, g_xhi);   cudaGetSymbolAddress((void**)&xl, g_xlo);
    cudaGetSymbolAddress((void**)&h1h, g_hhi);  cudaGetSymbolAddress((void**)&h1l, g_hlo);
    cudaGetSymbolAddress((void**)&h2h, g_h2hi); cudaGetSymbolAddress((void**)&h2l, g_h2lo);
    cudaGetSymbolAddress((void**)&h3h, g_h3hi); cudaGetSymbolAddress((void**)&h3l, g_h3lo);
    cudaGetSymbolAddress((void**)&t1h, g_zt1h); cudaGetSymbolAddress((void**)&t1l, g_zt1l);
    cudaGetSymbolAddress((void**)&t2h, g_zt2h); cudaGetSymbolAddress((void**)&t2l, g_zt2l);
    cudaGetSymbolAddress((void**)&t3h, g_zt3h); cudaGetSymbolAddress((void**)&t3l, g_zt3l);

    const int SMEM_SZ = 2 * STAGE_SZ;  // 81920
    cudaFuncSetAttribute(gemm_mma<768>, cudaFuncAttributeMaxDynamicSharedMemorySize, SMEM_SZ);
    cudaFuncSetAttribute(gemm_mma<512>, cudaFuncAttributeMaxDynamicSharedMemorySize, SMEM_SZ);
    cudaFuncSetAttribute(gemm_mma<256>, cudaFuncAttributeMaxDynamicSharedMemorySize, SMEM_SZ);

    const int warpBlocks = BATCH * 32 / 256;

    lam0_kernel<<<warpBlocks, 256>>>(x);
    prep_kernel<<<(512 * 32 + 255) / 256, 256>>>(z1, b1, 768, 512, 0);
    prep_kernel<<<(256 * 32 + 255) / 256, 256>>>(z2, b2, 512, 256, 512);
    prep_kernel<<<(128 * 32 + 255) / 256, 256>>>(z3, b3, 256, 128, 768);
    prep_kernel<<<1, 32>>>(z4, b4, 128, 1, 896);
    tsplit_kernel<<<(512 * 768 + 255) / 256, 256>>>(z1, t1h, t1l, 768, 512);
    tsplit_kernel<<<(256 * 512 + 255) / 256, 256>>>(z2, t2h, t2l, 512, 256);
    tsplit_kernel<<<(128 * 256 + 255) / 256, 256>>>(z3, t3h, t3l, 256, 128);

    // layer 1: (B,768) @ (768,512) -> relu(w) hi/lo
    gemm_mma<768><<<dim3(4, BATCH / 128), 256, SMEM_SZ>>>(xh, xl, t1h, t1l, h1h, h1l, 512, 0, pps, pfac);
    rowfac_kernel<4><<<BATCH / 256, 256>>>(pps, pfac, plam);
    // layer 2: (B,512) @ (512,256)
    gemm_mma<512><<<dim3(2, BATCH / 128), 256, SMEM_SZ>>>(h1h, h1l, t2h, t2l, h2h, h2l, 256, 512, pps, pfac);
    rowfac_kernel<2><<<BATCH / 256, 256>>>(pps, pfac, plam);
    // layer 3: (B,256) @ (256,128)
    gemm_mma<256><<<dim3(1, BATCH / 128), 256, SMEM_SZ>>>(h2h, h2l, t3h, t3l, h3h, h3l, 128, 768, pps, pfac);
    rowfac_kernel<1><<<BATCH / 256, 256>>>(pps, pfac, plam);
    // layer 4
    final_kernel<<<warpBlocks, 256>>>(h3h, h3l, z4, pfac, out);
}

// round 10
// speedup vs baseline: 3.2197x; 1.2703x over previous
#include <cuda_runtime.h>
#include <cuda_fp16.h>
#include <math.h>
#include <stdint.h>

#define CC 2.3026f
#define BATCH 65536
#define ASCALE 64.0f

// ---------------- static device scratch ----------------
__device__ __align__(256) __half g_xhi[(size_t)BATCH * 768];
__device__ __align__(256) __half g_xlo[(size_t)BATCH * 768];
__device__ __align__(256) __half g_hhi[(size_t)BATCH * 512];
__device__ __align__(256) __half g_hlo[(size_t)BATCH * 512];
__device__ __align__(256) __half g_h2hi[(size_t)BATCH * 256];
__device__ __align__(256) __half g_h2lo[(size_t)BATCH * 256];
__device__ __align__(256) __half g_h3hi[(size_t)BATCH * 128];
__device__ __align__(256) __half g_h3lo[(size_t)BATCH * 128];
__device__ float g_lam[BATCH];
__device__ float g_fac[BATCH];
__device__ float2 g_psum[(size_t)BATCH * 4];
__device__ float g_zn2[897], g_czn[897], g_shv[897];
// transposed fp16 weights [N, K] row-major (single precision level)
__device__ __align__(256) __half g_zt1[512 * 768];
__device__ __align__(256) __half g_zt2[256 * 512];
__device__ __align__(256) __half g_zt3[128 * 256];

// ---------------- PTX helpers ----------------
__device__ __forceinline__ uint32_t smem_u32(const void* p) {
    uint32_t a;
    asm("{ .reg .u64 t; cvta.to.shared.u64 t, %1; cvt.u32.u64 %0, t; }" : "=r"(a) : "l"(p));
    return a;
}
__device__ __forceinline__ void mma16816(float* d, const uint32_t* a, const uint32_t* b) {
    asm volatile(
        "mma.sync.aligned.m16n8k16.row.col.f32.f16.f16.f32 "
        "{%0,%1,%2,%3}, {%4,%5,%6,%7}, {%8,%9}, {%0,%1,%2,%3};"
        : "+f"(d[0]), "+f"(d[1]), "+f"(d[2]), "+f"(d[3])
        : "r"(a[0]), "r"(a[1]), "r"(a[2]), "r"(a[3]), "r"(b[0]), "r"(b[1]));
}
__device__ __forceinline__ void ldm_x4(uint32_t* r, uint32_t saddr) {
    asm volatile("ldmatrix.sync.aligned.m8n8.x4.shared.b16 {%0,%1,%2,%3}, [%4];"
        : "=r"(r[0]), "=r"(r[1]), "=r"(r[2]), "=r"(r[3]) : "r"(saddr));
}
#define CP16(sa, gp) asm volatile("cp.async.cg.shared.global [%0], [%1], 16;" :: "r"(sa), "l"(gp))
#define CP_COMMIT()  asm volatile("cp.async.commit_group;" ::: "memory")

// w = sinh(zn2 * asinh(u)) / cs,  u = a1*m*czn - a2*shv  (a1 includes fac_prev incl. 1/ASCALE)
__device__ __forceinline__ float wcalc(float mm, float a1, float a2,
                                       float czn, float shv, float zn2, float invcs)
{
    float u = fmaf(a1 * mm, czn, -(a2 * shv));
    float t = __logf(u + sqrtf(fmaf(u, u, 1.f)));
    float p = __expf(zn2 * t);
    return (p - __fdividef(1.f, p)) * (0.5f * invcs);
}

// ---------------- prep: warp per column ----------------
__global__ void prep_kernel(const float* __restrict__ z, const float* __restrict__ r,
                            int fi, int fo, int off)
{
    int gid = blockIdx.x * blockDim.x + threadIdx.x;
    int k = gid >> 5, lane = gid & 31;
    if (k >= fo) return;
    float s = 0.f;
    for (int i = lane; i < fi; i += 32) {
        float v = z[(long long)i * fo + k];
        s = fmaf(v, v, s);
    }
#pragma unroll
    for (int o = 16; o; o >>= 1) s += __shfl_xor_sync(0xffffffffu, s, o);
    if (lane == 0) {
        float zn = fmaxf(sqrtf(s), 1e-15f);
        float t = 2.f * sqrtf(CC) * r[k];
        float e = __expf(t);
        float ei = __fdividef(1.f, e);
        g_zn2[off + k] = 2.f * zn;
        g_czn[off + k] = 0.5f * (e + ei) / zn;
        g_shv[off + k] = 0.5f * (e - ei);
    }
}

// transpose weights -> fp16 single
__global__ void tsplit_kernel(const float* __restrict__ z, __half* __restrict__ th,
                              int fi, int fo)
{
    int idx = blockIdx.x * blockDim.x + threadIdx.x;
    if (idx >= fi * fo) return;
    int n = idx / fi, k = idx - n * fi;
    th[idx] = __float2half(z[(long long)k * fo + n]);
}

// lam0 + fac=1/ASCALE + split ASCALE*x into fp16 hi/lo. warp per row, fi=768.
__global__ void lam0_kernel(const float* __restrict__ x)
{
    int gid = blockIdx.x * blockDim.x + threadIdx.x;
    int row = gid >> 5, lane = gid & 31;
    const float4* xr = (const float4*)(x + (long long)row * 768);
    float s = 0.f;
#pragma unroll
    for (int p = 0; p < 6; p++) {
        int e4 = lane + 32 * p;
        float4 v = xr[e4];
        s += v.x * v.x + v.y * v.y + v.z * v.z + v.w * v.w;
        long long b = (long long)row * 768 + e4 * 4;
        float vv[4] = {v.x, v.y, v.z, v.w};
#pragma unroll
        for (int q = 0; q < 4; q++) {
            float xs = ASCALE * vv[q];
            __half h = __float2half(xs);
            g_xhi[b + q] = h;
            g_xlo[b + q] = __float2half(xs - __half2float(h));
        }
    }
#pragma unroll
    for (int o = 16; o; o >>= 1) s += __shfl_xor_sync(0xffffffffu, s, o);
    if (lane == 0) {
        g_lam[row] = __fdividef(2.f, 1.f - CC * s);
        g_fac[row] = 1.f / ASCALE;
    }
}

// ---------------- 3-stage pipelined 2-product fp16 GEMM + fused epilogue ----------------
// C = (Ahi+Alo)[128xK] @ Bt[128xK]^T; outputs ASCALE*relu(w) fp16 hi/lo + row psums.
#define STAGE_SZ 30720
template <int KDIM>
__global__ __launch_bounds__(256, 2)
void gemm_mma(const __half* __restrict__ Ahi, const __half* __restrict__ Alo,
              const __half* __restrict__ Bt,
              __half* __restrict__ Whh, __half* __restrict__ Whl,
              int Nfull, int offTab, float2* __restrict__ psum,
              const float* __restrict__ facPrev)
{
    extern __shared__ char smem[];
    const uint32_t sbase = smem_u32(smem);
    constexpr int NB = KDIM / 32;

    int tid = threadIdx.x, wid = tid >> 5, lane = tid & 31;
    int warp_m = wid >> 1, warp_n = wid & 1;
    int gID = lane >> 2, tig = lane & 3;
    long long bm = (long long)blockIdx.y * 128;
    int bn = blockIdx.x * 128;
    int ntiles = gridDim.x;

    int c_row0 = tid >> 2, c_seg0 = tid & 3;
    int c_row1 = (tid + 256) >> 2, c_seg1 = (tid + 256) & 3;
    uint32_t so0 = (uint32_t)(c_row0 * 80 + c_seg0 * 16);
    uint32_t so1 = (uint32_t)(c_row1 * 80 + c_seg1 * 16);

    uint32_t a_off0 = (uint32_t)((warp_m * 32 + (lane & 15)) * 80 + ((lane >> 4) * 8) * 2);
    uint32_t a_off1 = a_off0 + 16 * 80;
    uint32_t b_off = (uint32_t)((warp_n * 64 + (lane & 7) + ((lane >> 3) & 2) * 4) * 80
                                + (((lane >> 3) & 1) * 8) * 2);

    float acc[2][8][4];
#pragma unroll
    for (int m = 0; m < 2; m++)
#pragma unroll
        for (int n = 0; n < 8; n++)
#pragma unroll
            for (int q = 0; q < 4; q++) acc[m][n][q] = 0.f;

    auto issue = [&](int i) {
        uint32_t st = sbase + (i % 3) * STAGE_SZ;
        int k0 = i * 32;
        long long ga0 = (bm + c_row0) * KDIM + k0 + c_seg0 * 8;
        long long gb0 = (long long)(bn + c_row0) * KDIM + k0 + c_seg0 * 8;
        long long ga1 = (bm + c_row1) * KDIM + k0 + c_seg1 * 8;
        long long gb1 = (long long)(bn + c_row1) * KDIM + k0 + c_seg1 * 8;
        CP16(st + so0,          Ahi + ga0);
        CP16(st + 10240 + so0,  Alo + ga0);
        CP16(st + 20480 + so0,  Bt + gb0);
        CP16(st + so1,          Ahi + ga1);
        CP16(st + 10240 + so1,  Alo + ga1);
        CP16(st + 20480 + so1,  Bt + gb1);
    };

    issue(0); CP_COMMIT();
    if (NB > 1) { issue(1); CP_COMMIT(); }

    for (int i = 0; i < NB; i++) {
        if (i + 1 < NB) asm volatile("cp.async.wait_group 1;" ::: "memory");
        else            asm volatile("cp.async.wait_group 0;" ::: "memory");
        __syncthreads();
        if (i + 2 < NB) { issue(i + 2); CP_COMMIT(); }

        uint32_t st = sbase + (i % 3) * STAGE_SZ;
        uint32_t sA = st, sAl = st + 10240, sB = st + 20480;

#pragma unroll
        for (int ks = 0; ks < 32; ks += 16) {
            uint32_t ah[2][4], al[2][4];
            ldm_x4(ah[0], sA  + a_off0 + ks * 2);
            ldm_x4(ah[1], sA  + a_off1 + ks * 2);
            ldm_x4(al[0], sAl + a_off0 + ks * 2);
            ldm_x4(al[1], sAl + a_off1 + ks * 2);
#pragma unroll
            for (int n2 = 0; n2 < 4; n2++) {
                uint32_t bh[4];
                ldm_x4(bh, sB + b_off + (uint32_t)(n2 * 16 * 80) + ks * 2);
#pragma unroll
                for (int g = 0; g < 2; g++) {
#pragma unroll
                    for (int m = 0; m < 2; m++) {
                        mma16816(acc[m][n2 * 2 + g], ah[m], &bh[g * 2]);
                        mma16816(acc[m][n2 * 2 + g], al[m], &bh[g * 2]);
                    }
                }
            }
        }
        __syncthreads();
    }

    // ---- fused epilogue: m -> w -> relu -> scaled fp16 hi/lo, plus per-row partial sums ----
    const float cs = sqrtf(CC);
    const float invcs = 1.f / cs;
    float s4[4] = {0.f, 0.f, 0.f, 0.f}, sp4[4] = {0.f, 0.f, 0.f, 0.f};
#pragma unroll
    for (int m = 0; m < 2; m++) {
        long long rA = bm + warp_m * 32 + m * 16 + gID;
        float lamA = g_lam[rA], lamB = g_lam[rA + 8];
        float fA = facPrev[rA], fB = facPrev[rA + 8];
        float a1A = cs * lamA * fA, a2A = lamA - 1.f;
        float a1B = cs * lamB * fB, a2B = lamB - 1.f;
#pragma unroll
        for (int n = 0; n < 8; n++) {
            int k = offTab + bn + warp_n * 64 + n * 8 + tig * 2;
            float czn0 = g_czn[k], czn1 = g_czn[k + 1];
            float shv0 = g_shv[k], shv1 = g_shv[k + 1];
            float zn0  = g_zn2[k], zn1  = g_zn2[k + 1];
            float w0 = wcalc(acc[m][n][0], a1A, a2A, czn0, shv0, zn0, invcs);
            float w1 = wcalc(acc[m][n][1], a1A, a2A, czn1, shv1, zn1, invcs);
            float w2 = wcalc(acc[m][n][2], a1B, a2B, czn0, shv0, zn0, invcs);
            float w3 = wcalc(acc[m][n][3], a1B, a2B, czn1, shv1, zn1, invcs);
            s4[m * 2]     += fmaf(w0, w0, w1 * w1);
            s4[m * 2 + 1] += fmaf(w2, w2, w3 * w3);
            float p0 = fmaxf(w0, 0.f), p1 = fmaxf(w1, 0.f);
            float p2 = fmaxf(w2, 0.f), p3 = fmaxf(w3, 0.f);
            sp4[m * 2]     += fmaf(p0, p0, p1 * p1);
            sp4[m * 2 + 1] += fmaf(p2, p2, p3 * p3);
            acc[m][n][0] = p0; acc[m][n][1] = p1; acc[m][n][2] = p2; acc[m][n][3] = p3;
        }
    }
#pragma unroll
    for (int q = 0; q < 4; q++) {
        s4[q]  += __shfl_xor_sync(0xffffffffu, s4[q], 1);
        s4[q]  += __shfl_xor_sync(0xffffffffu, s4[q], 2);
        sp4[q] += __shfl_xor_sync(0xffffffffu, sp4[q], 1);
        sp4[q] += __shfl_xor_sync(0xffffffffu, sp4[q], 2);
    }
    __syncthreads();  // stage buffers may alias sred
    float2* sred = (float2*)smem;
    if (tig == 0) {
        int rl = warp_m * 32 + gID;
        sred[(rl)      * 2 + warp_n] = make_float2(s4[0], sp4[0]);
        sred[(rl + 8)  * 2 + warp_n] = make_float2(s4[1], sp4[1]);
        sred[(rl + 16) * 2 + warp_n] = make_float2(s4[2], sp4[2]);
        sred[(rl + 24) * 2 + warp_n] = make_float2(s4[3], sp4[3]);
    }
    __syncthreads();
    if (tid < 128) {
        float2 a = sred[tid * 2], b = sred[tid * 2 + 1];
        psum[(bm + tid) * ntiles + blockIdx.x] = make_float2(a.x + b.x, a.y + b.y);
    }

    // store ASCALE*relu(w) as fp16 hi/lo
#pragma unroll
    for (int m = 0; m < 2; m++) {
#pragma unroll
        for (int n = 0; n < 8; n++) {
            long long r = bm + warp_m * 32 + m * 16 + gID;
            int c = bn + warp_n * 64 + n * 8 + tig * 2;
            float p0 = ASCALE * acc[m][n][0], p1 = ASCALE * acc[m][n][1];
            float p2 = ASCALE * acc[m][n][2], p3 = ASCALE * acc[m][n][3];
            __half h0 = __float2half(p0), h1 = __float2half(p1);
            __half h2 = __float2half(p2), h3 = __float2half(p3);
            __half2 hi0; hi0.x = h0; hi0.y = h1;
            __half2 hi1; hi1.x = h2; hi1.y = h3;
            __half2 lo0, lo1;
            lo0.x = __float2half(p0 - __half2float(h0));
            lo0.y = __float2half(p1 - __half2float(h1));
            lo1.x = __float2half(p2 - __half2float(h2));
            lo1.y = __float2half(p3 - __half2float(h3));
            *(__half2*)(Whh + r * Nfull + c)       = hi0;
            *(__half2*)(Whh + (r + 8) * Nfull + c) = hi1;
            *(__half2*)(Whl + r * Nfull + c)       = lo0;
            *(__half2*)(Whl + (r + 8) * Nfull + c) = lo1;
        }
    }
}

// ---------------- per-row factor kernel ----------------
template <int NT>
__global__ void rowfac_kernel(const float2* __restrict__ ps,
                              float* __restrict__ fac, float* __restrict__ lam)
{
    int row = blockIdx.x * blockDim.x + threadIdx.x;
    float s = 0.f, sp = 0.f;
#pragma unroll
    for (int t = 0; t < NT; t++) {
        float2 v = ps[(long long)row * NT + t];
        s += v.x; sp += v.y;
    }
    const float cs = sqrtf(CC);
    float inv = __fdividef(1.f, 1.f + sqrtf(fmaf(CC, s, 1.f)));
    float n  = fmaxf(sqrtf(s) * inv, 1e-15f);
    float cn = fminf(cs * n, 1.f - 1e-7f);
    float a  = __fdividef(0.5f * __logf(__fdividef(1.f + cn, 1.f - cn)), cs * n);
    float vn = fmaxf(a * inv * sqrtf(sp), 1e-15f);
    float e  = __expf(2.f * cs * vn);
    float th = __fdividef(e - 1.f, e + 1.f);
    float fc = __fdividef(th, cs * vn) * a;
    fac[row] = fc * inv * (1.f / ASCALE);   // next GEMM's A is stored pre-scaled by ASCALE
    lam[row] = 0.5f * (e + 2.f + __fdividef(1.f, e));
}

// ---------------- final layer fo=1 ----------------
__global__ void final_kernel(const __half* __restrict__ hh, const __half* __restrict__ hl,
                             const float* __restrict__ z4, const float* __restrict__ fac,
                             float* __restrict__ out)
{
    int gid = blockIdx.x * blockDim.x + threadIdx.x;
    int row = gid >> 5, lane = gid & 31;
    float s = 0.f;
#pragma unroll
    for (int p = 0; p < 4; p++) {
        int k = lane + 32 * p;
        long long idx = (long long)row * 128 + k;
        float h = __half2float(hh[idx]) + __half2float(hl[idx]);
        s = fmaf(h, z4[k], s);
    }
#pragma unroll
    for (int o = 16; o; o >>= 1) s += __shfl_xor_sync(0xffffffffu, s, o);
    if (lane == 0) {
        const float cs = sqrtf(CC);
        float lam = g_lam[row];
        float se = s * fac[row];   // fac includes 1/ASCALE, h stored pre-scaled
        float u = fmaf(cs * lam * se, g_czn[896], -((lam - 1.f) * g_shv[896]));
        float t = __logf(u + sqrtf(fmaf(u, u, 1.f)));
        float p = __expf(g_zn2[896] * t);
        float w = (p - __fdividef(1.f, p)) * (0.5f / cs);
        out[row] = __fdividef(w, 1.f + sqrtf(fmaf(CC, w * w, 1.f)));
    }
}

// ---------------- launch ----------------
extern "C" void kernel_launch(void* const* d_in, const int* in_sizes, int n_in,
                              void* d_out, int out_size)
{
    const float* x  = (const float*)d_in[0];
    const float* z1 = (const float*)d_in[1];
    const float* b1 = (const float*)d_in[2];
    const float* z2 = (const float*)d_in[3];
    const float* b2 = (const float*)d_in[4];
    const float* z3 = (const float*)d_in[5];
    const float* b3 = (const float*)d_in[6];
    const float* z4 = (const float*)d_in[7];
    const float* b4 = (const float*)d_in[8];
    float* out = (float*)d_out;

    float* pfac; cudaGetSymbolAddress((void**)&pfac, g_fac);
    float* plam; cudaGetSymbolAddress((void**)&plam, g_lam);
    float2* pps; cudaGetSymbolAddress((void**)&pps, g_psum);
    __half *xh, *xl, *h1h, *h1l, *h2h, *h2l, *h3h, *h3l, *t1, *t2, *t3;
    cudaGetSymbolAddress((void**)&xh, g_xhi);   cudaGetSymbolAddress((void**)&xl, g_xlo);
    cudaGetSymbolAddress((void**)&h1h, g_hhi);  cudaGetSymbolAddress((void**)&h1l, g_hlo);
    cudaGetSymbolAddress((void**)&h2h, g_h2hi); cudaGetSymbolAddress((void**)&h2l, g_h2lo);
    cudaGetSymbolAddress((void**)&h3h, g_h3hi); cudaGetSymbolAddress((void**)&h3l, g_h3lo);
    cudaGetSymbolAddress((void**)&t1, g_zt1);
    cudaGetSymbolAddress((void**)&t2, g_zt2);
    cudaGetSymbolAddress((void**)&t3, g_zt3);

    const int SMEM_SZ = 3 * STAGE_SZ;  // 92160
    cudaFuncSetAttribute(gemm_mma<768>, cudaFuncAttributeMaxDynamicSharedMemorySize, SMEM_SZ);
    cudaFuncSetAttribute(gemm_mma<512>, cudaFuncAttributeMaxDynamicSharedMemorySize, SMEM_SZ);
    cudaFuncSetAttribute(gemm_mma<256>, cudaFuncAttributeMaxDynamicSharedMemorySize, SMEM_SZ);

    const int warpBlocks = BATCH * 32 / 256;

    lam0_kernel<<<warpBlocks, 256>>>(x);
    prep_kernel<<<(512 * 32 + 255) / 256, 256>>>(z1, b1, 768, 512, 0);
    prep_kernel<<<(256 * 32 + 255) / 256, 256>>>(z2, b2, 512, 256, 512);
    prep_kernel<<<(128 * 32 + 255) / 256, 256>>>(z3, b3, 256, 128, 768);
    prep_kernel<<<1, 32>>>(z4, b4, 128, 1, 896);
    tsplit_kernel<<<(512 * 768 + 255) / 256, 256>>>(z1, t1, 768, 512);
    tsplit_kernel<<<(256 * 512 + 255) / 256, 256>>>(z2, t2, 512, 256);
    tsplit_kernel<<<(128 * 256 + 255) / 256, 256>>>(z3, t3, 256, 128);

    // layer 1: (B,768) @ (768,512)
    gemm_mma<768><<<dim3(4, BATCH / 128), 256, SMEM_SZ>>>(xh, xl, t1, h1h, h1l, 512, 0, pps, pfac);
    rowfac_kernel<4><<<BATCH / 256, 256>>>(pps, pfac, plam);
    // layer 2: (B,512) @ (512,256)
    gemm_mma<512><<<dim3(2, BATCH / 128), 256, SMEM_SZ>>>(h1h, h1l, t2, h2h, h2l, 256, 512, pps, pfac);
    rowfac_kernel<2><<<BATCH / 256, 256>>>(pps, pfac, plam);
    // layer 3: (B,256) @ (256,128)
    gemm_mma<256><<<dim3(1, BATCH / 128), 256, SMEM_SZ>>>(h2h, h2l, t3, h3h, h3l, 128, 768, pps, pfac);
    rowfac_kernel<1><<<BATCH / 256, 256>>>(pps, pfac, plam);
    // layer 4
    final_kernel<<<warpBlocks, 256>>>(h3h, h3l, z4, pfac, out);
}

// round 11
// speedup vs baseline: 4.6134x; 1.4329x over previous
#include <cuda_runtime.h>
#include <cuda_fp16.h>
#include <math.h>
#include <stdint.h>

#define CC 2.3026f
#define BATCH 65536
#define ASCALE 64.0f

// ---------------- static device scratch ----------------
__device__ __align__(256) __half g_x16[(size_t)BATCH * 768];
__device__ __align__(256) __half g_h1[(size_t)BATCH * 512];
__device__ __align__(256) __half g_h2[(size_t)BATCH * 256];
__device__ __align__(256) __half g_h3[(size_t)BATCH * 128];
__device__ float g_lam[BATCH];
__device__ float g_fac[BATCH];
__device__ float2 g_psum[(size_t)BATCH * 4];
__device__ float g_zn2[897], g_czn[897], g_shv[897];
// transposed fp16 weights [N, K] row-major
__device__ __align__(256) __half g_zt1[512 * 768];
__device__ __align__(256) __half g_zt2[256 * 512];
__device__ __align__(256) __half g_zt3[128 * 256];

// ---------------- PTX helpers ----------------
__device__ __forceinline__ uint32_t smem_u32(const void* p) {
    uint32_t a;
    asm("{ .reg .u64 t; cvta.to.shared.u64 t, %1; cvt.u32.u64 %0, t; }" : "=r"(a) : "l"(p));
    return a;
}
__device__ __forceinline__ void mma16816(float* d, const uint32_t* a, const uint32_t* b) {
    asm volatile(
        "mma.sync.aligned.m16n8k16.row.col.f32.f16.f16.f32 "
        "{%0,%1,%2,%3}, {%4,%5,%6,%7}, {%8,%9}, {%0,%1,%2,%3};"
        : "+f"(d[0]), "+f"(d[1]), "+f"(d[2]), "+f"(d[3])
        : "r"(a[0]), "r"(a[1]), "r"(a[2]), "r"(a[3]), "r"(b[0]), "r"(b[1]));
}
__device__ __forceinline__ void ldm_x4(uint32_t* r, uint32_t saddr) {
    asm volatile("ldmatrix.sync.aligned.m8n8.x4.shared.b16 {%0,%1,%2,%3}, [%4];"
        : "=r"(r[0]), "=r"(r[1]), "=r"(r[2]), "=r"(r[3]) : "r"(saddr));
}
#define CP16(sa, gp) asm volatile("cp.async.cg.shared.global [%0], [%1], 16;" :: "r"(sa), "l"(gp))
#define CP_COMMIT()  asm volatile("cp.async.commit_group;" ::: "memory")

// w = sinh(zn2 * asinh(u)) / cs,  u = a1*m*czn - a2*shv  (a1 includes fac_prev incl. 1/ASCALE)
__device__ __forceinline__ float wcalc(float mm, float a1, float a2,
                                       float czn, float shv, float zn2, float invcs)
{
    float u = fmaf(a1 * mm, czn, -(a2 * shv));
    float t = __logf(u + sqrtf(fmaf(u, u, 1.f)));
    float p = __expf(zn2 * t);
    return (p - __fdividef(1.f, p)) * (0.5f * invcs);
}

// ---------------- prep: warp per column ----------------
__global__ void prep_kernel(const float* __restrict__ z, const float* __restrict__ r,
                            int fi, int fo, int off)
{
    int gid = blockIdx.x * blockDim.x + threadIdx.x;
    int k = gid >> 5, lane = gid & 31;
    if (k >= fo) return;
    float s = 0.f;
    for (int i = lane; i < fi; i += 32) {
        float v = z[(long long)i * fo + k];
        s = fmaf(v, v, s);
    }
#pragma unroll
    for (int o = 16; o; o >>= 1) s += __shfl_xor_sync(0xffffffffu, s, o);
    if (lane == 0) {
        float zn = fmaxf(sqrtf(s), 1e-15f);
        float t = 2.f * sqrtf(CC) * r[k];
        float e = __expf(t);
        float ei = __fdividef(1.f, e);
        g_zn2[off + k] = 2.f * zn;
        g_czn[off + k] = 0.5f * (e + ei) / zn;
        g_shv[off + k] = 0.5f * (e - ei);
    }
}

// transpose weights -> fp16
__global__ void tsplit_kernel(const float* __restrict__ z, __half* __restrict__ th,
                              int fi, int fo)
{
    int idx = blockIdx.x * blockDim.x + threadIdx.x;
    if (idx >= fi * fo) return;
    int n = idx / fi, k = idx - n * fi;
    th[idx] = __float2half(z[(long long)k * fo + n]);
}

// lam0 + fac=1/ASCALE + ASCALE*x -> fp16. warp per row, fi=768.
__global__ void lam0_kernel(const float* __restrict__ x)
{
    int gid = blockIdx.x * blockDim.x + threadIdx.x;
    int row = gid >> 5, lane = gid & 31;
    const float4* xr = (const float4*)(x + (long long)row * 768);
    float s = 0.f;
#pragma unroll
    for (int p = 0; p < 6; p++) {
        int e4 = lane + 32 * p;
        float4 v = xr[e4];
        s += v.x * v.x + v.y * v.y + v.z * v.z + v.w * v.w;
        long long b = (long long)row * 768 + e4 * 4;
        __half2 h0; h0.x = __float2half(ASCALE * v.x); h0.y = __float2half(ASCALE * v.y);
        __half2 h1; h1.x = __float2half(ASCALE * v.z); h1.y = __float2half(ASCALE * v.w);
        ((__half2*)(g_x16 + b))[0] = h0;
        ((__half2*)(g_x16 + b))[1] = h1;
    }
#pragma unroll
    for (int o = 16; o; o >>= 1) s += __shfl_xor_sync(0xffffffffu, s, o);
    if (lane == 0) {
        g_lam[row] = __fdividef(2.f, 1.f - CC * s);
        g_fac[row] = 1.f / ASCALE;
    }
}

// ---------------- 4-stage pipelined single-product fp16 GEMM + fused epilogue ----------------
// C = A[128xK] @ Bt[128xK]^T; outputs ASCALE*relu(w) fp16 + row psums.
#define STAGE_SZ 20480
template <int KDIM>
__global__ __launch_bounds__(256, 2)
void gemm_mma(const __half* __restrict__ A, const __half* __restrict__ Bt,
              __half* __restrict__ Wh,
              int Nfull, int offTab, float2* __restrict__ psum,
              const float* __restrict__ facPrev)
{
    extern __shared__ char smem[];
    const uint32_t sbase = smem_u32(smem);
    constexpr int NB = KDIM / 32;

    int tid = threadIdx.x, wid = tid >> 5, lane = tid & 31;
    int warp_m = wid >> 1, warp_n = wid & 1;
    int gID = lane >> 2, tig = lane & 3;
    long long bm = (long long)blockIdx.y * 128;
    int bn = blockIdx.x * 128;
    int ntiles = gridDim.x;

    int c_row0 = tid >> 2, c_seg0 = tid & 3;
    int c_row1 = (tid + 256) >> 2, c_seg1 = (tid + 256) & 3;
    uint32_t so0 = (uint32_t)(c_row0 * 80 + c_seg0 * 16);
    uint32_t so1 = (uint32_t)(c_row1 * 80 + c_seg1 * 16);

    uint32_t a_off0 = (uint32_t)((warp_m * 32 + (lane & 15)) * 80 + ((lane >> 4) * 8) * 2);
    uint32_t a_off1 = a_off0 + 16 * 80;
    uint32_t b_off = (uint32_t)((warp_n * 64 + (lane & 7) + ((lane >> 3) & 2) * 4) * 80
                                + (((lane >> 3) & 1) * 8) * 2);

    float acc[2][8][4];
#pragma unroll
    for (int m = 0; m < 2; m++)
#pragma unroll
        for (int n = 0; n < 8; n++)
#pragma unroll
            for (int q = 0; q < 4; q++) acc[m][n][q] = 0.f;

    auto issue = [&](int i) {
        uint32_t st = sbase + (i & 3) * STAGE_SZ;
        int k0 = i * 32;
        long long ga0 = (bm + c_row0) * KDIM + k0 + c_seg0 * 8;
        long long gb0 = (long long)(bn + c_row0) * KDIM + k0 + c_seg0 * 8;
        long long ga1 = (bm + c_row1) * KDIM + k0 + c_seg1 * 8;
        long long gb1 = (long long)(bn + c_row1) * KDIM + k0 + c_seg1 * 8;
        CP16(st + so0,          A + ga0);
        CP16(st + 10240 + so0,  Bt + gb0);
        CP16(st + so1,          A + ga1);
        CP16(st + 10240 + so1,  Bt + gb1);
    };

    issue(0); CP_COMMIT();
    issue(1); CP_COMMIT();
    issue(2); CP_COMMIT();

    for (int i = 0; i < NB; i++) {
        int rem = NB - 1 - i;                   // stages still pending after i
        if (rem >= 2)      asm volatile("cp.async.wait_group 2;" ::: "memory");
        else if (rem == 1) asm volatile("cp.async.wait_group 1;" ::: "memory");
        else               asm volatile("cp.async.wait_group 0;" ::: "memory");
        __syncthreads();
        if (i + 3 < NB) { issue(i + 3); CP_COMMIT(); }

        uint32_t st = sbase + (i & 3) * STAGE_SZ;
        uint32_t sA = st, sB = st + 10240;

#pragma unroll
        for (int ks = 0; ks < 32; ks += 16) {
            uint32_t ah[2][4];
            ldm_x4(ah[0], sA + a_off0 + ks * 2);
            ldm_x4(ah[1], sA + a_off1 + ks * 2);
#pragma unroll
            for (int n2 = 0; n2 < 4; n2++) {
                uint32_t bh[4];
                ldm_x4(bh, sB + b_off + (uint32_t)(n2 * 16 * 80) + ks * 2);
#pragma unroll
                for (int g = 0; g < 2; g++) {
#pragma unroll
                    for (int m = 0; m < 2; m++)
                        mma16816(acc[m][n2 * 2 + g], ah[m], &bh[g * 2]);
                }
            }
        }
        __syncthreads();
    }

    // ---- fused epilogue: m -> w -> relu -> scaled fp16, plus per-row partial sums ----
    const float cs = sqrtf(CC);
    const float invcs = 1.f / cs;
    float s4[4] = {0.f, 0.f, 0.f, 0.f}, sp4[4] = {0.f, 0.f, 0.f, 0.f};
#pragma unroll
    for (int m = 0; m < 2; m++) {
        long long rA = bm + warp_m * 32 + m * 16 + gID;
        float lamA = g_lam[rA], lamB = g_lam[rA + 8];
        float fA = facPrev[rA], fB = facPrev[rA + 8];
        float a1A = cs * lamA * fA, a2A = lamA - 1.f;
        float a1B = cs * lamB * fB, a2B = lamB - 1.f;
#pragma unroll
        for (int n = 0; n < 8; n++) {
            int k = offTab + bn + warp_n * 64 + n * 8 + tig * 2;
            float czn0 = g_czn[k], czn1 = g_czn[k + 1];
            float shv0 = g_shv[k], shv1 = g_shv[k + 1];
            float zn0  = g_zn2[k], zn1  = g_zn2[k + 1];
            float w0 = wcalc(acc[m][n][0], a1A, a2A, czn0, shv0, zn0, invcs);
            float w1 = wcalc(acc[m][n][1], a1A, a2A, czn1, shv1, zn1, invcs);
            float w2 = wcalc(acc[m][n][2], a1B, a2B, czn0, shv0, zn0, invcs);
            float w3 = wcalc(acc[m][n][3], a1B, a2B, czn1, shv1, zn1, invcs);
            s4[m * 2]     += fmaf(w0, w0, w1 * w1);
            s4[m * 2 + 1] += fmaf(w2, w2, w3 * w3);
            float p0 = fmaxf(w0, 0.f), p1 = fmaxf(w1, 0.f);
            float p2 = fmaxf(w2, 0.f), p3 = fmaxf(w3, 0.f);
            sp4[m * 2]     += fmaf(p0, p0, p1 * p1);
            sp4[m * 2 + 1] += fmaf(p2, p2, p3 * p3);
            acc[m][n][0] = p0; acc[m][n][1] = p1; acc[m][n][2] = p2; acc[m][n][3] = p3;
        }
    }
#pragma unroll
    for (int q = 0; q < 4; q++) {
        s4[q]  += __shfl_xor_sync(0xffffffffu, s4[q], 1);
        s4[q]  += __shfl_xor_sync(0xffffffffu, s4[q], 2);
        sp4[q] += __shfl_xor_sync(0xffffffffu, sp4[q], 1);
        sp4[q] += __shfl_xor_sync(0xffffffffu, sp4[q], 2);
    }
    __syncthreads();  // stage buffers alias sred
    float2* sred = (float2*)smem;
    if (tig == 0) {
        int rl = warp_m * 32 + gID;
        sred[(rl)      * 2 + warp_n] = make_float2(s4[0], sp4[0]);
        sred[(rl + 8)  * 2 + warp_n] = make_float2(s4[1], sp4[1]);
        sred[(rl + 16) * 2 + warp_n] = make_float2(s4[2], sp4[2]);
        sred[(rl + 24) * 2 + warp_n] = make_float2(s4[3], sp4[3]);
    }
    __syncthreads();
    if (tid < 128) {
        float2 a = sred[tid * 2], b = sred[tid * 2 + 1];
        psum[(bm + tid) * ntiles + blockIdx.x] = make_float2(a.x + b.x, a.y + b.y);
    }

    // store ASCALE*relu(w) as fp16
#pragma unroll
    for (int m = 0; m < 2; m++) {
#pragma unroll
        for (int n = 0; n < 8; n++) {
            long long r = bm + warp_m * 32 + m * 16 + gID;
            int c = bn + warp_n * 64 + n * 8 + tig * 2;
            __half2 hi0, hi1;
            hi0.x = __float2half(ASCALE * acc[m][n][0]);
            hi0.y = __float2half(ASCALE * acc[m][n][1]);
            hi1.x = __float2half(ASCALE * acc[m][n][2]);
            hi1.y = __float2half(ASCALE * acc[m][n][3]);
            *(__half2*)(Wh + r * Nfull + c)       = hi0;
            *(__half2*)(Wh + (r + 8) * Nfull + c) = hi1;
        }
    }
}

// ---------------- per-row factor kernel ----------------
template <int NT>
__global__ void rowfac_kernel(const float2* __restrict__ ps,
                              float* __restrict__ fac, float* __restrict__ lam)
{
    int row = blockIdx.x * blockDim.x + threadIdx.x;
    float s = 0.f, sp = 0.f;
#pragma unroll
    for (int t = 0; t < NT; t++) {
        float2 v = ps[(long long)row * NT + t];
        s += v.x; sp += v.y;
    }
    const float cs = sqrtf(CC);
    float inv = __fdividef(1.f, 1.f + sqrtf(fmaf(CC, s, 1.f)));
    float n  = fmaxf(sqrtf(s) * inv, 1e-15f);
    float cn = fminf(cs * n, 1.f - 1e-7f);
    float a  = __fdividef(0.5f * __logf(__fdividef(1.f + cn, 1.f - cn)), cs * n);
    float vn = fmaxf(a * inv * sqrtf(sp), 1e-15f);
    float e  = __expf(2.f * cs * vn);
    float th = __fdividef(e - 1.f, e + 1.f);
    float fc = __fdividef(th, cs * vn) * a;
    fac[row] = fc * inv * (1.f / ASCALE);   // next GEMM's A stored pre-scaled by ASCALE
    lam[row] = 0.5f * (e + 2.f + __fdividef(1.f, e));
}

// ---------------- final layer fo=1 ----------------
__global__ void final_kernel(const __half* __restrict__ hh,
                             const float* __restrict__ z4, const float* __restrict__ fac,
                             float* __restrict__ out)
{
    int gid = blockIdx.x * blockDim.x + threadIdx.x;
    int row = gid >> 5, lane = gid & 31;
    float s = 0.f;
#pragma unroll
    for (int p = 0; p < 4; p++) {
        int k = lane + 32 * p;
        s = fmaf(__half2float(hh[(long long)row * 128 + k]), z4[k], s);
    }
#pragma unroll
    for (int o = 16; o; o >>= 1) s += __shfl_xor_sync(0xffffffffu, s, o);
    if (lane == 0) {
        const float cs = sqrtf(CC);
        float lam = g_lam[row];
        float se = s * fac[row];
        float u = fmaf(cs * lam * se, g_czn[896], -((lam - 1.f) * g_shv[896]));
        float t = __logf(u + sqrtf(fmaf(u, u, 1.f)));
        float p = __expf(g_zn2[896] * t);
        float w = (p - __fdividef(1.f, p)) * (0.5f / cs);
        out[row] = __fdividef(w, 1.f + sqrtf(fmaf(CC, w * w, 1.f)));
    }
}

// ---------------- launch ----------------
extern "C" void kernel_launch(void* const* d_in, const int* in_sizes, int n_in,
                              void* d_out, int out_size)
{
    const float* x  = (const float*)d_in[0];
    const float* z1 = (const float*)d_in[1];
    const float* b1 = (const float*)d_in[2];
    const float* z2 = (const float*)d_in[3];
    const float* b2 = (const float*)d_in[4];
    const float* z3 = (const float*)d_in[5];
    const float* b3 = (const float*)d_in[6];
    const float* z4 = (const float*)d_in[7];
    const float* b4 = (const float*)d_in[8];
    float* out = (float*)d_out;

    float* pfac; cudaGetSymbolAddress((void**)&pfac, g_fac);
    float* plam; cudaGetSymbolAddress((void**)&plam, g_lam);
    float2* pps; cudaGetSymbolAddress((void**)&pps, g_psum);
    __half *xh, *h1, *h2, *h3, *t1, *t2, *t3;
    cudaGetSymbolAddress((void**)&xh, g_x16);
    cudaGetSymbolAddress((void**)&h1, g_h1);
    cudaGetSymbolAddress((void**)&h2, g_h2);
    cudaGetSymbolAddress((void**)&h3, g_h3);
    cudaGetSymbolAddress((void**)&t1, g_zt1);
    cudaGetSymbolAddress((void**)&t2, g_zt2);
    cudaGetSymbolAddress((void**)&t3, g_zt3);

    const int SMEM_SZ = 4 * STAGE_SZ;  // 81920
    cudaFuncSetAttribute(gemm_mma<768>, cudaFuncAttributeMaxDynamicSharedMemorySize, SMEM_SZ);
    cudaFuncSetAttribute(gemm_mma<512>, cudaFuncAttributeMaxDynamicSharedMemorySize, SMEM_SZ);
    cudaFuncSetAttribute(gemm_mma<256>, cudaFuncAttributeMaxDynamicSharedMemorySize, SMEM_SZ);

    const int warpBlocks = BATCH * 32 / 256;

    lam0_kernel<<<warpBlocks, 256>>>(x);
    prep_kernel<<<(512 * 32 + 255) / 256, 256>>>(z1, b1, 768, 512, 0);
    prep_kernel<<<(256 * 32 + 255) / 256, 256>>>(z2, b2, 512, 256, 512);
    prep_kernel<<<(128 * 32 + 255) / 256, 256>>>(z3, b3, 256, 128, 768);
    prep_kernel<<<1, 32>>>(z4, b4, 128, 1, 896);
    tsplit_kernel<<<(512 * 768 + 255) / 256, 256>>>(z1, t1, 768, 512);
    tsplit_kernel<<<(256 * 512 + 255) / 256, 256>>>(z2, t2, 512, 256);
    tsplit_kernel<<<(128 * 256 + 255) / 256, 256>>>(z3, t3, 256, 128);

    // layer 1: (B,768) @ (768,512)
    gemm_mma<768><<<dim3(4, BATCH / 128), 256, SMEM_SZ>>>(xh, t1, h1, 512, 0, pps, pfac);
    rowfac_kernel<4><<<BATCH / 256, 256>>>(pps, pfac, plam);
    // layer 2: (B,512) @ (512,256)
    gemm_mma<512><<<dim3(2, BATCH / 128), 256, SMEM_SZ>>>(h1, t2, h2, 256, 512, pps, pfac);
    rowfac_kernel<2><<<BATCH / 256, 256>>>(pps, pfac, plam);
    // layer 3: (B,256) @ (256,128)
    gemm_mma<256><<<dim3(1, BATCH / 128), 256, SMEM_SZ>>>(h2, t3, h3, 128, 768, pps, pfac);
    rowfac_kernel<1><<<BATCH / 256, 256>>>(pps, pfac, plam);
    // layer 4
    final_kernel<<<warpBlocks, 256>>>(h3, z4, pfac, out);
}

// round 12
// speedup vs baseline: 4.8327x; 1.0475x over previous
#include <cuda_runtime.h>
#include <cuda_fp16.h>
#include <math.h>
#include <stdint.h>

#define CC 2.3026f
#define BATCH 65536
#define ASCALE 64.0f

// ---------------- static device scratch ----------------
__device__ __align__(256) __half g_x16[(size_t)BATCH * 768];
__device__ __align__(256) __half g_h1[(size_t)BATCH * 512];
__device__ __align__(256) __half g_h2[(size_t)BATCH * 256];
__device__ __align__(256) __half g_h3[(size_t)BATCH * 128];
__device__ float g_lam[BATCH];
__device__ float g_fac[BATCH];
__device__ float2 g_psumA[(size_t)BATCH * 4];
__device__ float2 g_psumB[(size_t)BATCH * 4];
__device__ float g_zn2[897], g_czn[897], g_shv[897];
__device__ __align__(256) __half g_zt1[512 * 768];
__device__ __align__(256) __half g_zt2[256 * 512];
__device__ __align__(256) __half g_zt3[128 * 256];

// ---------------- PTX helpers ----------------
__device__ __forceinline__ uint32_t smem_u32(const void* p) {
    uint32_t a;
    asm("{ .reg .u64 t; cvta.to.shared.u64 t, %1; cvt.u32.u64 %0, t; }" : "=r"(a) : "l"(p));
    return a;
}
__device__ __forceinline__ void mma16816(float* d, const uint32_t* a, const uint32_t* b) {
    asm volatile(
        "mma.sync.aligned.m16n8k16.row.col.f32.f16.f16.f32 "
        "{%0,%1,%2,%3}, {%4,%5,%6,%7}, {%8,%9}, {%0,%1,%2,%3};"
        : "+f"(d[0]), "+f"(d[1]), "+f"(d[2]), "+f"(d[3])
        : "r"(a[0]), "r"(a[1]), "r"(a[2]), "r"(a[3]), "r"(b[0]), "r"(b[1]));
}
__device__ __forceinline__ void ldm_x4(uint32_t* r, uint32_t saddr) {
    asm volatile("ldmatrix.sync.aligned.m8n8.x4.shared.b16 {%0,%1,%2,%3}, [%4];"
        : "=r"(r[0]), "=r"(r[1]), "=r"(r[2]), "=r"(r[3]) : "r"(saddr));
}
#define CP16(sa, gp) asm volatile("cp.async.cg.shared.global [%0], [%1], 16;" :: "r"(sa), "l"(gp))
#define CP_COMMIT()  asm volatile("cp.async.commit_group;" ::: "memory")

// w = sinh(zn2 * asinh(u)) / cs
__device__ __forceinline__ float wcalc(float mm, float a1, float a2,
                                       float czn, float shv, float zn2, float invcs)
{
    float u = fmaf(a1 * mm, czn, -(a2 * shv));
    float t = __logf(u + sqrtf(fmaf(u, u, 1.f)));
    float p = __expf(zn2 * t);
    return (p - __fdividef(1.f, p)) * (0.5f * invcs);
}

// (fac, lam) from per-row sums (identical arithmetic to R11 rowfac_kernel)
__device__ __forceinline__ float2 faclam(float s, float sp)
{
    const float cs = sqrtf(CC);
    float inv = __fdividef(1.f, 1.f + sqrtf(fmaf(CC, s, 1.f)));
    float n  = fmaxf(sqrtf(s) * inv, 1e-15f);
    float cn = fminf(cs * n, 1.f - 1e-7f);
    float a  = __fdividef(0.5f * __logf(__fdividef(1.f + cn, 1.f - cn)), cs * n);
    float vn = fmaxf(a * inv * sqrtf(sp), 1e-15f);
    float e  = __expf(2.f * cs * vn);
    float th = __fdividef(e - 1.f, e + 1.f);
    float fc = __fdividef(th, cs * vn) * a;
    return make_float2(fc * inv * (1.f / ASCALE), 0.5f * (e + 2.f + __fdividef(1.f, e)));
}

// ---------------- fused weight prep: transpose-convert + column tables, ONE launch ----------------
// blocks [0,2176): tsplit for z1/z2/z3 ; blocks [2176,2289): warp-per-column tables
__global__ void wprep_kernel(const float* __restrict__ z1, const float* __restrict__ b1,
                             const float* __restrict__ z2, const float* __restrict__ b2,
                             const float* __restrict__ z3, const float* __restrict__ b3,
                             const float* __restrict__ z4, const float* __restrict__ b4,
                             __half* __restrict__ t1, __half* __restrict__ t2, __half* __restrict__ t3)
{
    if (blockIdx.x < 2176) {
        int idx = blockIdx.x * 256 + threadIdx.x;
        if (idx < 393216) {
            int n = idx / 768, k = idx - n * 768;
            t1[idx] = __float2half(z1[(long long)k * 512 + n]);
        } else if (idx < 524288) {
            int i2 = idx - 393216;
            int n = i2 / 512, k = i2 - n * 512;
            t2[i2] = __float2half(z2[(long long)k * 256 + n]);
        } else {
            int i3 = idx - 524288;
            int n = i3 / 256, k = i3 - n * 256;
            t3[i3] = __float2half(z3[(long long)k * 128 + n]);
        }
    } else {
        int tid2 = (blockIdx.x - 2176) * 256 + threadIdx.x;
        int w = tid2 >> 5, lane = tid2 & 31;
        if (w >= 897) return;
        const float *z, *r; int fi, fo, off, k;
        if (w < 512)      { z = z1; r = b1; fi = 768; fo = 512; off = 0;   k = w; }
        else if (w < 768) { z = z2; r = b2; fi = 512; fo = 256; off = 512; k = w - 512; }
        else if (w < 896) { z = z3; r = b3; fi = 256; fo = 128; off = 768; k = w - 768; }
        else              { z = z4; r = b4; fi = 128; fo = 1;   off = 896; k = 0; }
        float s = 0.f;
        for (int i = lane; i < fi; i += 32) {
            float v = z[(long long)i * fo + k];
            s = fmaf(v, v, s);
        }
#pragma unroll
        for (int o = 16; o; o >>= 1) s += __shfl_xor_sync(0xffffffffu, s, o);
        if (lane == 0) {
            float zn = fmaxf(sqrtf(s), 1e-15f);
            float t = 2.f * sqrtf(CC) * r[k];
            float e = __expf(t);
            float ei = __fdividef(1.f, e);
            g_zn2[off + k] = 2.f * zn;
            g_czn[off + k] = 0.5f * (e + ei) / zn;
            g_shv[off + k] = 0.5f * (e - ei);
        }
    }
}

// lam0 + fac=1/ASCALE + ASCALE*x -> fp16. warp per row, fi=768.
__global__ void lam0_kernel(const float* __restrict__ x)
{
    int gid = blockIdx.x * blockDim.x + threadIdx.x;
    int row = gid >> 5, lane = gid & 31;
    const float4* xr = (const float4*)(x + (long long)row * 768);
    float s = 0.f;
#pragma unroll
    for (int p = 0; p < 6; p++) {
        int e4 = lane + 32 * p;
        float4 v = xr[e4];
        s += v.x * v.x + v.y * v.y + v.z * v.z + v.w * v.w;
        long long b = (long long)row * 768 + e4 * 4;
        __half2 h0; h0.x = __float2half(ASCALE * v.x); h0.y = __float2half(ASCALE * v.y);
        __half2 h1; h1.x = __float2half(ASCALE * v.z); h1.y = __float2half(ASCALE * v.w);
        ((__half2*)(g_x16 + b))[0] = h0;
        ((__half2*)(g_x16 + b))[1] = h1;
    }
#pragma unroll
    for (int o = 16; o; o >>= 1) s += __shfl_xor_sync(0xffffffffu, s, o);
    if (lane == 0) {
        g_lam[row] = __fdividef(2.f, 1.f - CC * s);
        g_fac[row] = 1.f / ASCALE;
    }
}

// ---------------- 4-stage pipelined fp16 GEMM + fused epilogue (incl. row factors) ----------------
// NTPREV==0: first layer, (fac,lam) from g_fac/g_lam; else computed from psumPrev (NTPREV tiles/row).
#define STAGE_SZ 20480
template <int KDIM, int NTPREV>
__global__ __launch_bounds__(256, 2)
void gemm_mma(const __half* __restrict__ A, const __half* __restrict__ Bt,
              __half* __restrict__ Wh,
              int Nfull, int offTab, float2* __restrict__ psum,
              const float2* __restrict__ psumPrev)
{
    extern __shared__ char smem[];
    const uint32_t sbase = smem_u32(smem);
    constexpr int NB = KDIM / 32;

    int tid = threadIdx.x, wid = tid >> 5, lane = tid & 31;
    int warp_m = wid >> 1, warp_n = wid & 1;
    int gID = lane >> 2, tig = lane & 3;
    long long bm = (long long)blockIdx.y * 128;
    int bn = blockIdx.x * 128;
    int ntiles = gridDim.x;

    int c_row0 = tid >> 2, c_seg0 = tid & 3;
    int c_row1 = (tid + 256) >> 2, c_seg1 = (tid + 256) & 3;
    uint32_t so0 = (uint32_t)(c_row0 * 80 + c_seg0 * 16);
    uint32_t so1 = (uint32_t)(c_row1 * 80 + c_seg1 * 16);

    uint32_t a_off0 = (uint32_t)((warp_m * 32 + (lane & 15)) * 80 + ((lane >> 4) * 8) * 2);
    uint32_t a_off1 = a_off0 + 16 * 80;
    uint32_t b_off = (uint32_t)((warp_n * 64 + (lane & 7) + ((lane >> 3) & 2) * 4) * 80
                                + (((lane >> 3) & 1) * 8) * 2);

    float acc[2][8][4];
#pragma unroll
    for (int m = 0; m < 2; m++)
#pragma unroll
        for (int n = 0; n < 8; n++)
#pragma unroll
            for (int q = 0; q < 4; q++) acc[m][n][q] = 0.f;

    auto issue = [&](int i) {
        uint32_t st = sbase + (i & 3) * STAGE_SZ;
        int k0 = i * 32;
        long long ga0 = (bm + c_row0) * KDIM + k0 + c_seg0 * 8;
        long long gb0 = (long long)(bn + c_row0) * KDIM + k0 + c_seg0 * 8;
        long long ga1 = (bm + c_row1) * KDIM + k0 + c_seg1 * 8;
        long long gb1 = (long long)(bn + c_row1) * KDIM + k0 + c_seg1 * 8;
        CP16(st + so0,          A + ga0);
        CP16(st + 10240 + so0,  Bt + gb0);
        CP16(st + so1,          A + ga1);
        CP16(st + 10240 + so1,  Bt + gb1);
    };

    issue(0); CP_COMMIT();
    issue(1); CP_COMMIT();
    issue(2); CP_COMMIT();

    for (int i = 0; i < NB; i++) {
        int rem = NB - 1 - i;
        if (rem >= 2)      asm volatile("cp.async.wait_group 2;" ::: "memory");
        else if (rem == 1) asm volatile("cp.async.wait_group 1;" ::: "memory");
        else               asm volatile("cp.async.wait_group 0;" ::: "memory");
        __syncthreads();
        if (i + 3 < NB) { issue(i + 3); CP_COMMIT(); }

        uint32_t st = sbase + (i & 3) * STAGE_SZ;
        uint32_t sA = st, sB = st + 10240;

#pragma unroll
        for (int ks = 0; ks < 32; ks += 16) {
            uint32_t ah[2][4];
            ldm_x4(ah[0], sA + a_off0 + ks * 2);
            ldm_x4(ah[1], sA + a_off1 + ks * 2);
#pragma unroll
            for (int n2 = 0; n2 < 4; n2++) {
                uint32_t bh[4];
                ldm_x4(bh, sB + b_off + (uint32_t)(n2 * 16 * 80) + ks * 2);
#pragma unroll
                for (int g = 0; g < 2; g++) {
#pragma unroll
                    for (int m = 0; m < 2; m++)
                        mma16816(acc[m][n2 * 2 + g], ah[m], &bh[g * 2]);
                }
            }
        }
        __syncthreads();
    }

    // ---- row factors into SMEM (replaces standalone rowfac kernel) ----
    float2* sred   = (float2*)smem;                 // [0, 2048)
    float2* rowdat = (float2*)(smem + 2048);        // [2048, 3072)
    if (tid < 128) {
        float2 fl;
        if (NTPREV == 0) {
            fl = make_float2(g_fac[bm + tid], g_lam[bm + tid]);
        } else {
            float s = 0.f, sp = 0.f;
#pragma unroll
            for (int t = 0; t < NTPREV; t++) {
                float2 v = psumPrev[(bm + tid) * NTPREV + t];
                s += v.x; sp += v.y;
            }
            fl = faclam(s, sp);
        }
        rowdat[tid] = fl;
    }
    __syncthreads();

    // ---- fused epilogue: m -> w -> relu -> scaled fp16, plus per-row partial sums ----
    const float cs = sqrtf(CC);
    const float invcs = 1.f / cs;
    float s4[4] = {0.f, 0.f, 0.f, 0.f}, sp4[4] = {0.f, 0.f, 0.f, 0.f};
#pragma unroll
    for (int m = 0; m < 2; m++) {
        int lr = warp_m * 32 + m * 16 + gID;
        float2 flA = rowdat[lr], flB = rowdat[lr + 8];
        float a1A = cs * flA.y * flA.x, a2A = flA.y - 1.f;
        float a1B = cs * flB.y * flB.x, a2B = flB.y - 1.f;
#pragma unroll
        for (int n = 0; n < 8; n++) {
            int k = offTab + bn + warp_n * 64 + n * 8 + tig * 2;
            float czn0 = g_czn[k], czn1 = g_czn[k + 1];
            float shv0 = g_shv[k], shv1 = g_shv[k + 1];
            float zn0  = g_zn2[k], zn1  = g_zn2[k + 1];
            float w0 = wcalc(acc[m][n][0], a1A, a2A, czn0, shv0, zn0, invcs);
            float w1 = wcalc(acc[m][n][1], a1A, a2A, czn1, shv1, zn1, invcs);
            float w2 = wcalc(acc[m][n][2], a1B, a2B, czn0, shv0, zn0, invcs);
            float w3 = wcalc(acc[m][n][3], a1B, a2B, czn1, shv1, zn1, invcs);
            s4[m * 2]     += fmaf(w0, w0, w1 * w1);
            s4[m * 2 + 1] += fmaf(w2, w2, w3 * w3);
            float p0 = fmaxf(w0, 0.f), p1 = fmaxf(w1, 0.f);
            float p2 = fmaxf(w2, 0.f), p3 = fmaxf(w3, 0.f);
            sp4[m * 2]     += fmaf(p0, p0, p1 * p1);
            sp4[m * 2 + 1] += fmaf(p2, p2, p3 * p3);
            acc[m][n][0] = p0; acc[m][n][1] = p1; acc[m][n][2] = p2; acc[m][n][3] = p3;
        }
    }
#pragma unroll
    for (int q = 0; q < 4; q++) {
        s4[q]  += __shfl_xor_sync(0xffffffffu, s4[q], 1);
        s4[q]  += __shfl_xor_sync(0xffffffffu, s4[q], 2);
        sp4[q] += __shfl_xor_sync(0xffffffffu, sp4[q], 1);
        sp4[q] += __shfl_xor_sync(0xffffffffu, sp4[q], 2);
    }
    if (tig == 0) {
        int rl = warp_m * 32 + gID;
        sred[(rl)      * 2 + warp_n] = make_float2(s4[0], sp4[0]);
        sred[(rl + 8)  * 2 + warp_n] = make_float2(s4[1], sp4[1]);
        sred[(rl + 16) * 2 + warp_n] = make_float2(s4[2], sp4[2]);
        sred[(rl + 24) * 2 + warp_n] = make_float2(s4[3], sp4[3]);
    }
    __syncthreads();
    if (tid < 128) {
        float2 a = sred[tid * 2], b = sred[tid * 2 + 1];
        psum[(bm + tid) * ntiles + blockIdx.x] = make_float2(a.x + b.x, a.y + b.y);
    }

    // store ASCALE*relu(w) as fp16
#pragma unroll
    for (int m = 0; m < 2; m++) {
#pragma unroll
        for (int n = 0; n < 8; n++) {
            long long r = bm + warp_m * 32 + m * 16 + gID;
            int c = bn + warp_n * 64 + n * 8 + tig * 2;
            __half2 hi0, hi1;
            hi0.x = __float2half(ASCALE * acc[m][n][0]);
            hi0.y = __float2half(ASCALE * acc[m][n][1]);
            hi1.x = __float2half(ASCALE * acc[m][n][2]);
            hi1.y = __float2half(ASCALE * acc[m][n][3]);
            *(__half2*)(Wh + r * Nfull + c)       = hi0;
            *(__half2*)(Wh + (r + 8) * Nfull + c) = hi1;
        }
    }
}

// ---------------- final layer fo=1 ----------------
__global__ void final_kernel(const __half* __restrict__ hh,
                             const float* __restrict__ z4, const float2* __restrict__ psum3,
                             float* __restrict__ out)
{
    int gid = blockIdx.x * blockDim.x + threadIdx.x;
    int row = gid >> 5, lane = gid & 31;
    float s = 0.f;
#pragma unroll
    for (int p = 0; p < 4; p++) {
        int k = lane + 32 * p;
        s = fmaf(__half2float(hh[(long long)row * 128 + k]), z4[k], s);
    }
#pragma unroll
    for (int o = 16; o; o >>= 1) s += __shfl_xor_sync(0xffffffffu, s, o);
    if (lane == 0) {
        const float cs = sqrtf(CC);
        float2 v = psum3[row];                 // layer-3 psum (NT=1)
        float2 fl = faclam(v.x, v.y);
        float lam = fl.y;
        float se = s * fl.x;
        float u = fmaf(cs * lam * se, g_czn[896], -((lam - 1.f) * g_shv[896]));
        float t = __logf(u + sqrtf(fmaf(u, u, 1.f)));
        float p = __expf(g_zn2[896] * t);
        float w = (p - __fdividef(1.f, p)) * (0.5f / cs);
        out[row] = __fdividef(w, 1.f + sqrtf(fmaf(CC, w * w, 1.f)));
    }
}

// ---------------- launch ----------------
extern "C" void kernel_launch(void* const* d_in, const int* in_sizes, int n_in,
                              void* d_out, int out_size)
{
    const float* x  = (const float*)d_in[0];
    const float* z1 = (const float*)d_in[1];
    const float* b1 = (const float*)d_in[2];
    const float* z2 = (const float*)d_in[3];
    const float* b2 = (const float*)d_in[4];
    const float* z3 = (const float*)d_in[5];
    const float* b3 = (const float*)d_in[6];
    const float* z4 = (const float*)d_in[7];
    const float* b4 = (const float*)d_in[8];
    float* out = (float*)d_out;

    float2 *ppsA, *ppsB;
    cudaGetSymbolAddress((void**)&ppsA, g_psumA);
    cudaGetSymbolAddress((void**)&ppsB, g_psumB);
    __half *xh, *h1, *h2, *h3, *t1, *t2, *t3;
    cudaGetSymbolAddress((void**)&xh, g_x16);
    cudaGetSymbolAddress((void**)&h1, g_h1);
    cudaGetSymbolAddress((void**)&h2, g_h2);
    cudaGetSymbolAddress((void**)&h3, g_h3);
    cudaGetSymbolAddress((void**)&t1, g_zt1);
    cudaGetSymbolAddress((void**)&t2, g_zt2);
    cudaGetSymbolAddress((void**)&t3, g_zt3);

    const int SMEM_SZ = 4 * STAGE_SZ;  // 81920
    cudaFuncSetAttribute((const void*)gemm_mma<768, 0>, cudaFuncAttributeMaxDynamicSharedMemorySize, SMEM_SZ);
    cudaFuncSetAttribute((const void*)gemm_mma<512, 4>, cudaFuncAttributeMaxDynamicSharedMemorySize, SMEM_SZ);
    cudaFuncSetAttribute((const void*)gemm_mma<256, 2>, cudaFuncAttributeMaxDynamicSharedMemorySize, SMEM_SZ);

    const int warpBlocks = BATCH * 32 / 256;

    lam0_kernel<<<warpBlocks, 256>>>(x);
    wprep_kernel<<<2289, 256>>>(z1, b1, z2, b2, z3, b3, z4, b4, t1, t2, t3);

    // layer 1: (B,768) @ (768,512) -> psumA (4 tiles/row)
    gemm_mma<768, 0><<<dim3(4, BATCH / 128), 256, SMEM_SZ>>>(xh, t1, h1, 512, 0, ppsA, nullptr);
    // layer 2: (B,512) @ (512,256), factors from psumA -> psumB (2 tiles/row)
    gemm_mma<512, 4><<<dim3(2, BATCH / 128), 256, SMEM_SZ>>>(h1, t2, h2, 256, 512, ppsB, ppsA);
    // layer 3: (B,256) @ (256,128), factors from psumB -> psumA (1 tile/row)
    gemm_mma<256, 2><<<dim3(1, BATCH / 128), 256, SMEM_SZ>>>(h2, t3, h3, 128, 768, ppsA, ppsB);
    // layer 4: factors from psumA
    final_kernel<<<warpBlocks, 256>>>(h3, z4, ppsA, out);
}

// round 14
// speedup vs baseline: 5.1778x; 1.0714x over previous
#include <cuda_runtime.h>
#include <cuda_fp16.h>
#include <math.h>
#include <stdint.h>

#define CC 2.3026f
#define BATCH 65536
#define ASCALE 64.0f

// ---------------- static device scratch ----------------
__device__ __align__(256) __half g_x16[(size_t)BATCH * 768];
__device__ __align__(256) __half g_h1[(size_t)BATCH * 512];
__device__ __align__(256) __half g_h2[(size_t)BATCH * 256];
__device__ __align__(256) __half g_h3[(size_t)BATCH * 128];
__device__ float g_lam[BATCH];
__device__ float g_fac[BATCH];
__device__ float2 g_psumA[(size_t)BATCH * 4];
__device__ float2 g_psumB[(size_t)BATCH * 4];
__device__ float g_zn2[897], g_czn[897], g_shv[897];
__device__ __align__(256) __half g_zt1[512 * 768];
__device__ __align__(256) __half g_zt2[256 * 512];
__device__ __align__(256) __half g_zt3[128 * 256];

// ---------------- PTX helpers ----------------
__device__ __forceinline__ uint32_t smem_u32(const void* p) {
    uint32_t a;
    asm("{ .reg .u64 t; cvta.to.shared.u64 t, %1; cvt.u32.u64 %0, t; }" : "=r"(a) : "l"(p));
    return a;
}
__device__ __forceinline__ void mma16816(float* d, const uint32_t* a, const uint32_t* b) {
    asm volatile(
        "mma.sync.aligned.m16n8k16.row.col.f32.f16.f16.f32 "
        "{%0,%1,%2,%3}, {%4,%5,%6,%7}, {%8,%9}, {%0,%1,%2,%3};"
        : "+f"(d[0]), "+f"(d[1]), "+f"(d[2]), "+f"(d[3])
        : "r"(a[0]), "r"(a[1]), "r"(a[2]), "r"(a[3]), "r"(b[0]), "r"(b[1]));
}
__device__ __forceinline__ void ldm_x4(uint32_t* r, uint32_t saddr) {
    asm volatile("ldmatrix.sync.aligned.m8n8.x4.shared.b16 {%0,%1,%2,%3}, [%4];"
        : "=r"(r[0]), "=r"(r[1]), "=r"(r[2]), "=r"(r[3]) : "r"(saddr));
}
#define CP16(sa, gp) asm volatile("cp.async.cg.shared.global [%0], [%1], 16;" :: "r"(sa), "l"(gp))
#define CP_COMMIT()  asm volatile("cp.async.commit_group;" ::: "memory")

// w = sinh(zn2 * asinh(u)) / cs
__device__ __forceinline__ float wcalc(float mm, float a1, float a2,
                                       float czn, float shv, float zn2, float invcs)
{
    float u = fmaf(a1 * mm, czn, -(a2 * shv));
    float t = __logf(u + sqrtf(fmaf(u, u, 1.f)));
    float p = __expf(zn2 * t);
    return (p - __fdividef(1.f, p)) * (0.5f * invcs);
}

// (fac, lam) from per-row sums
__device__ __forceinline__ float2 faclam(float s, float sp)
{
    const float cs = sqrtf(CC);
    float inv = __fdividef(1.f, 1.f + sqrtf(fmaf(CC, s, 1.f)));
    float n  = fmaxf(sqrtf(s) * inv, 1e-15f);
    float cn = fminf(cs * n, 1.f - 1e-7f);
    float a  = __fdividef(0.5f * __logf(__fdividef(1.f + cn, 1.f - cn)), cs * n);
    float vn = fmaxf(a * inv * sqrtf(sp), 1e-15f);
    float e  = __expf(2.f * cs * vn);
    float th = __fdividef(e - 1.f, e + 1.f);
    float fc = __fdividef(th, cs * vn) * a;
    return make_float2(fc * inv * (1.f / ASCALE), 0.5f * (e + 2.f + __fdividef(1.f, e)));
}

// ---------------- fused weight prep (one launch) ----------------
__global__ void wprep_kernel(const float* __restrict__ z1, const float* __restrict__ b1,
                             const float* __restrict__ z2, const float* __restrict__ b2,
                             const float* __restrict__ z3, const float* __restrict__ b3,
                             const float* __restrict__ z4, const float* __restrict__ b4,
                             __half* __restrict__ t1, __half* __restrict__ t2, __half* __restrict__ t3)
{
    if (blockIdx.x < 2176) {
        int idx = blockIdx.x * 256 + threadIdx.x;
        if (idx < 393216) {
            int n = idx / 768, k = idx - n * 768;
            t1[idx] = __float2half(z1[(long long)k * 512 + n]);
        } else if (idx < 524288) {
            int i2 = idx - 393216;
            int n = i2 / 512, k = i2 - n * 512;
            t2[i2] = __float2half(z2[(long long)k * 256 + n]);
        } else {
            int i3 = idx - 524288;
            int n = i3 / 256, k = i3 - n * 256;
            t3[i3] = __float2half(z3[(long long)k * 128 + n]);
        }
    } else {
        int tid2 = (blockIdx.x - 2176) * 256 + threadIdx.x;
        int w = tid2 >> 5, lane = tid2 & 31;
        if (w >= 897) return;
        const float *z, *r; int fi, fo, off, k;
        if (w < 512)      { z = z1; r = b1; fi = 768; fo = 512; off = 0;   k = w; }
        else if (w < 768) { z = z2; r = b2; fi = 512; fo = 256; off = 512; k = w - 512; }
        else if (w < 896) { z = z3; r = b3; fi = 256; fo = 128; off = 768; k = w - 768; }
        else              { z = z4; r = b4; fi = 128; fo = 1;   off = 896; k = 0; }
        float s = 0.f;
        for (int i = lane; i < fi; i += 32) {
            float v = z[(long long)i * fo + k];
            s = fmaf(v, v, s);
        }
#pragma unroll
        for (int o = 16; o; o >>= 1) s += __shfl_xor_sync(0xffffffffu, s, o);
        if (lane == 0) {
            float zn = fmaxf(sqrtf(s), 1e-15f);
            float t = 2.f * sqrtf(CC) * r[k];
            float e = __expf(t);
            float ei = __fdividef(1.f, e);
            g_zn2[off + k] = 2.f * zn;
            g_czn[off + k] = 0.5f * (e + ei) / zn;
            g_shv[off + k] = 0.5f * (e - ei);
        }
    }
}

// lam0 + fac=1/ASCALE + ASCALE*x -> fp16
__global__ void lam0_kernel(const float* __restrict__ x)
{
    int gid = blockIdx.x * blockDim.x + threadIdx.x;
    int row = gid >> 5, lane = gid & 31;
    const float4* xr = (const float4*)(x + (long long)row * 768);
    float s = 0.f;
#pragma unroll
    for (int p = 0; p < 6; p++) {
        int e4 = lane + 32 * p;
        float4 v = xr[e4];
        s += v.x * v.x + v.y * v.y + v.z * v.z + v.w * v.w;
        long long b = (long long)row * 768 + e4 * 4;
        __half2 h0; h0.x = __float2half(ASCALE * v.x); h0.y = __float2half(ASCALE * v.y);
        __half2 h1; h1.x = __float2half(ASCALE * v.z); h1.y = __float2half(ASCALE * v.w);
        ((__half2*)(g_x16 + b))[0] = h0;
        ((__half2*)(g_x16 + b))[1] = h1;
    }
#pragma unroll
    for (int o = 16; o; o >>= 1) s += __shfl_xor_sync(0xffffffffu, s, o);
    if (lane == 0) {
        g_lam[row] = __fdividef(2.f, 1.f - CC * s);
        g_fac[row] = 1.f / ASCALE;
    }
}

// ---------------- 3-stage pipelined fp16 GEMM, K-chunk 64, prefetch distance 2 ----------------
// SMEM stage: A 128x64 halfs @ pitch 144B (18432) | B same (18432) = 36864.
#define STAGE_SZ 36864
#define PITCH 144
template <int KDIM, int NTPREV>
__global__ __launch_bounds__(256, 2)
void gemm_mma(const __half* __restrict__ A, const __half* __restrict__ Bt,
              __half* __restrict__ Wh,
              int Nfull, int offTab, float2* __restrict__ psum,
              const float2* __restrict__ psumPrev)
{
    extern __shared__ char smem[];
    const uint32_t sbase = smem_u32(smem);
    constexpr int NB = KDIM / 64;

    int tid = threadIdx.x, wid = tid >> 5, lane = tid & 31;
    int warp_m = wid >> 1, warp_n = wid & 1;
    int gID = lane >> 2, tig = lane & 3;
    long long bm = (long long)blockIdx.y * 128;
    int bn = blockIdx.x * 128;
    int ntiles = gridDim.x;

    // cp.async: 1024 16B-vecs per matrix per stage; thread does 4 A + 4 B.
    uint32_t soA[4]; long long goA[4], goB[4];
#pragma unroll
    for (int j = 0; j < 4; j++) {
        int v = tid + 256 * j;
        int row = v >> 3, seg = v & 7;
        soA[j] = (uint32_t)(row * PITCH + seg * 16);
        goA[j] = (bm + row) * KDIM + seg * 8;
        goB[j] = (long long)(bn + row) * KDIM + seg * 8;
    }

    uint32_t a_off0 = (uint32_t)((warp_m * 32 + (lane & 15)) * PITCH + ((lane >> 4) * 8) * 2);
    uint32_t a_off1 = a_off0 + 16 * PITCH;
    uint32_t b_off = (uint32_t)((warp_n * 64 + (lane & 7) + ((lane >> 3) & 2) * 4) * PITCH
                                + (((lane >> 3) & 1) * 8) * 2);

    float acc[2][8][4];
#pragma unroll
    for (int m = 0; m < 2; m++)
#pragma unroll
        for (int n = 0; n < 8; n++)
#pragma unroll
            for (int q = 0; q < 4; q++) acc[m][n][q] = 0.f;

    auto issue = [&](int i) {
        uint32_t st = sbase + (i % 3) * STAGE_SZ;
        int k0 = i * 64;
#pragma unroll
        for (int j = 0; j < 4; j++) {
            CP16(st + soA[j],         A + goA[j] + k0);
            CP16(st + 18432 + soA[j], Bt + goB[j] + k0);
        }
    };

    // prefetch distance 2 (3 buffers -> max 2 stages in flight beyond current)
    issue(0); CP_COMMIT();
    if (NB > 1) { issue(1); CP_COMMIT(); }

    for (int i = 0; i < NB; i++) {
        if (i + 1 < NB) asm volatile("cp.async.wait_group 1;" ::: "memory");
        else            asm volatile("cp.async.wait_group 0;" ::: "memory");
        __syncthreads();
        // buffer (i+2)%3 == (i-1)%3 was fully consumed in iteration i-1 (trailing sync)
        if (i + 2 < NB) { issue(i + 2); CP_COMMIT(); }

        uint32_t st = sbase + (i % 3) * STAGE_SZ;
        uint32_t sA = st, sB = st + 18432;

#pragma unroll
        for (int ks = 0; ks < 64; ks += 16) {
            // batched fragment loads: one exposed LDS latency per slice
            uint32_t ah[2][4], bh[4][4];
            ldm_x4(ah[0], sA + a_off0 + ks * 2);
            ldm_x4(ah[1], sA + a_off1 + ks * 2);
#pragma unroll
            for (int n2 = 0; n2 < 4; n2++)
                ldm_x4(bh[n2], sB + b_off + (uint32_t)(n2 * 16 * PITCH) + ks * 2);
#pragma unroll
            for (int n2 = 0; n2 < 4; n2++) {
#pragma unroll
                for (int g = 0; g < 2; g++) {
#pragma unroll
                    for (int m = 0; m < 2; m++)
                        mma16816(acc[m][n2 * 2 + g], ah[m], &bh[n2][g * 2]);
                }
            }
        }
        __syncthreads();
    }

    // ---- row factors into SMEM ----
    float2* sred   = (float2*)smem;
    float2* rowdat = (float2*)(smem + 2048);
    if (tid < 128) {
        float2 fl;
        if (NTPREV == 0) {
            fl = make_float2(g_fac[bm + tid], g_lam[bm + tid]);
        } else {
            float s = 0.f, sp = 0.f;
#pragma unroll
            for (int t = 0; t < NTPREV; t++) {
                float2 v = psumPrev[(bm + tid) * NTPREV + t];
                s += v.x; sp += v.y;
            }
            fl = faclam(s, sp);
        }
        rowdat[tid] = fl;
    }
    __syncthreads();

    // ---- fused epilogue ----
    const float cs = sqrtf(CC);
    const float invcs = 1.f / cs;
    float s4[4] = {0.f, 0.f, 0.f, 0.f}, sp4[4] = {0.f, 0.f, 0.f, 0.f};
#pragma unroll
    for (int m = 0; m < 2; m++) {
        int lr = warp_m * 32 + m * 16 + gID;
        float2 flA = rowdat[lr], flB = rowdat[lr + 8];
        float a1A = cs * flA.y * flA.x, a2A = flA.y - 1.f;
        float a1B = cs * flB.y * flB.x, a2B = flB.y - 1.f;
#pragma unroll
        for (int n = 0; n < 8; n++) {
            int k = offTab + bn + warp_n * 64 + n * 8 + tig * 2;
            float czn0 = g_czn[k], czn1 = g_czn[k + 1];
            float shv0 = g_shv[k], shv1 = g_shv[k + 1];
            float zn0  = g_zn2[k], zn1  = g_zn2[k + 1];
            float w0 = wcalc(acc[m][n][0], a1A, a2A, czn0, shv0, zn0, invcs);
            float w1 = wcalc(acc[m][n][1], a1A, a2A, czn1, shv1, zn1, invcs);
            float w2 = wcalc(acc[m][n][2], a1B, a2B, czn0, shv0, zn0, invcs);
            float w3 = wcalc(acc[m][n][3], a1B, a2B, czn1, shv1, zn1, invcs);
            s4[m * 2]     += fmaf(w0, w0, w1 * w1);
            s4[m * 2 + 1] += fmaf(w2, w2, w3 * w3);
            float p0 = fmaxf(w0, 0.f), p1 = fmaxf(w1, 0.f);
            float p2 = fmaxf(w2, 0.f), p3 = fmaxf(w3, 0.f);
            sp4[m * 2]     += fmaf(p0, p0, p1 * p1);
            sp4[m * 2 + 1] += fmaf(p2, p2, p3 * p3);
            acc[m][n][0] = p0; acc[m][n][1] = p1; acc[m][n][2] = p2; acc[m][n][3] = p3;
        }
    }
#pragma unroll
    for (int q = 0; q < 4; q++) {
        s4[q]  += __shfl_xor_sync(0xffffffffu, s4[q], 1);
        s4[q]  += __shfl_xor_sync(0xffffffffu, s4[q], 2);
        sp4[q] += __shfl_xor_sync(0xffffffffu, sp4[q], 1);
        sp4[q] += __shfl_xor_sync(0xffffffffu, sp4[q], 2);
    }
    if (tig == 0) {
        int rl = warp_m * 32 + gID;
        sred[(rl)      * 2 + warp_n] = make_float2(s4[0], sp4[0]);
        sred[(rl + 8)  * 2 + warp_n] = make_float2(s4[1], sp4[1]);
        sred[(rl + 16) * 2 + warp_n] = make_float2(s4[2], sp4[2]);
        sred[(rl + 24) * 2 + warp_n] = make_float2(s4[3], sp4[3]);
    }
    __syncthreads();
    if (tid < 128) {
        float2 a = sred[tid * 2], b = sred[tid * 2 + 1];
        psum[(bm + tid) * ntiles + blockIdx.x] = make_float2(a.x + b.x, a.y + b.y);
    }

    // store ASCALE*relu(w) as fp16
#pragma unroll
    for (int m = 0; m < 2; m++) {
#pragma unroll
        for (int n = 0; n < 8; n++) {
            long long r = bm + warp_m * 32 + m * 16 + gID;
            int c = bn + warp_n * 64 + n * 8 + tig * 2;
            __half2 hi0, hi1;
            hi0.x = __float2half(ASCALE * acc[m][n][0]);
            hi0.y = __float2half(ASCALE * acc[m][n][1]);
            hi1.x = __float2half(ASCALE * acc[m][n][2]);
            hi1.y = __float2half(ASCALE * acc[m][n][3]);
            *(__half2*)(Wh + r * Nfull + c)       = hi0;
            *(__half2*)(Wh + (r + 8) * Nfull + c) = hi1;
        }
    }
}

// ---------------- final layer fo=1 ----------------
__global__ void final_kernel(const __half* __restrict__ hh,
                             const float* __restrict__ z4, const float2* __restrict__ psum3,
                             float* __restrict__ out)
{
    int gid = blockIdx.x * blockDim.x + threadIdx.x;
    int row = gid >> 5, lane = gid & 31;
    float s = 0.f;
#pragma unroll
    for (int p = 0; p < 4; p++) {
        int k = lane + 32 * p;
        s = fmaf(__half2float(hh[(long long)row * 128 + k]), z4[k], s);
    }
#pragma unroll
    for (int o = 16; o; o >>= 1) s += __shfl_xor_sync(0xffffffffu, s, o);
    if (lane == 0) {
        const float cs = sqrtf(CC);
        float2 v = psum3[row];
        float2 fl = faclam(v.x, v.y);
        float lam = fl.y;
        float se = s * fl.x;
        float u = fmaf(cs * lam * se, g_czn[896], -((lam - 1.f) * g_shv[896]));
        float t = __logf(u + sqrtf(fmaf(u, u, 1.f)));
        float p = __expf(g_zn2[896] * t);
        float w = (p - __fdividef(1.f, p)) * (0.5f / cs);
        out[row] = __fdividef(w, 1.f + sqrtf(fmaf(CC, w * w, 1.f)));
    }
}

// ---------------- launch ----------------
extern "C" void kernel_launch(void* const* d_in, const int* in_sizes, int n_in,
                              void* d_out, int out_size)
{
    const float* x  = (const float*)d_in[0];
    const float* z1 = (const float*)d_in[1];
    const float* b1 = (const float*)d_in[2];
    const float* z2 = (const float*)d_in[3];
    const float* b2 = (const float*)d_in[4];
    const float* z3 = (const float*)d_in[5];
    const float* b3 = (const float*)d_in[6];
    const float* z4 = (const float*)d_in[7];
    const float* b4 = (const float*)d_in[8];
    float* out = (float*)d_out;

    float2 *ppsA, *ppsB;
    cudaGetSymbolAddress((void**)&ppsA, g_psumA);
    cudaGetSymbolAddress((void**)&ppsB, g_psumB);
    __half *xh, *h1, *h2, *h3, *t1, *t2, *t3;
    cudaGetSymbolAddress((void**)&xh, g_x16);
    cudaGetSymbolAddress((void**)&h1, g_h1);
    cudaGetSymbolAddress((void**)&h2, g_h2);
    cudaGetSymbolAddress((void**)&h3, g_h3);
    cudaGetSymbolAddress((void**)&t1, g_zt1);
    cudaGetSymbolAddress((void**)&t2, g_zt2);
    cudaGetSymbolAddress((void**)&t3, g_zt3);

    const int SMEM_SZ = 3 * STAGE_SZ;  // 110592
    cudaFuncSetAttribute((const void*)gemm_mma<768, 0>, cudaFuncAttributeMaxDynamicSharedMemorySize, SMEM_SZ);
    cudaFuncSetAttribute((const void*)gemm_mma<512, 4>, cudaFuncAttributeMaxDynamicSharedMemorySize, SMEM_SZ);
    cudaFuncSetAttribute((const void*)gemm_mma<256, 2>, cudaFuncAttributeMaxDynamicSharedMemorySize, SMEM_SZ);

    const int warpBlocks = BATCH * 32 / 256;

    lam0_kernel<<<warpBlocks, 256>>>(x);
    wprep_kernel<<<2289, 256>>>(z1, b1, z2, b2, z3, b3, z4, b4, t1, t2, t3);

    // layer 1: (B,768) @ (768,512) -> psumA (4 tiles/row)
    gemm_mma<768, 0><<<dim3(4, BATCH / 128), 256, SMEM_SZ>>>(xh, t1, h1, 512, 0, ppsA, nullptr);
    // layer 2: (B,512) @ (512,256), factors from psumA -> psumB
    gemm_mma<512, 4><<<dim3(2, BATCH / 128), 256, SMEM_SZ>>>(h1, t2, h2, 256, 512, ppsB, ppsA);
    // layer 3: (B,256) @ (256,128), factors from psumB -> psumA
    gemm_mma<256, 2><<<dim3(1, BATCH / 128), 256, SMEM_SZ>>>(h2, t3, h3, 128, 768, ppsA, ppsB);
    // layer 4
    final_kernel<<<warpBlocks, 256>>>(h3, z4, ppsA, out);
}

// round 15
// speedup vs baseline: 5.1952x; 1.0034x over previous
#include <cuda_runtime.h>
#include <cuda_fp16.h>
#include <math.h>
#include <stdint.h>

#define CC 2.3026f
#define BATCH 65536
#define ASCALE 64.0f

// ---------------- static device scratch ----------------
__device__ __align__(256) __half g_x16[(size_t)BATCH * 768];
__device__ __align__(256) __half g_h1[(size_t)BATCH * 512];
__device__ __align__(256) __half g_h2[(size_t)BATCH * 256];
__device__ __align__(256) __half g_h3[(size_t)BATCH * 128];
__device__ float g_lam[BATCH];
__device__ float g_fac[BATCH];
__device__ float2 g_psumA[(size_t)BATCH * 4];
__device__ float2 g_psumB[(size_t)BATCH * 4];
__device__ float g_zn2[897], g_czn[897], g_shv[897];
__device__ __align__(256) __half g_zt1[512 * 768];
__device__ __align__(256) __half g_zt2[256 * 512];
__device__ __align__(256) __half g_zt3[128 * 256];

// ---------------- PTX helpers ----------------
__device__ __forceinline__ uint32_t smem_u32(const void* p) {
    uint32_t a;
    asm("{ .reg .u64 t; cvta.to.shared.u64 t, %1; cvt.u32.u64 %0, t; }" : "=r"(a) : "l"(p));
    return a;
}
__device__ __forceinline__ void mma16816(float* d, const uint32_t* a, const uint32_t* b) {
    asm volatile(
        "mma.sync.aligned.m16n8k16.row.col.f32.f16.f16.f32 "
        "{%0,%1,%2,%3}, {%4,%5,%6,%7}, {%8,%9}, {%0,%1,%2,%3};"
        : "+f"(d[0]), "+f"(d[1]), "+f"(d[2]), "+f"(d[3])
        : "r"(a[0]), "r"(a[1]), "r"(a[2]), "r"(a[3]), "r"(b[0]), "r"(b[1]));
}
__device__ __forceinline__ void ldm_x4(uint32_t* r, uint32_t saddr) {
    asm volatile("ldmatrix.sync.aligned.m8n8.x4.shared.b16 {%0,%1,%2,%3}, [%4];"
        : "=r"(r[0]), "=r"(r[1]), "=r"(r[2]), "=r"(r[3]) : "r"(saddr));
}
#define CP16(sa, gp) asm volatile("cp.async.cg.shared.global [%0], [%1], 16;" :: "r"(sa), "l"(gp))
#define CP_COMMIT()  asm volatile("cp.async.commit_group;" ::: "memory")

// w = sinh(zn2 * asinh(u)) / cs
__device__ __forceinline__ float wcalc(float mm, float a1, float a2,
                                       float czn, float shv, float zn2, float invcs)
{
    float u = fmaf(a1 * mm, czn, -(a2 * shv));
    float t = __logf(u + sqrtf(fmaf(u, u, 1.f)));
    float p = __expf(zn2 * t);
    return (p - __fdividef(1.f, p)) * (0.5f * invcs);
}

// (fac, lam) from per-row sums
__device__ __forceinline__ float2 faclam(float s, float sp)
{
    const float cs = sqrtf(CC);
    float inv = __fdividef(1.f, 1.f + sqrtf(fmaf(CC, s, 1.f)));
    float n  = fmaxf(sqrtf(s) * inv, 1e-15f);
    float cn = fminf(cs * n, 1.f - 1e-7f);
    float a  = __fdividef(0.5f * __logf(__fdividef(1.f + cn, 1.f - cn)), cs * n);
    float vn = fmaxf(a * inv * sqrtf(sp), 1e-15f);
    float e  = __expf(2.f * cs * vn);
    float th = __fdividef(e - 1.f, e + 1.f);
    float fc = __fdividef(th, cs * vn) * a;
    return make_float2(fc * inv * (1.f / ASCALE), 0.5f * (e + 2.f + __fdividef(1.f, e)));
}

// ---------------- merged prep: lam0/x-convert + weight transpose + column tables ----------------
// blocks [0,8192): lam0 (warp per row); [8192,10368): tsplit; [10368,10481): tables
__global__ void prep_all(const float* __restrict__ x,
                         const float* __restrict__ z1, const float* __restrict__ b1,
                         const float* __restrict__ z2, const float* __restrict__ b2,
                         const float* __restrict__ z3, const float* __restrict__ b3,
                         const float* __restrict__ z4, const float* __restrict__ b4,
                         __half* __restrict__ t1, __half* __restrict__ t2, __half* __restrict__ t3)
{
    if (blockIdx.x < 8192) {
        int gid = blockIdx.x * 256 + threadIdx.x;
        int row = gid >> 5, lane = gid & 31;
        const float4* xr = (const float4*)(x + (long long)row * 768);
        float s = 0.f;
#pragma unroll
        for (int p = 0; p < 6; p++) {
            int e4 = lane + 32 * p;
            float4 v = xr[e4];
            s += v.x * v.x + v.y * v.y + v.z * v.z + v.w * v.w;
            long long b = (long long)row * 768 + e4 * 4;
            __half2 h0; h0.x = __float2half(ASCALE * v.x); h0.y = __float2half(ASCALE * v.y);
            __half2 h1; h1.x = __float2half(ASCALE * v.z); h1.y = __float2half(ASCALE * v.w);
            ((__half2*)(g_x16 + b))[0] = h0;
            ((__half2*)(g_x16 + b))[1] = h1;
        }
#pragma unroll
        for (int o = 16; o; o >>= 1) s += __shfl_xor_sync(0xffffffffu, s, o);
        if (lane == 0) {
            g_lam[row] = __fdividef(2.f, 1.f - CC * s);
            g_fac[row] = 1.f / ASCALE;
        }
    } else if (blockIdx.x < 10368) {
        int idx = (blockIdx.x - 8192) * 256 + threadIdx.x;
        if (idx < 393216) {
            int n = idx / 768, k = idx - n * 768;
            t1[idx] = __float2half(z1[(long long)k * 512 + n]);
        } else if (idx < 524288) {
            int i2 = idx - 393216;
            int n = i2 / 512, k = i2 - n * 512;
            t2[i2] = __float2half(z2[(long long)k * 256 + n]);
        } else {
            int i3 = idx - 524288;
            int n = i3 / 256, k = i3 - n * 256;
            t3[i3] = __float2half(z3[(long long)k * 128 + n]);
        }
    } else {
        int tid2 = (blockIdx.x - 10368) * 256 + threadIdx.x;
        int w = tid2 >> 5, lane = tid2 & 31;
        if (w >= 897) return;
        const float *z, *r; int fi, fo, off, k;
        if (w < 512)      { z = z1; r = b1; fi = 768; fo = 512; off = 0;   k = w; }
        else if (w < 768) { z = z2; r = b2; fi = 512; fo = 256; off = 512; k = w - 512; }
        else if (w < 896) { z = z3; r = b3; fi = 256; fo = 128; off = 768; k = w - 768; }
        else              { z = z4; r = b4; fi = 128; fo = 1;   off = 896; k = 0; }
        float s = 0.f;
        for (int i = lane; i < fi; i += 32) {
            float v = z[(long long)i * fo + k];
            s = fmaf(v, v, s);
        }
#pragma unroll
        for (int o = 16; o; o >>= 1) s += __shfl_xor_sync(0xffffffffu, s, o);
        if (lane == 0) {
            float zn = fmaxf(sqrtf(s), 1e-15f);
            float t = 2.f * sqrtf(CC) * r[k];
            float e = __expf(t);
            float ei = __fdividef(1.f, e);
            g_zn2[off + k] = 2.f * zn;
            g_czn[off + k] = 0.5f * (e + ei) / zn;
            g_shv[off + k] = 0.5f * (e - ei);
        }
    }
}

// ---------------- 3-stage pipelined fp16 GEMM, K-chunk 64, one barrier per chunk ----------------
#define PITCH 144
template <int KDIM, int NTPREV, int MTILE>
__global__ __launch_bounds__(256, 2)
void gemm_mma(const __half* __restrict__ A, const __half* __restrict__ Bt,
              __half* __restrict__ Wh,
              int Nfull, int offTab, float2* __restrict__ psum,
              const float2* __restrict__ psumPrev)
{
    extern __shared__ char smem[];
    const uint32_t sbase = smem_u32(smem);
    constexpr int NB = KDIM / 64;
    constexpr int MFRAG = MTILE / 64;                 // 2 (M128) or 1 (M64)
    constexpr int A_BYTES = MTILE * PITCH;
    constexpr int STAGE = A_BYTES + 128 * PITCH;
    constexpr int AV = MTILE * 8 / 256;               // A 16B-vecs per thread

    int tid = threadIdx.x, wid = tid >> 5, lane = tid & 31;
    int warp_m = wid >> 1, warp_n = wid & 1;
    int gID = lane >> 2, tig = lane & 3;
    long long bm = (long long)blockIdx.y * MTILE;
    int bn = blockIdx.x * 128;
    int ntiles = gridDim.x;

    uint32_t soA[AV]; long long goA[AV];
#pragma unroll
    for (int j = 0; j < AV; j++) {
        int v = tid + 256 * j;
        int row = v >> 3, seg = v & 7;
        soA[j] = (uint32_t)(row * PITCH + seg * 16);
        goA[j] = (bm + row) * KDIM + seg * 8;
    }
    uint32_t soB[4]; long long goB[4];
#pragma unroll
    for (int j = 0; j < 4; j++) {
        int v = tid + 256 * j;
        int row = v >> 3, seg = v & 7;
        soB[j] = (uint32_t)(row * PITCH + seg * 16);
        goB[j] = (long long)(bn + row) * KDIM + seg * 8;
    }

    uint32_t a_off[MFRAG];
#pragma unroll
    for (int m = 0; m < MFRAG; m++)
        a_off[m] = (uint32_t)((warp_m * 16 * MFRAG + m * 16 + (lane & 15)) * PITCH
                              + ((lane >> 4) * 8) * 2);
    uint32_t b_off = (uint32_t)((warp_n * 64 + (lane & 7) + ((lane >> 3) & 2) * 4) * PITCH
                                + (((lane >> 3) & 1) * 8) * 2);

    float acc[MFRAG][8][4];
#pragma unroll
    for (int m = 0; m < MFRAG; m++)
#pragma unroll
        for (int n = 0; n < 8; n++)
#pragma unroll
            for (int q = 0; q < 4; q++) acc[m][n][q] = 0.f;

    auto issue = [&](int i) {
        uint32_t st = sbase + (i % 3) * STAGE;
        int k0 = i * 64;
#pragma unroll
        for (int j = 0; j < AV; j++) CP16(st + soA[j], A + goA[j] + k0);
#pragma unroll
        for (int j = 0; j < 4; j++)  CP16(st + A_BYTES + soB[j], Bt + goB[j] + k0);
    };

    issue(0); CP_COMMIT();
    if (NB > 1) { issue(1); CP_COMMIT(); }

    for (int i = 0; i < NB; i++) {
        if (i + 1 < NB) asm volatile("cp.async.wait_group 1;" ::: "memory");
        else            asm volatile("cp.async.wait_group 0;" ::: "memory");
        __syncthreads();   // orders: stage i visible to all; all warps done with iter i-1
        if (i + 2 < NB) { issue(i + 2); CP_COMMIT(); }

        uint32_t st = sbase + (i % 3) * STAGE;
        uint32_t sA = st, sB = st + A_BYTES;

#pragma unroll
        for (int ks = 0; ks < 64; ks += 16) {
            uint32_t ah[MFRAG][4], bh[4][4];
#pragma unroll
            for (int m = 0; m < MFRAG; m++) ldm_x4(ah[m], sA + a_off[m] + ks * 2);
#pragma unroll
            for (int n2 = 0; n2 < 4; n2++)
                ldm_x4(bh[n2], sB + b_off + (uint32_t)(n2 * 16 * PITCH) + ks * 2);
#pragma unroll
            for (int n2 = 0; n2 < 4; n2++) {
#pragma unroll
                for (int g = 0; g < 2; g++) {
#pragma unroll
                    for (int m = 0; m < MFRAG; m++)
                        mma16816(acc[m][n2 * 2 + g], ah[m], &bh[n2][g * 2]);
                }
            }
        }
    }
    __syncthreads();   // all warps past mainloop before smem reuse (sred/rowdat alias stages)

    // ---- row factors into SMEM ----
    float2* sred   = (float2*)smem;
    float2* rowdat = (float2*)(smem + 4096);
    if (tid < MTILE) {
        float2 fl;
        if (NTPREV == 0) {
            fl = make_float2(g_fac[bm + tid], g_lam[bm + tid]);
        } else {
            float s = 0.f, sp = 0.f;
#pragma unroll
            for (int t = 0; t < NTPREV; t++) {
                float2 v = psumPrev[(bm + tid) * NTPREV + t];
                s += v.x; sp += v.y;
            }
            fl = faclam(s, sp);
        }
        rowdat[tid] = fl;
    }
    __syncthreads();

    // ---- fused epilogue ----
    const float cs = sqrtf(CC);
    const float invcs = 1.f / cs;
    float s4[2 * MFRAG], sp4[2 * MFRAG];
#pragma unroll
    for (int q = 0; q < 2 * MFRAG; q++) { s4[q] = 0.f; sp4[q] = 0.f; }
#pragma unroll
    for (int m = 0; m < MFRAG; m++) {
        int lr = warp_m * 16 * MFRAG + m * 16 + gID;
        float2 flA = rowdat[lr], flB = rowdat[lr + 8];
        float a1A = cs * flA.y * flA.x, a2A = flA.y - 1.f;
        float a1B = cs * flB.y * flB.x, a2B = flB.y - 1.f;
#pragma unroll
        for (int n = 0; n < 8; n++) {
            int k = offTab + bn + warp_n * 64 + n * 8 + tig * 2;
            float czn0 = g_czn[k], czn1 = g_czn[k + 1];
            float shv0 = g_shv[k], shv1 = g_shv[k + 1];
            float zn0  = g_zn2[k], zn1  = g_zn2[k + 1];
            float w0 = wcalc(acc[m][n][0], a1A, a2A, czn0, shv0, zn0, invcs);
            float w1 = wcalc(acc[m][n][1], a1A, a2A, czn1, shv1, zn1, invcs);
            float w2 = wcalc(acc[m][n][2], a1B, a2B, czn0, shv0, zn0, invcs);
            float w3 = wcalc(acc[m][n][3], a1B, a2B, czn1, shv1, zn1, invcs);
            s4[m * 2]     += fmaf(w0, w0, w1 * w1);
            s4[m * 2 + 1] += fmaf(w2, w2, w3 * w3);
            float p0 = fmaxf(w0, 0.f), p1 = fmaxf(w1, 0.f);
            float p2 = fmaxf(w2, 0.f), p3 = fmaxf(w3, 0.f);
            sp4[m * 2]     += fmaf(p0, p0, p1 * p1);
            sp4[m * 2 + 1] += fmaf(p2, p2, p3 * p3);
            acc[m][n][0] = p0; acc[m][n][1] = p1; acc[m][n][2] = p2; acc[m][n][3] = p3;
        }
    }
#pragma unroll
    for (int q = 0; q < 2 * MFRAG; q++) {
        s4[q]  += __shfl_xor_sync(0xffffffffu, s4[q], 1);
        s4[q]  += __shfl_xor_sync(0xffffffffu, s4[q], 2);
        sp4[q] += __shfl_xor_sync(0xffffffffu, sp4[q], 1);
        sp4[q] += __shfl_xor_sync(0xffffffffu, sp4[q], 2);
    }
    if (tig == 0) {
#pragma unroll
        for (int m = 0; m < MFRAG; m++) {
            int rl = warp_m * 16 * MFRAG + m * 16 + gID;
            sred[(rl)     * 2 + warp_n] = make_float2(s4[m * 2],     sp4[m * 2]);
            sred[(rl + 8) * 2 + warp_n] = make_float2(s4[m * 2 + 1], sp4[m * 2 + 1]);
        }
    }
    __syncthreads();
    if (tid < MTILE) {
        float2 a = sred[tid * 2], b = sred[tid * 2 + 1];
        psum[(bm + tid) * ntiles + blockIdx.x] = make_float2(a.x + b.x, a.y + b.y);
    }

    // store ASCALE*relu(w) as fp16
#pragma unroll
    for (int m = 0; m < MFRAG; m++) {
#pragma unroll
        for (int n = 0; n < 8; n++) {
            long long r = bm + warp_m * 16 * MFRAG + m * 16 + gID;
            int c = bn + warp_n * 64 + n * 8 + tig * 2;
            __half2 hi0, hi1;
            hi0.x = __float2half(ASCALE * acc[m][n][0]);
            hi0.y = __float2half(ASCALE * acc[m][n][1]);
            hi1.x = __float2half(ASCALE * acc[m][n][2]);
            hi1.y = __float2half(ASCALE * acc[m][n][3]);
            *(__half2*)(Wh + r * Nfull + c)       = hi0;
            *(__half2*)(Wh + (r + 8) * Nfull + c) = hi1;
        }
    }
}

// ---------------- final layer fo=1 ----------------
__global__ void final_kernel(const __half* __restrict__ hh,
                             const float* __restrict__ z4, const float2* __restrict__ psum3,
                             float* __restrict__ out)
{
    int gid = blockIdx.x * blockDim.x + threadIdx.x;
    int row = gid >> 5, lane = gid & 31;
    float s = 0.f;
#pragma unroll
    for (int p = 0; p < 4; p++) {
        int k = lane + 32 * p;
        s = fmaf(__half2float(hh[(long long)row * 128 + k]), z4[k], s);
    }
#pragma unroll
    for (int o = 16; o; o >>= 1) s += __shfl_xor_sync(0xffffffffu, s, o);
    if (lane == 0) {
        const float cs = sqrtf(CC);
        float2 v = psum3[row];
        float2 fl = faclam(v.x, v.y);
        float lam = fl.y;
        float se = s * fl.x;
        float u = fmaf(cs * lam * se, g_czn[896], -((lam - 1.f) * g_shv[896]));
        float t = __logf(u + sqrtf(fmaf(u, u, 1.f)));
        float p = __expf(g_zn2[896] * t);
        float w = (p - __fdividef(1.f, p)) * (0.5f / cs);
        out[row] = __fdividef(w, 1.f + sqrtf(fmaf(CC, w * w, 1.f)));
    }
}

// ---------------- launch ----------------
extern "C" void kernel_launch(void* const* d_in, const int* in_sizes, int n_in,
                              void* d_out, int out_size)
{
    const float* x  = (const float*)d_in[0];
    const float* z1 = (const float*)d_in[1];
    const float* b1 = (const float*)d_in[2];
    const float* z2 = (const float*)d_in[3];
    const float* b2 = (const float*)d_in[4];
    const float* z3 = (const float*)d_in[5];
    const float* b3 = (const float*)d_in[6];
    const float* z4 = (const float*)d_in[7];
    const float* b4 = (const float*)d_in[8];
    float* out = (float*)d_out;

    float2 *ppsA, *ppsB;
    cudaGetSymbolAddress((void**)&ppsA, g_psumA);
    cudaGetSymbolAddress((void**)&ppsB, g_psumB);
    __half *xh, *h1, *h2, *h3, *t1, *t2, *t3;
    cudaGetSymbolAddress((void**)&xh, g_x16);
    cudaGetSymbolAddress((void**)&h1, g_h1);
    cudaGetSymbolAddress((void**)&h2, g_h2);
    cudaGetSymbolAddress((void**)&h3, g_h3);
    cudaGetSymbolAddress((void**)&t1, g_zt1);
    cudaGetSymbolAddress((void**)&t2, g_zt2);
    cudaGetSymbolAddress((void**)&t3, g_zt3);

    const int SM128 = 3 * (128 * PITCH + 128 * PITCH);   // 110592
    const int SM64  = 3 * (64 * PITCH + 128 * PITCH);    // 82944
    cudaFuncSetAttribute((const void*)gemm_mma<768, 0, 128>, cudaFuncAttributeMaxDynamicSharedMemorySize, SM128);
    cudaFuncSetAttribute((const void*)gemm_mma<512, 4, 128>, cudaFuncAttributeMaxDynamicSharedMemorySize, SM128);
    cudaFuncSetAttribute((const void*)gemm_mma<256, 2, 64>,  cudaFuncAttributeMaxDynamicSharedMemorySize, SM64);

    // merged prep: lam0 (8192) + tsplit (2176) + tables (113)
    prep_all<<<10481, 256>>>(x, z1, b1, z2, b2, z3, b3, z4, b4, t1, t2, t3);

    // layer 1: (B,768) @ (768,512) -> psumA (4 tiles/row)
    gemm_mma<768, 0, 128><<<dim3(4, BATCH / 128), 256, SM128>>>(xh, t1, h1, 512, 0, ppsA, nullptr);
    // layer 2: (B,512) @ (512,256), factors from psumA -> psumB
    gemm_mma<512, 4, 128><<<dim3(2, BATCH / 128), 256, SM128>>>(h1, t2, h2, 256, 512, ppsB, ppsA);
    // layer 3: (B,256) @ (256,128), M-tile 64, factors from psumB -> psumA
    gemm_mma<256, 2, 64><<<dim3(1, BATCH / 64), 256, SM64>>>(h2, t3, h3, 128, 768, ppsA, ppsB);
    // layer 4
    final_kernel<<<BATCH * 32 / 256, 256>>>(h3, z4, ppsA, out);
}

// round 16
// speedup vs baseline: 5.4465x; 1.0484x over previous
#include <cuda_runtime.h>
#include <cuda_fp16.h>
#include <math.h>
#include <stdint.h>

#define CC 2.3026f
#define BATCH 65536
#define ASCALE 64.0f

// ---------------- static device scratch ----------------
__device__ __align__(256) __half g_x16[(size_t)BATCH * 768];
__device__ __align__(256) __half g_h1[(size_t)BATCH * 512];
__device__ __align__(256) __half g_h2[(size_t)BATCH * 256];
__device__ float g_lam[BATCH];
__device__ float g_fac[BATCH];
__device__ float2 g_psumA[(size_t)BATCH * 4];
__device__ float2 g_psumB[(size_t)BATCH * 4];
__device__ float g_zn2[897], g_czn[897], g_shv[897];
__device__ __align__(256) __half g_zt1[512 * 768];
__device__ __align__(256) __half g_zt2[256 * 512];
__device__ __align__(256) __half g_zt3[128 * 256];

// ---------------- PTX helpers ----------------
__device__ __forceinline__ uint32_t smem_u32(const void* p) {
    uint32_t a;
    asm("{ .reg .u64 t; cvta.to.shared.u64 t, %1; cvt.u32.u64 %0, t; }" : "=r"(a) : "l"(p));
    return a;
}
__device__ __forceinline__ void mma16816(float* d, const uint32_t* a, const uint32_t* b) {
    asm volatile(
        "mma.sync.aligned.m16n8k16.row.col.f32.f16.f16.f32 "
        "{%0,%1,%2,%3}, {%4,%5,%6,%7}, {%8,%9}, {%0,%1,%2,%3};"
        : "+f"(d[0]), "+f"(d[1]), "+f"(d[2]), "+f"(d[3])
        : "r"(a[0]), "r"(a[1]), "r"(a[2]), "r"(a[3]), "r"(b[0]), "r"(b[1]));
}
__device__ __forceinline__ void ldm_x4(uint32_t* r, uint32_t saddr) {
    asm volatile("ldmatrix.sync.aligned.m8n8.x4.shared.b16 {%0,%1,%2,%3}, [%4];"
        : "=r"(r[0]), "=r"(r[1]), "=r"(r[2]), "=r"(r[3]) : "r"(saddr));
}
#define CP16(sa, gp) asm volatile("cp.async.cg.shared.global [%0], [%1], 16;" :: "r"(sa), "l"(gp))
#define CP_COMMIT()  asm volatile("cp.async.commit_group;" ::: "memory")

// w = sinh(zn2 * asinh(u)) / cs
__device__ __forceinline__ float wcalc(float mm, float a1, float a2,
                                       float czn, float shv, float zn2, float invcs)
{
    float u = fmaf(a1 * mm, czn, -(a2 * shv));
    float t = __logf(u + sqrtf(fmaf(u, u, 1.f)));
    float p = __expf(zn2 * t);
    return (p - __fdividef(1.f, p)) * (0.5f * invcs);
}

// (fac, lam) from per-row sums
__device__ __forceinline__ float2 faclam(float s, float sp)
{
    const float cs = sqrtf(CC);
    float inv = __fdividef(1.f, 1.f + sqrtf(fmaf(CC, s, 1.f)));
    float n  = fmaxf(sqrtf(s) * inv, 1e-15f);
    float cn = fminf(cs * n, 1.f - 1e-7f);
    float a  = __fdividef(0.5f * __logf(__fdividef(1.f + cn, 1.f - cn)), cs * n);
    float vn = fmaxf(a * inv * sqrtf(sp), 1e-15f);
    float e  = __expf(2.f * cs * vn);
    float th = __fdividef(e - 1.f, e + 1.f);
    float fc = __fdividef(th, cs * vn) * a;
    return make_float2(fc * inv * (1.f / ASCALE), 0.5f * (e + 2.f + __fdividef(1.f, e)));
}

// ---------------- merged prep: lam0/x-convert + weight transpose + column tables ----------------
__global__ void prep_all(const float* __restrict__ x,
                         const float* __restrict__ z1, const float* __restrict__ b1,
                         const float* __restrict__ z2, const float* __restrict__ b2,
                         const float* __restrict__ z3, const float* __restrict__ b3,
                         const float* __restrict__ z4, const float* __restrict__ b4,
                         __half* __restrict__ t1, __half* __restrict__ t2, __half* __restrict__ t3)
{
    if (blockIdx.x < 8192) {
        int gid = blockIdx.x * 256 + threadIdx.x;
        int row = gid >> 5, lane = gid & 31;
        const float4* xr = (const float4*)(x + (long long)row * 768);
        float s = 0.f;
#pragma unroll
        for (int p = 0; p < 6; p++) {
            int e4 = lane + 32 * p;
            float4 v = xr[e4];
            s += v.x * v.x + v.y * v.y + v.z * v.z + v.w * v.w;
            long long b = (long long)row * 768 + e4 * 4;
            __half2 h0; h0.x = __float2half(ASCALE * v.x); h0.y = __float2half(ASCALE * v.y);
            __half2 h1; h1.x = __float2half(ASCALE * v.z); h1.y = __float2half(ASCALE * v.w);
            ((__half2*)(g_x16 + b))[0] = h0;
            ((__half2*)(g_x16 + b))[1] = h1;
        }
#pragma unroll
        for (int o = 16; o; o >>= 1) s += __shfl_xor_sync(0xffffffffu, s, o);
        if (lane == 0) {
            g_lam[row] = __fdividef(2.f, 1.f - CC * s);
            g_fac[row] = 1.f / ASCALE;
        }
    } else if (blockIdx.x < 10368) {
        int idx = (blockIdx.x - 8192) * 256 + threadIdx.x;
        if (idx < 393216) {
            int n = idx / 768, k = idx - n * 768;
            t1[idx] = __float2half(z1[(long long)k * 512 + n]);
        } else if (idx < 524288) {
            int i2 = idx - 393216;
            int n = i2 / 512, k = i2 - n * 512;
            t2[i2] = __float2half(z2[(long long)k * 256 + n]);
        } else {
            int i3 = idx - 524288;
            int n = i3 / 256, k = i3 - n * 256;
            t3[i3] = __float2half(z3[(long long)k * 128 + n]);
        }
    } else {
        int tid2 = (blockIdx.x - 10368) * 256 + threadIdx.x;
        int w = tid2 >> 5, lane = tid2 & 31;
        if (w >= 897) return;
        const float *z, *r; int fi, fo, off, k;
        if (w < 512)      { z = z1; r = b1; fi = 768; fo = 512; off = 0;   k = w; }
        else if (w < 768) { z = z2; r = b2; fi = 512; fo = 256; off = 512; k = w - 512; }
        else if (w < 896) { z = z3; r = b3; fi = 256; fo = 128; off = 768; k = w - 768; }
        else              { z = z4; r = b4; fi = 128; fo = 1;   off = 896; k = 0; }
        float s = 0.f;
        for (int i = lane; i < fi; i += 32) {
            float v = z[(long long)i * fo + k];
            s = fmaf(v, v, s);
        }
#pragma unroll
        for (int o = 16; o; o >>= 1) s += __shfl_xor_sync(0xffffffffu, s, o);
        if (lane == 0) {
            float zn = fmaxf(sqrtf(s), 1e-15f);
            float t = 2.f * sqrtf(CC) * r[k];
            float e = __expf(t);
            float ei = __fdividef(1.f, e);
            g_zn2[off + k] = 2.f * zn;
            g_czn[off + k] = 0.5f * (e + ei) / zn;
            g_shv[off + k] = 0.5f * (e - ei);
        }
    }
}

// ---------------- 3-stage pipelined fp16 GEMM + fused epilogue (+ optional final layer) ----------------
#define PITCH 144
template <int KDIM, int NTPREV, int MTILE, bool FINAL>
__global__ __launch_bounds__(256, 2)
void gemm_mma(const __half* __restrict__ A, const __half* __restrict__ Bt,
              __half* __restrict__ Wh,
              int Nfull, int offTab, float2* __restrict__ psum,
              const float2* __restrict__ psumPrev,
              const float* __restrict__ z4g, float* __restrict__ outp)
{
    extern __shared__ char smem[];
    const uint32_t sbase = smem_u32(smem);
    constexpr int NB = KDIM / 64;
    constexpr int MFRAG = MTILE / 64;
    constexpr int A_BYTES = MTILE * PITCH;
    constexpr int AV = MTILE * 8 / 256;

    int tid = threadIdx.x, wid = tid >> 5, lane = tid & 31;
    int warp_m = wid >> 1, warp_n = wid & 1;
    int gID = lane >> 2, tig = lane & 3;
    long long bm = (long long)blockIdx.y * MTILE;
    int bn = blockIdx.x * 128;
    int ntiles = gridDim.x;

    uint32_t soA[AV]; long long goA[AV];
#pragma unroll
    for (int j = 0; j < AV; j++) {
        int v = tid + 256 * j;
        int row = v >> 3, seg = v & 7;
        soA[j] = (uint32_t)(row * PITCH + seg * 16);
        goA[j] = (bm + row) * KDIM + seg * 8;
    }
    uint32_t soB[4]; long long goB[4];
#pragma unroll
    for (int j = 0; j < 4; j++) {
        int v = tid + 256 * j;
        int row = v >> 3, seg = v & 7;
        soB[j] = (uint32_t)(row * PITCH + seg * 16);
        goB[j] = (long long)(bn + row) * KDIM + seg * 8;
    }

    uint32_t a_off[MFRAG];
#pragma unroll
    for (int m = 0; m < MFRAG; m++)
        a_off[m] = (uint32_t)((warp_m * 16 * MFRAG + m * 16 + (lane & 15)) * PITCH
                              + ((lane >> 4) * 8) * 2);
    uint32_t b_off = (uint32_t)((warp_n * 64 + (lane & 7) + ((lane >> 3) & 2) * 4) * PITCH
                                + (((lane >> 3) & 1) * 8) * 2);

    float acc[MFRAG][8][4];
#pragma unroll
    for (int m = 0; m < MFRAG; m++)
#pragma unroll
        for (int n = 0; n < 8; n++)
#pragma unroll
            for (int q = 0; q < 4; q++) acc[m][n][q] = 0.f;

    auto issue = [&](int i) {
        uint32_t st = sbase + (i % 3) * (A_BYTES + 128 * PITCH);
        int k0 = i * 64;
#pragma unroll
        for (int j = 0; j < AV; j++) CP16(st + soA[j], A + goA[j] + k0);
#pragma unroll
        for (int j = 0; j < 4; j++)  CP16(st + A_BYTES + soB[j], Bt + goB[j] + k0);
    };

    issue(0); CP_COMMIT();
    if (NB > 1) { issue(1); CP_COMMIT(); }

    for (int i = 0; i < NB; i++) {
        if (i + 1 < NB) asm volatile("cp.async.wait_group 1;" ::: "memory");
        else            asm volatile("cp.async.wait_group 0;" ::: "memory");
        __syncthreads();
        if (i + 2 < NB) { issue(i + 2); CP_COMMIT(); }

        uint32_t st = sbase + (i % 3) * (A_BYTES + 128 * PITCH);
        uint32_t sA = st, sB = st + A_BYTES;

#pragma unroll
        for (int ks = 0; ks < 64; ks += 16) {
            uint32_t ah[MFRAG][4], bh[4][4];
#pragma unroll
            for (int m = 0; m < MFRAG; m++) ldm_x4(ah[m], sA + a_off[m] + ks * 2);
#pragma unroll
            for (int n2 = 0; n2 < 4; n2++)
                ldm_x4(bh[n2], sB + b_off + (uint32_t)(n2 * 16 * PITCH) + ks * 2);
#pragma unroll
            for (int n2 = 0; n2 < 4; n2++) {
#pragma unroll
                for (int g = 0; g < 2; g++) {
#pragma unroll
                    for (int m = 0; m < MFRAG; m++)
                        mma16816(acc[m][n2 * 2 + g], ah[m], &bh[n2][g * 2]);
                }
            }
        }
    }
    __syncthreads();

    // ---- row factors into SMEM ----
    float2* sred   = (float2*)smem;
    float2* rowdat = (float2*)(smem + 4096);
    float*  dred   = (float*)(smem + 8192);
    if (tid < MTILE) {
        float2 fl;
        if (NTPREV == 0) {
            fl = make_float2(g_fac[bm + tid], g_lam[bm + tid]);
        } else {
            float s = 0.f, sp = 0.f;
#pragma unroll
            for (int t = 0; t < NTPREV; t++) {
                float2 v = psumPrev[(bm + tid) * NTPREV + t];
                s += v.x; sp += v.y;
            }
            fl = faclam(s, sp);
        }
        rowdat[tid] = fl;
    }
    __syncthreads();

    // ---- fused epilogue ----
    const float cs = sqrtf(CC);
    const float invcs = 1.f / cs;
    float s4[2 * MFRAG], sp4[2 * MFRAG], d4[2 * MFRAG];
#pragma unroll
    for (int q = 0; q < 2 * MFRAG; q++) { s4[q] = 0.f; sp4[q] = 0.f; d4[q] = 0.f; }
#pragma unroll
    for (int m = 0; m < MFRAG; m++) {
        int lr = warp_m * 16 * MFRAG + m * 16 + gID;
        float2 flA = rowdat[lr], flB = rowdat[lr + 8];
        float a1A = cs * flA.y * flA.x, a2A = flA.y - 1.f;
        float a1B = cs * flB.y * flB.x, a2B = flB.y - 1.f;
#pragma unroll
        for (int n = 0; n < 8; n++) {
            int kk = bn + warp_n * 64 + n * 8 + tig * 2;
            int k = offTab + kk;
            float czn0 = g_czn[k], czn1 = g_czn[k + 1];
            float shv0 = g_shv[k], shv1 = g_shv[k + 1];
            float zn0  = g_zn2[k], zn1  = g_zn2[k + 1];
            float w0 = wcalc(acc[m][n][0], a1A, a2A, czn0, shv0, zn0, invcs);
            float w1 = wcalc(acc[m][n][1], a1A, a2A, czn1, shv1, zn1, invcs);
            float w2 = wcalc(acc[m][n][2], a1B, a2B, czn0, shv0, zn0, invcs);
            float w3 = wcalc(acc[m][n][3], a1B, a2B, czn1, shv1, zn1, invcs);
            s4[m * 2]     += fmaf(w0, w0, w1 * w1);
            s4[m * 2 + 1] += fmaf(w2, w2, w3 * w3);
            float p0 = fmaxf(w0, 0.f), p1 = fmaxf(w1, 0.f);
            float p2 = fmaxf(w2, 0.f), p3 = fmaxf(w3, 0.f);
            sp4[m * 2]     += fmaf(p0, p0, p1 * p1);
            sp4[m * 2 + 1] += fmaf(p2, p2, p3 * p3);
            if (FINAL) {
                // quantize exactly as the h-store would, then dot with z4
                float q0 = __half2float(__float2half(ASCALE * p0));
                float q1 = __half2float(__float2half(ASCALE * p1));
                float q2 = __half2float(__float2half(ASCALE * p2));
                float q3 = __half2float(__float2half(ASCALE * p3));
                float z0 = z4g[kk], z1 = z4g[kk + 1];
                d4[m * 2]     += fmaf(q0, z0, q1 * z1);
                d4[m * 2 + 1] += fmaf(q2, z0, q3 * z1);
            } else {
                acc[m][n][0] = p0; acc[m][n][1] = p1;
                acc[m][n][2] = p2; acc[m][n][3] = p3;
            }
        }
    }
#pragma unroll
    for (int q = 0; q < 2 * MFRAG; q++) {
        s4[q]  += __shfl_xor_sync(0xffffffffu, s4[q], 1);
        s4[q]  += __shfl_xor_sync(0xffffffffu, s4[q], 2);
        sp4[q] += __shfl_xor_sync(0xffffffffu, sp4[q], 1);
        sp4[q] += __shfl_xor_sync(0xffffffffu, sp4[q], 2);
        if (FINAL) {
            d4[q] += __shfl_xor_sync(0xffffffffu, d4[q], 1);
            d4[q] += __shfl_xor_sync(0xffffffffu, d4[q], 2);
        }
    }
    if (tig == 0) {
#pragma unroll
        for (int m = 0; m < MFRAG; m++) {
            int rl = warp_m * 16 * MFRAG + m * 16 + gID;
            sred[(rl)     * 2 + warp_n] = make_float2(s4[m * 2],     sp4[m * 2]);
            sred[(rl + 8) * 2 + warp_n] = make_float2(s4[m * 2 + 1], sp4[m * 2 + 1]);
            if (FINAL) {
                dred[(rl)     * 2 + warp_n] = d4[m * 2];
                dred[(rl + 8) * 2 + warp_n] = d4[m * 2 + 1];
            }
        }
    }
    __syncthreads();
    if (FINAL) {
        if (tid < MTILE) {
            float2 a = sred[tid * 2], b = sred[tid * 2 + 1];
            float2 fl = faclam(a.x + b.x, a.y + b.y);
            float lam = fl.y;
            float se = (dred[tid * 2] + dred[tid * 2 + 1]) * fl.x;
            float u = fmaf(cs * lam * se, g_czn[896], -((lam - 1.f) * g_shv[896]));
            float t = __logf(u + sqrtf(fmaf(u, u, 1.f)));
            float p = __expf(g_zn2[896] * t);
            float w = (p - __fdividef(1.f, p)) * (0.5f * invcs);
            outp[bm + tid] = __fdividef(w, 1.f + sqrtf(fmaf(CC, w * w, 1.f)));
        }
        return;
    }
    if (tid < MTILE) {
        float2 a = sred[tid * 2], b = sred[tid * 2 + 1];
        psum[(bm + tid) * ntiles + blockIdx.x] = make_float2(a.x + b.x, a.y + b.y);
    }

    // store ASCALE*relu(w) as fp16
#pragma unroll
    for (int m = 0; m < MFRAG; m++) {
#pragma unroll
        for (int n = 0; n < 8; n++) {
            long long r = bm + warp_m * 16 * MFRAG + m * 16 + gID;
            int c = bn + warp_n * 64 + n * 8 + tig * 2;
            __half2 hi0, hi1;
            hi0.x = __float2half(ASCALE * acc[m][n][0]);
            hi0.y = __float2half(ASCALE * acc[m][n][1]);
            hi1.x = __float2half(ASCALE * acc[m][n][2]);
            hi1.y = __float2half(ASCALE * acc[m][n][3]);
            *(__half2*)(Wh + r * Nfull + c)       = hi0;
            *(__half2*)(Wh + (r + 8) * Nfull + c) = hi1;
        }
    }
}

// ---------------- launch ----------------
extern "C" void kernel_launch(void* const* d_in, const int* in_sizes, int n_in,
                              void* d_out, int out_size)
{
    const float* x  = (const float*)d_in[0];
    const float* z1 = (const float*)d_in[1];
    const float* b1 = (const float*)d_in[2];
    const float* z2 = (const float*)d_in[3];
    const float* b2 = (const float*)d_in[4];
    const float* z3 = (const float*)d_in[5];
    const float* b3 = (const float*)d_in[6];
    const float* z4 = (const float*)d_in[7];
    const float* b4 = (const float*)d_in[8];
    float* out = (float*)d_out;

    float2 *ppsA, *ppsB;
    cudaGetSymbolAddress((void**)&ppsA, g_psumA);
    cudaGetSymbolAddress((void**)&ppsB, g_psumB);
    __half *xh, *h1, *h2, *t1, *t2, *t3;
    cudaGetSymbolAddress((void**)&xh, g_x16);
    cudaGetSymbolAddress((void**)&h1, g_h1);
    cudaGetSymbolAddress((void**)&h2, g_h2);
    cudaGetSymbolAddress((void**)&t1, g_zt1);
    cudaGetSymbolAddress((void**)&t2, g_zt2);
    cudaGetSymbolAddress((void**)&t3, g_zt3);

    const int SM128 = 3 * (128 * PITCH + 128 * PITCH);   // 110592
    const int SM64  = 3 * (64 * PITCH + 128 * PITCH);    // 82944
    cudaFuncSetAttribute((const void*)gemm_mma<768, 0, 128, false>, cudaFuncAttributeMaxDynamicSharedMemorySize, SM128);
    cudaFuncSetAttribute((const void*)gemm_mma<512, 4, 128, false>, cudaFuncAttributeMaxDynamicSharedMemorySize, SM128);
    cudaFuncSetAttribute((const void*)gemm_mma<256, 2, 64, true>,   cudaFuncAttributeMaxDynamicSharedMemorySize, SM64);

    // merged prep: lam0 (8192) + tsplit (2176) + tables (113)
    prep_all<<<10481, 256>>>(x, z1, b1, z2, b2, z3, b3, z4, b4, t1, t2, t3);

    // layer 1: (B,768) @ (768,512) -> psumA (4 tiles/row)
    gemm_mma<768, 0, 128, false><<<dim3(4, BATCH / 128), 256, SM128>>>(xh, t1, h1, 512, 0, ppsA, nullptr, nullptr, nullptr);
    // layer 2: (B,512) @ (512,256), factors from psumA -> psumB
    gemm_mma<512, 4, 128, false><<<dim3(2, BATCH / 128), 256, SM128>>>(h1, t2, h2, 256, 512, ppsB, ppsA, nullptr, nullptr);
    // layer 3+4 fused: (B,256) @ (256,128) + final dot + ball map -> out
    gemm_mma<256, 2, 64, true><<<dim3(1, BATCH / 64), 256, SM64>>>(h2, t3, nullptr, 128, 768, nullptr, ppsB, z4, out);
}

// round 17
// speedup vs baseline: 5.5972x; 1.0277x over previous
#include <cuda_runtime.h>
#include <cuda_fp16.h>
#include <math.h>
#include <stdint.h>

#define CC 2.3026f
#define BATCH 65536
#define ASCALE 64.0f

// ---------------- static device scratch ----------------
__device__ __align__(256) __half g_x16[(size_t)BATCH * 768];
__device__ __align__(256) __half g_h1[(size_t)BATCH * 512];
__device__ __align__(256) __half g_h2[(size_t)BATCH * 256];
__device__ float g_lam[BATCH];
__device__ float g_fac[BATCH];
__device__ float2 g_psumA[(size_t)BATCH * 4];
__device__ float2 g_psumB[(size_t)BATCH * 4];
__device__ float g_zdel[897], g_czn[897], g_shv[897];   // zdel = 2*||z||-2
__device__ __align__(256) __half g_zt1[512 * 768];
__device__ __align__(256) __half g_zt2[256 * 512];
__device__ __align__(256) __half g_zt3[128 * 256];

// ---------------- PTX helpers ----------------
__device__ __forceinline__ uint32_t smem_u32(const void* p) {
    uint32_t a;
    asm("{ .reg .u64 t; cvta.to.shared.u64 t, %1; cvt.u32.u64 %0, t; }" : "=r"(a) : "l"(p));
    return a;
}
__device__ __forceinline__ void mma16816(float* d, const uint32_t* a, const uint32_t* b) {
    asm volatile(
        "mma.sync.aligned.m16n8k16.row.col.f32.f16.f16.f32 "
        "{%0,%1,%2,%3}, {%4,%5,%6,%7}, {%8,%9}, {%0,%1,%2,%3};"
        : "+f"(d[0]), "+f"(d[1]), "+f"(d[2]), "+f"(d[3])
        : "r"(a[0]), "r"(a[1]), "r"(a[2]), "r"(a[3]), "r"(b[0]), "r"(b[1]));
}
__device__ __forceinline__ void ldm_x4(uint32_t* r, uint32_t saddr) {
    asm volatile("ldmatrix.sync.aligned.m8n8.x4.shared.b16 {%0,%1,%2,%3}, [%4];"
        : "=r"(r[0]), "=r"(r[1]), "=r"(r[2]), "=r"(r[3]) : "r"(saddr));
}
#define CP16(sa, gp) asm volatile("cp.async.cg.shared.global [%0], [%1], 16;" :: "r"(sa), "l"(gp))
#define CP_COMMIT()  asm volatile("cp.async.commit_group;" ::: "memory")

// w = sinh((2+zdel)*asinh(u))/cs via addition theorem + small-angle Taylor:
//   y = asinh(u); sinh(2y)=2u*sqrt(u^2+1); cosh(2y)=1+2u^2; |zdel*y| small.
// MUFU: sqrt + log only (was sqrt+log+exp+rcp).
__device__ __forceinline__ float wcalc_u(float u, float zdel, float invcs)
{
    float sq  = sqrtf(fmaf(u, u, 1.f));
    float y   = __logf(u + sq);
    float dy  = zdel * y;
    float dy2 = dy * dy;
    float ch  = fmaf(dy2, fmaf(dy2, (1.f / 24.f), 0.5f), 1.f);   // cosh(dy)
    float sh  = dy * fmaf(dy2, (1.f / 6.f), 1.f);                // sinh(dy)
    float sh2y = 2.f * u * sq;
    float ch2y = fmaf(2.f * u, u, 1.f);
    return fmaf(sh2y, ch, ch2y * sh) * invcs;
}
__device__ __forceinline__ float wcalc(float mm, float a1, float a2,
                                       float czn, float shv, float zdel, float invcs)
{
    float u = fmaf(a1 * mm, czn, -(a2 * shv));
    return wcalc_u(u, zdel, invcs);
}

// (fac, lam) from per-row sums (unchanged arithmetic)
__device__ __forceinline__ float2 faclam(float s, float sp)
{
    const float cs = sqrtf(CC);
    float inv = __fdividef(1.f, 1.f + sqrtf(fmaf(CC, s, 1.f)));
    float n  = fmaxf(sqrtf(s) * inv, 1e-15f);
    float cn = fminf(cs * n, 1.f - 1e-7f);
    float a  = __fdividef(0.5f * __logf(__fdividef(1.f + cn, 1.f - cn)), cs * n);
    float vn = fmaxf(a * inv * sqrtf(sp), 1e-15f);
    float e  = __expf(2.f * cs * vn);
    float th = __fdividef(e - 1.f, e + 1.f);
    float fc = __fdividef(th, cs * vn) * a;
    return make_float2(fc * inv * (1.f / ASCALE), 0.5f * (e + 2.f + __fdividef(1.f, e)));
}

// ---------------- merged prep: lam0/x-convert + weight transpose + column tables ----------------
__global__ void prep_all(const float* __restrict__ x,
                         const float* __restrict__ z1, const float* __restrict__ b1,
                         const float* __restrict__ z2, const float* __restrict__ b2,
                         const float* __restrict__ z3, const float* __restrict__ b3,
                         const float* __restrict__ z4, const float* __restrict__ b4,
                         __half* __restrict__ t1, __half* __restrict__ t2, __half* __restrict__ t3)
{
    if (blockIdx.x < 8192) {
        int gid = blockIdx.x * 256 + threadIdx.x;
        int row = gid >> 5, lane = gid & 31;
        const float4* xr = (const float4*)(x + (long long)row * 768);
        float s = 0.f;
#pragma unroll
        for (int p = 0; p < 6; p++) {
            int e4 = lane + 32 * p;
            float4 v = xr[e4];
            s += v.x * v.x + v.y * v.y + v.z * v.z + v.w * v.w;
            long long b = (long long)row * 768 + e4 * 4;
            __half2 h0; h0.x = __float2half(ASCALE * v.x); h0.y = __float2half(ASCALE * v.y);
            __half2 h1; h1.x = __float2half(ASCALE * v.z); h1.y = __float2half(ASCALE * v.w);
            ((__half2*)(g_x16 + b))[0] = h0;
            ((__half2*)(g_x16 + b))[1] = h1;
        }
#pragma unroll
        for (int o = 16; o; o >>= 1) s += __shfl_xor_sync(0xffffffffu, s, o);
        if (lane == 0) {
            g_lam[row] = __fdividef(2.f, 1.f - CC * s);
            g_fac[row] = 1.f / ASCALE;
        }
    } else if (blockIdx.x < 10368) {
        int idx = (blockIdx.x - 8192) * 256 + threadIdx.x;
        if (idx < 393216) {
            int n = idx / 768, k = idx - n * 768;
            t1[idx] = __float2half(z1[(long long)k * 512 + n]);
        } else if (idx < 524288) {
            int i2 = idx - 393216;
            int n = i2 / 512, k = i2 - n * 512;
            t2[i2] = __float2half(z2[(long long)k * 256 + n]);
        } else {
            int i3 = idx - 524288;
            int n = i3 / 256, k = i3 - n * 256;
            t3[i3] = __float2half(z3[(long long)k * 128 + n]);
        }
    } else {
        int tid2 = (blockIdx.x - 10368) * 256 + threadIdx.x;
        int w = tid2 >> 5, lane = tid2 & 31;
        if (w >= 897) return;
        const float *z, *r; int fi, fo, off, k;
        if (w < 512)      { z = z1; r = b1; fi = 768; fo = 512; off = 0;   k = w; }
        else if (w < 768) { z = z2; r = b2; fi = 512; fo = 256; off = 512; k = w - 512; }
        else if (w < 896) { z = z3; r = b3; fi = 256; fo = 128; off = 768; k = w - 768; }
        else              { z = z4; r = b4; fi = 128; fo = 1;   off = 896; k = 0; }
        float s = 0.f;
        for (int i = lane; i < fi; i += 32) {
            float v = z[(long long)i * fo + k];
            s = fmaf(v, v, s);
        }
#pragma unroll
        for (int o = 16; o; o >>= 1) s += __shfl_xor_sync(0xffffffffu, s, o);
        if (lane == 0) {
            float zn = fmaxf(sqrtf(s), 1e-15f);
            float t = 2.f * sqrtf(CC) * r[k];
            float e = __expf(t);
            float ei = __fdividef(1.f, e);
            g_zdel[off + k] = 2.f * zn - 2.f;
            g_czn[off + k] = 0.5f * (e + ei) / zn;
            g_shv[off + k] = 0.5f * (e - ei);
        }
    }
}

// ---------------- 3-stage pipelined fp16 GEMM + fused epilogue (+ optional final layer) ----------------
#define PITCH 144
template <int KDIM, int NTPREV, int MTILE, bool FINAL>
__global__ __launch_bounds__(256, 2)
void gemm_mma(const __half* __restrict__ A, const __half* __restrict__ Bt,
              __half* __restrict__ Wh,
              int Nfull, int offTab, float2* __restrict__ psum,
              const float2* __restrict__ psumPrev,
              const float* __restrict__ z4g, float* __restrict__ outp)
{
    extern __shared__ char smem[];
    const uint32_t sbase = smem_u32(smem);
    constexpr int NB = KDIM / 64;
    constexpr int MFRAG = MTILE / 64;
    constexpr int A_BYTES = MTILE * PITCH;
    constexpr int AV = MTILE * 8 / 256;

    int tid = threadIdx.x, wid = tid >> 5, lane = tid & 31;
    int warp_m = wid >> 1, warp_n = wid & 1;
    int gID = lane >> 2, tig = lane & 3;
    long long bm = (long long)blockIdx.y * MTILE;
    int bn = blockIdx.x * 128;
    int ntiles = gridDim.x;

    uint32_t soA[AV]; long long goA[AV];
#pragma unroll
    for (int j = 0; j < AV; j++) {
        int v = tid + 256 * j;
        int row = v >> 3, seg = v & 7;
        soA[j] = (uint32_t)(row * PITCH + seg * 16);
        goA[j] = (bm + row) * KDIM + seg * 8;
    }
    uint32_t soB[4]; long long goB[4];
#pragma unroll
    for (int j = 0; j < 4; j++) {
        int v = tid + 256 * j;
        int row = v >> 3, seg = v & 7;
        soB[j] = (uint32_t)(row * PITCH + seg * 16);
        goB[j] = (long long)(bn + row) * KDIM + seg * 8;
    }

    uint32_t a_off[MFRAG];
#pragma unroll
    for (int m = 0; m < MFRAG; m++)
        a_off[m] = (uint32_t)((warp_m * 16 * MFRAG + m * 16 + (lane & 15)) * PITCH
                              + ((lane >> 4) * 8) * 2);
    uint32_t b_off = (uint32_t)((warp_n * 64 + (lane & 7) + ((lane >> 3) & 2) * 4) * PITCH
                                + (((lane >> 3) & 1) * 8) * 2);

    float acc[MFRAG][8][4];
#pragma unroll
    for (int m = 0; m < MFRAG; m++)
#pragma unroll
        for (int n = 0; n < 8; n++)
#pragma unroll
            for (int q = 0; q < 4; q++) acc[m][n][q] = 0.f;

    auto issue = [&](int i) {
        uint32_t st = sbase + (i % 3) * (A_BYTES + 128 * PITCH);
        int k0 = i * 64;
#pragma unroll
        for (int j = 0; j < AV; j++) CP16(st + soA[j], A + goA[j] + k0);
#pragma unroll
        for (int j = 0; j < 4; j++)  CP16(st + A_BYTES + soB[j], Bt + goB[j] + k0);
    };

    issue(0); CP_COMMIT();
    if (NB > 1) { issue(1); CP_COMMIT(); }

    for (int i = 0; i < NB; i++) {
        if (i + 1 < NB) asm volatile("cp.async.wait_group 1;" ::: "memory");
        else            asm volatile("cp.async.wait_group 0;" ::: "memory");
        __syncthreads();
        if (i + 2 < NB) { issue(i + 2); CP_COMMIT(); }

        uint32_t st = sbase + (i % 3) * (A_BYTES + 128 * PITCH);
        uint32_t sA = st, sB = st + A_BYTES;

#pragma unroll
        for (int ks = 0; ks < 64; ks += 16) {
            uint32_t ah[MFRAG][4], bh[4][4];
#pragma unroll
            for (int m = 0; m < MFRAG; m++) ldm_x4(ah[m], sA + a_off[m] + ks * 2);
#pragma unroll
            for (int n2 = 0; n2 < 4; n2++)
                ldm_x4(bh[n2], sB + b_off + (uint32_t)(n2 * 16 * PITCH) + ks * 2);
#pragma unroll
            for (int n2 = 0; n2 < 4; n2++) {
#pragma unroll
                for (int g = 0; g < 2; g++) {
#pragma unroll
                    for (int m = 0; m < MFRAG; m++)
                        mma16816(acc[m][n2 * 2 + g], ah[m], &bh[n2][g * 2]);
                }
            }
        }
    }
    __syncthreads();

    // ---- row factors into SMEM ----
    float2* sred   = (float2*)smem;
    float2* rowdat = (float2*)(smem + 4096);
    float*  dred   = (float*)(smem + 8192);
    if (tid < MTILE) {
        float2 fl;
        if (NTPREV == 0) {
            fl = make_float2(g_fac[bm + tid], g_lam[bm + tid]);
        } else {
            float s = 0.f, sp = 0.f;
#pragma unroll
            for (int t = 0; t < NTPREV; t++) {
                float2 v = psumPrev[(bm + tid) * NTPREV + t];
                s += v.x; sp += v.y;
            }
            fl = faclam(s, sp);
        }
        rowdat[tid] = fl;
    }
    __syncthreads();

    // ---- fused epilogue ----
    const float cs = sqrtf(CC);
    const float invcs = 1.f / cs;
    float s4[2 * MFRAG], sp4[2 * MFRAG], d4[2 * MFRAG];
#pragma unroll
    for (int q = 0; q < 2 * MFRAG; q++) { s4[q] = 0.f; sp4[q] = 0.f; d4[q] = 0.f; }
#pragma unroll
    for (int m = 0; m < MFRAG; m++) {
        int lr = warp_m * 16 * MFRAG + m * 16 + gID;
        float2 flA = rowdat[lr], flB = rowdat[lr + 8];
        float a1A = cs * flA.y * flA.x, a2A = flA.y - 1.f;
        float a1B = cs * flB.y * flB.x, a2B = flB.y - 1.f;
#pragma unroll
        for (int n = 0; n < 8; n++) {
            int kk = bn + warp_n * 64 + n * 8 + tig * 2;
            int k = offTab + kk;
            float czn0 = g_czn[k], czn1 = g_czn[k + 1];
            float shv0 = g_shv[k], shv1 = g_shv[k + 1];
            float zd0  = g_zdel[k], zd1 = g_zdel[k + 1];
            float w0 = wcalc(acc[m][n][0], a1A, a2A, czn0, shv0, zd0, invcs);
            float w1 = wcalc(acc[m][n][1], a1A, a2A, czn1, shv1, zd1, invcs);
            float w2 = wcalc(acc[m][n][2], a1B, a2B, czn0, shv0, zd0, invcs);
            float w3 = wcalc(acc[m][n][3], a1B, a2B, czn1, shv1, zd1, invcs);
            s4[m * 2]     += fmaf(w0, w0, w1 * w1);
            s4[m * 2 + 1] += fmaf(w2, w2, w3 * w3);
            float p0 = fmaxf(w0, 0.f), p1 = fmaxf(w1, 0.f);
            float p2 = fmaxf(w2, 0.f), p3 = fmaxf(w3, 0.f);
            sp4[m * 2]     += fmaf(p0, p0, p1 * p1);
            sp4[m * 2 + 1] += fmaf(p2, p2, p3 * p3);
            if (FINAL) {
                float q0 = __half2float(__float2half(ASCALE * p0));
                float q1 = __half2float(__float2half(ASCALE * p1));
                float q2 = __half2float(__float2half(ASCALE * p2));
                float q3 = __half2float(__float2half(ASCALE * p3));
                float z0 = z4g[kk], z1 = z4g[kk + 1];
                d4[m * 2]     += fmaf(q0, z0, q1 * z1);
                d4[m * 2 + 1] += fmaf(q2, z0, q3 * z1);
            } else {
                acc[m][n][0] = p0; acc[m][n][1] = p1;
                acc[m][n][2] = p2; acc[m][n][3] = p3;
            }
        }
    }
#pragma unroll
    for (int q = 0; q < 2 * MFRAG; q++) {
        s4[q]  += __shfl_xor_sync(0xffffffffu, s4[q], 1);
        s4[q]  += __shfl_xor_sync(0xffffffffu, s4[q], 2);
        sp4[q] += __shfl_xor_sync(0xffffffffu, sp4[q], 1);
        sp4[q] += __shfl_xor_sync(0xffffffffu, sp4[q], 2);
        if (FINAL) {
            d4[q] += __shfl_xor_sync(0xffffffffu, d4[q], 1);
            d4[q] += __shfl_xor_sync(0xffffffffu, d4[q], 2);
        }
    }
    if (tig == 0) {
#pragma unroll
        for (int m = 0; m < MFRAG; m++) {
            int rl = warp_m * 16 * MFRAG + m * 16 + gID;
            sred[(rl)     * 2 + warp_n] = make_float2(s4[m * 2],     sp4[m * 2]);
            sred[(rl + 8) * 2 + warp_n] = make_float2(s4[m * 2 + 1], sp4[m * 2 + 1]);
            if (FINAL) {
                dred[(rl)     * 2 + warp_n] = d4[m * 2];
                dred[(rl + 8) * 2 + warp_n] = d4[m * 2 + 1];
            }
        }
    }
    __syncthreads();
    if (FINAL) {
        if (tid < MTILE) {
            float2 a = sred[tid * 2], b = sred[tid * 2 + 1];
            float2 fl = faclam(a.x + b.x, a.y + b.y);
            float lam = fl.y;
            float se = (dred[tid * 2] + dred[tid * 2 + 1]) * fl.x;
            float u = fmaf(cs * lam * se, g_czn[896], -((lam - 1.f) * g_shv[896]));
            float w = wcalc_u(u, g_zdel[896], invcs);
            outp[bm + tid] = __fdividef(w, 1.f + sqrtf(fmaf(CC, w * w, 1.f)));
        }
        return;
    }
    if (tid < MTILE) {
        float2 a = sred[tid * 2], b = sred[tid * 2 + 1];
        psum[(bm + tid) * ntiles + blockIdx.x] = make_float2(a.x + b.x, a.y + b.y);
    }

    // store ASCALE*relu(w) as fp16
#pragma unroll
    for (int m = 0; m < MFRAG; m++) {
#pragma unroll
        for (int n = 0; n < 8; n++) {
            long long r = bm + warp_m * 16 * MFRAG + m * 16 + gID;
            int c = bn + warp_n * 64 + n * 8 + tig * 2;
            __half2 hi0, hi1;
            hi0.x = __float2half(ASCALE * acc[m][n][0]);
            hi0.y = __float2half(ASCALE * acc[m][n][1]);
            hi1.x = __float2half(ASCALE * acc[m][n][2]);
            hi1.y = __float2half(ASCALE * acc[m][n][3]);
            *(__half2*)(Wh + r * Nfull + c)       = hi0;
            *(__half2*)(Wh + (r + 8) * Nfull + c) = hi1;
        }
    }
}

// ---------------- launch ----------------
extern "C" void kernel_launch(void* const* d_in, const int* in_sizes, int n_in,
                              void* d_out, int out_size)
{
    const float* x  = (const float*)d_in[0];
    const float* z1 = (const float*)d_in[1];
    const float* b1 = (const float*)d_in[2];
    const float* z2 = (const float*)d_in[3];
    const float* b2 = (const float*)d_in[4];
    const float* z3 = (const float*)d_in[5];
    const float* b3 = (const float*)d_in[6];
    const float* z4 = (const float*)d_in[7];
    const float* b4 = (const float*)d_in[8];
    float* out = (float*)d_out;

    float2 *ppsA, *ppsB;
    cudaGetSymbolAddress((void**)&ppsA, g_psumA);
    cudaGetSymbolAddress((void**)&ppsB, g_psumB);
    __half *xh, *h1, *h2, *t1, *t2, *t3;
    cudaGetSymbolAddress((void**)&xh, g_x16);
    cudaGetSymbolAddress((void**)&h1, g_h1);
    cudaGetSymbolAddress((void**)&h2, g_h2);
    cudaGetSymbolAddress((void**)&t1, g_zt1);
    cudaGetSymbolAddress((void**)&t2, g_zt2);
    cudaGetSymbolAddress((void**)&t3, g_zt3);

    const int SM128 = 3 * (128 * PITCH + 128 * PITCH);   // 110592
    const int SM64  = 3 * (64 * PITCH + 128 * PITCH);    // 82944
    cudaFuncSetAttribute((const void*)gemm_mma<768, 0, 128, false>, cudaFuncAttributeMaxDynamicSharedMemorySize, SM128);
    cudaFuncSetAttribute((const void*)gemm_mma<512, 4, 128, false>, cudaFuncAttributeMaxDynamicSharedMemorySize, SM128);
    cudaFuncSetAttribute((const void*)gemm_mma<256, 2, 64, true>,   cudaFuncAttributeMaxDynamicSharedMemorySize, SM64);

    prep_all<<<10481, 256>>>(x, z1, b1, z2, b2, z3, b3, z4, b4, t1, t2, t3);

    // layer 1: (B,768) @ (768,512) -> psumA (4 tiles/row)
    gemm_mma<768, 0, 128, false><<<dim3(4, BATCH / 128), 256, SM128>>>(xh, t1, h1, 512, 0, ppsA, nullptr, nullptr, nullptr);
    // layer 2: (B,512) @ (512,256), factors from psumA -> psumB
    gemm_mma<512, 4, 128, false><<<dim3(2, BATCH / 128), 256, SM128>>>(h1, t2, h2, 256, 512, ppsB, ppsA, nullptr, nullptr);
    // layer 3+4 fused: (B,256) @ (256,128) + final dot + ball map -> out
    gemm_mma<256, 2, 64, true><<<dim3(1, BATCH / 64), 256, SM64>>>(h2, t3, nullptr, 128, 768, nullptr, ppsB, z4, out);
}